// round 3
// baseline (speedup 1.0000x reference)
#include <cuda_runtime.h>
#include <math.h>

// ---------------- problem constants ----------------
#define NB 8          // batch
#define CC 256        // channels
#define NGROUPS 16
#define GSIZE 16      // channels per group
#define GN_EPS 1e-5f

#define TOTHW   16800                 // 12800 + 3200 + 800
#define CLSBASE 0                     // cls_cat: [8, 16800, 20]
#define REGBASE 2688000               // reg_cat: [8, 67200, 1]
#define CTRBASE 3225600               // ctr_cat: [8, 16800, 1]

// scratch (device globals: no runtime allocation allowed)
__device__ float  g_bufA[NB * CC * 12800];
__device__ float  g_bufB[NB * CC * 12800];
__device__ float  g_stats[NB * NGROUPS * 2];        // mean, rstd per (n, group)
__device__ float2 g_part[16 * 104 * 8];             // per-block GN partials (max level0)

// ---------------- f32x2 helpers (sm_103a packed fp32) ----------------
__device__ __forceinline__ unsigned long long pk2(float lo, float hi) {
    unsigned long long r;
    asm("mov.b64 %0, {%1, %2};" : "=l"(r) : "f"(lo), "f"(hi));
    return r;
}
__device__ __forceinline__ void fma2(unsigned long long& d,
                                     unsigned long long a, unsigned long long b) {
    asm("fma.rn.f32x2 %0, %1, %2, %0;" : "+l"(d) : "l"(a), "l"(b));
}
__device__ __forceinline__ float2 upk2(unsigned long long v) {
    float2 f;
    asm("mov.b64 {%0, %1}, %2;" : "=f"(f.x), "=f"(f.y) : "l"(v));
    return f;
}

// ============================================================
// Tower conv: 3x3, Cin=256 -> Cout=256, pad 1, NCHW.
// Block: 128 out-channels x (8 rows x 16 cols). grid=(W/16,ceil(H/8),N*2).
// 256 threads: cog=tid>>4 (16), pxg=tid&15 (16).
// Thread: 8 channels (cog+16*i) x 8 rows paired as 4 f32x2.
// Optional GN(stats_in,gam,bet)+ReLU applied to input during load.
// Epilogue emits deterministic per-block GN partial sums (sum, sumsq).
// ============================================================
__global__ __launch_bounds__(256, 2) void conv3x3_f2(
    const float* __restrict__ in, const float* __restrict__ w,
    const float* __restrict__ bias, float* __restrict__ out,
    int H, int W,
    const float* __restrict__ stats_in,
    const float* __restrict__ gam, const float* __restrict__ bet,
    float2* __restrict__ part)
{
    const int tx  = blockIdx.x * 16;
    const int ty  = blockIdx.y * 8;
    const int n   = blockIdx.z >> 1;
    const int co0 = (blockIdx.z & 1) * 128;
    const int tid = threadIdx.x;
    const int cog = tid >> 4;
    const int pxg = tid & 15;

    __shared__ float2 Ws2[128 * 36];    // [co][ci(4)*9], value splatted {w,w}
    __shared__ float  Xs[4 * 200];      // [ci][row(10)][col pitch 20]
    __shared__ float  redS[8][8], redQ[8][8];

    unsigned long long acc2[8][4];
#pragma unroll
    for (int i = 0; i < 8; i++)
#pragma unroll
        for (int j = 0; j < 4; j++) acc2[i][j] = 0ull;

    const float* inN = in + (size_t)n * CC * H * W;
    const unsigned long long* Wq = reinterpret_cast<const unsigned long long*>(Ws2);

#pragma unroll 1
    for (int ci0 = 0; ci0 < CC; ci0 += 4) {
        // ---- input tile (4 ci, 10x18 halo), normalize+ReLU in-bounds only ----
        for (int l = tid; l < 4 * 180; l += 256) {
            int ci  = l / 180;
            int rem = l - ci * 180;
            int ry  = rem / 18;
            int cx  = rem - ry * 18;
            int gy = ty - 1 + ry, gx = tx - 1 + cx;
            float v = 0.0f;
            if (gy >= 0 && gy < H && gx >= 0 && gx < W) {
                int c = ci0 + ci;
                v = inN[((size_t)c * H + gy) * W + gx];
                if (stats_in) {
                    int sg = (n * NGROUPS + (c >> 4)) * 2;
                    v = (v - stats_in[sg]) * stats_in[sg + 1] * gam[c] + bet[c];
                    v = fmaxf(v, 0.0f);
                }
            }
            Xs[ci * 200 + ry * 20 + cx] = v;
        }
        // ---- weight chunk: 128 co x (4 ci x 9), splatted to float2 ----
        const float* wg = w + (size_t)co0 * 2304 + (size_t)ci0 * 9;
        for (int l = tid; l < 128 * 36; l += 256) {
            int co = l / 36;
            int r  = l - co * 36;
            float wv = wg[(size_t)co * 2304 + r];
            Ws2[l] = make_float2(wv, wv);
        }
        __syncthreads();

#pragma unroll 1
        for (int ci = 0; ci < 4; ci++) {
            const float* xrow = &Xs[ci * 200];
            const int wb = cog * 36 + ci * 9;
#pragma unroll
            for (int k = 0; k < 9; k++) {
                const int ky = k / 3, kx = k - ky * 3;
                float xv[8];
#pragma unroll
                for (int r = 0; r < 8; r++)
                    xv[r] = xrow[(r + ky) * 20 + pxg + kx];
                unsigned long long xp[4];
#pragma unroll
                for (int j = 0; j < 4; j++)
                    xp[j] = pk2(xv[2 * j], xv[2 * j + 1]);
#pragma unroll
                for (int i = 0; i < 8; i++) {
                    unsigned long long wv2 = Wq[wb + i * (16 * 36) + k];
#pragma unroll
                    for (int j = 0; j < 4; j++)
                        fma2(acc2[i][j], xp[j], wv2);
                }
            }
        }
        __syncthreads();
    }

    // ---- epilogue: bias, store, deterministic GN partials ----
    const int warp = tid >> 5, lane = tid & 31;
#pragma unroll
    for (int i = 0; i < 8; i++) {
        const int co = co0 + cog + 16 * i;
        const float b = bias[co];
        float s = 0.0f, q = 0.0f;
        float* orow = out + (((size_t)n * CC + co) * H) * (size_t)W + tx + pxg;
#pragma unroll
        for (int j = 0; j < 4; j++) {
            float2 v2 = upk2(acc2[i][j]);
            float v0 = v2.x + b, v1 = v2.y + b;
            int gy0 = ty + 2 * j, gy1 = gy0 + 1;
            if (gy0 < H) { orow[(size_t)gy0 * W] = v0; s += v0; q += v0 * v0; }
            if (gy1 < H) { orow[(size_t)gy1 * W] = v1; s += v1; q += v1 * v1; }
        }
#pragma unroll
        for (int off = 16; off > 0; off >>= 1) {
            s += __shfl_down_sync(0xffffffffu, s, off);
            q += __shfl_down_sync(0xffffffffu, q, off);
        }
        if (lane == 0) { redS[warp][i] = s; redQ[warp][i] = q; }
    }
    __syncthreads();
    if (tid < 8) {
        float S = 0.0f, Q = 0.0f;
#pragma unroll
        for (int wdx = 0; wdx < 8; wdx++) { S += redS[wdx][tid]; Q += redQ[wdx][tid]; }
        size_t pidx = ((size_t)blockIdx.z * gridDim.y + blockIdx.y) * gridDim.x + blockIdx.x;
        part[pidx * 8 + tid] = make_float2(S, Q);
    }
}

// ============================================================
// GN finalize: 128 blocks = (n, group). Sums the per-block partials.
// ============================================================
__global__ __launch_bounds__(256) void gn_finalize(
    const float2* __restrict__ part, float* __restrict__ stats,
    int GX, int GY, int HW)
{
    const int b = blockIdx.x;               // 0..127
    const int n = b >> 4, grp = b & 15;
    const int half = grp >> 3, i = grp & 7;
    const int bz = n * 2 + half;
    const int nb = GX * GY;

    float S = 0.0f, Q = 0.0f;
    for (int t = threadIdx.x; t < nb; t += 256) {
        float2 p = part[(size_t)(bz * nb + t) * 8 + i];
        S += p.x; Q += p.y;
    }
    __shared__ float sS[256], sQ[256];
    sS[threadIdx.x] = S; sQ[threadIdx.x] = Q;
    __syncthreads();
    for (int off = 128; off > 0; off >>= 1) {
        if (threadIdx.x < off) {
            sS[threadIdx.x] += sS[threadIdx.x + off];
            sQ[threadIdx.x] += sQ[threadIdx.x + off];
        }
        __syncthreads();
    }
    if (threadIdx.x == 0) {
        float cnt  = (float)(GSIZE * HW);
        float mean = sS[0] / cnt;
        float var  = sQ[0] / cnt - mean * mean;
        stats[2 * b]     = mean;
        stats[2 * b + 1] = rsqrtf(var + GN_EPS);
    }
}

// ============================================================
// Output conv: 3x3, Cin=256 -> COUT (small). Applies GN+ReLU to the
// (un-normalized) tower output during load, writes into the permuted
// concat layout.
// MODE 0: cls   MODE 1: reg(+relu)   MODE 2: ctr
// ============================================================
template <int COUT, int MODE>
__global__ __launch_bounds__(256) void outconv(
    const float* __restrict__ in, const float* __restrict__ w,
    const float* __restrict__ bias, float* __restrict__ out,
    int H, int W, int poff,
    const float* __restrict__ stats_in,
    const float* __restrict__ gam, const float* __restrict__ bet)
{
    const int tx = blockIdx.x * 16;
    const int ty = blockIdx.y * 8;
    const int n  = blockIdx.z;
    const int tid = threadIdx.x;
    const int px  = tid & 127;
    const int half = tid >> 7;
    const int row = px >> 4;
    const int col = px & 15;

    constexpr int COH = (COUT + 1) / 2;
    const int cobase = half * COH;
    const int conum  = (COUT - cobase) < COH ? (COUT - cobase) : COH;

    __shared__ float Ws[COUT * 72];
    __shared__ float Xs[8 * 200];

    float acc[COH];
#pragma unroll
    for (int c = 0; c < COH; c++) acc[c] = 0.0f;

    const float* inN = in + (size_t)n * CC * H * W;

#pragma unroll 1
    for (int ci0 = 0; ci0 < CC; ci0 += 8) {
        for (int l = tid; l < 8 * 180; l += 256) {
            int ci  = l / 180;
            int rem = l - ci * 180;
            int ry  = rem / 18;
            int cx  = rem - ry * 18;
            int gy = ty - 1 + ry, gx = tx - 1 + cx;
            float v = 0.0f;
            if (gy >= 0 && gy < H && gx >= 0 && gx < W) {
                int c = ci0 + ci;
                v = inN[((size_t)c * H + gy) * W + gx];
                int sg = (n * NGROUPS + (c >> 4)) * 2;
                v = (v - stats_in[sg]) * stats_in[sg + 1] * gam[c] + bet[c];
                v = fmaxf(v, 0.0f);
            }
            Xs[ci * 200 + ry * 20 + cx] = v;
        }
        const float* wg = w + (size_t)ci0 * 9;
        for (int l = tid; l < COUT * 72; l += 256) {
            int co = l / 72;
            int r  = l - co * 72;
            Ws[l] = wg[(size_t)co * 2304 + r];
        }
        __syncthreads();

#pragma unroll 1
        for (int ci = 0; ci < 8; ci++) {
            const float* xrow = &Xs[ci * 200];
#pragma unroll
            for (int k = 0; k < 9; k++) {
                const int ky = k / 3, kx = k - ky * 3;
                float x = xrow[(row + ky) * 20 + col + kx];
#pragma unroll
                for (int c = 0; c < COH; c++)
                    if (c < conum)
                        acc[c] += Ws[(cobase + c) * 72 + ci * 9 + k] * x;
            }
        }
        __syncthreads();
    }

    const int gy = ty + row;
    if (gy < H && conum > 0) {
        const int pix = poff + gy * W + tx + col;
        const size_t gp = (size_t)n * TOTHW + pix;
#pragma unroll
        for (int c = 0; c < COH; c++) {
            if (c >= conum) break;
            const int co = cobase + c;
            float v = acc[c] + bias[co];
            if (MODE == 0) {
                out[CLSBASE + gp * 20 + co] = v;
            } else if (MODE == 1) {
                out[REGBASE + gp * 4 + co] = fmaxf(v, 0.0f);
            } else {
                out[CTRBASE + gp] = v;
            }
        }
    }
}

// ============================================================
// host launcher
// ============================================================
extern "C" void kernel_launch(void* const* d_in, const int* in_sizes, int n_in,
                              void* d_out, int out_size)
{
    (void)in_sizes; (void)n_in; (void)out_size;

    const float* feat[3] = { (const float*)d_in[0], (const float*)d_in[1],
                             (const float*)d_in[2] };
    const float* cls_conv_w = (const float*)d_in[3];   // [2,256,256,3,3]
    const float* cls_conv_b = (const float*)d_in[4];   // [2,256]
    const float* cls_gn_g   = (const float*)d_in[5];
    const float* cls_gn_b   = (const float*)d_in[6];
    const float* cls_out_w  = (const float*)d_in[7];   // [20,256,3,3]
    const float* cls_out_b  = (const float*)d_in[8];
    const float* reg_conv_w = (const float*)d_in[9];
    const float* reg_conv_b = (const float*)d_in[10];
    const float* reg_gn_g   = (const float*)d_in[11];
    const float* reg_gn_b   = (const float*)d_in[12];
    const float* reg_out_w  = (const float*)d_in[13];  // [4,256,3,3]
    const float* reg_out_b  = (const float*)d_in[14];
    const float* ctr_w      = (const float*)d_in[15];  // [1,256,3,3]
    const float* ctr_b      = (const float*)d_in[16];

    float* out = (float*)d_out;

    float *bufA, *bufB, *stats;
    float2* part;
    cudaGetSymbolAddress((void**)&bufA, g_bufA);
    cudaGetSymbolAddress((void**)&bufB, g_bufB);
    cudaGetSymbolAddress((void**)&stats, g_stats);
    cudaGetSymbolAddress((void**)&part, g_part);

    const int LH[3] = {100, 50, 25};
    const int LW[3] = {128, 64, 32};
    const int LP[3] = {0, 12800, 16000};
    const size_t WSTRIDE = (size_t)CC * CC * 9;   // per-layer tower weight stride

    for (int L = 0; L < 3; L++) {
        const int H = LH[L], W = LW[L], HW = H * W, poff = LP[L];
        const int GX = W / 16, GY = (H + 7) / 8;
        dim3 cgrid(GX, GY, NB * 2);
        dim3 ogrid(GX, GY, NB);

        // ---- classification tower ----
        conv3x3_f2<<<cgrid, 256>>>(feat[L], cls_conv_w, cls_conv_b, bufA, H, W,
                                   nullptr, nullptr, nullptr, part);
        gn_finalize<<<NB * NGROUPS, 256>>>(part, stats, GX, GY, HW);
        conv3x3_f2<<<cgrid, 256>>>(bufA, cls_conv_w + WSTRIDE, cls_conv_b + CC,
                                   bufB, H, W, stats, cls_gn_g, cls_gn_b, part);
        gn_finalize<<<NB * NGROUPS, 256>>>(part, stats, GX, GY, HW);
        outconv<20, 0><<<ogrid, 256>>>(bufB, cls_out_w, cls_out_b, out, H, W, poff,
                                       stats, cls_gn_g + CC, cls_gn_b + CC);

        // ---- regression tower ----
        conv3x3_f2<<<cgrid, 256>>>(feat[L], reg_conv_w, reg_conv_b, bufA, H, W,
                                   nullptr, nullptr, nullptr, part);
        gn_finalize<<<NB * NGROUPS, 256>>>(part, stats, GX, GY, HW);
        conv3x3_f2<<<cgrid, 256>>>(bufA, reg_conv_w + WSTRIDE, reg_conv_b + CC,
                                   bufB, H, W, stats, reg_gn_g, reg_gn_b, part);
        gn_finalize<<<NB * NGROUPS, 256>>>(part, stats, GX, GY, HW);
        outconv<4, 1><<<ogrid, 256>>>(bufB, reg_out_w, reg_out_b, out, H, W, poff,
                                      stats, reg_gn_g + CC, reg_gn_b + CC);
        outconv<1, 2><<<ogrid, 256>>>(bufB, ctr_w, ctr_b, out, H, W, poff,
                                      stats, reg_gn_g + CC, reg_gn_b + CC);
    }
}

// round 4
// speedup vs baseline: 2.0418x; 2.0418x over previous
#include <cuda_runtime.h>
#include <math.h>

// ---------------- problem constants ----------------
#define NB 8          // batch
#define CC 256        // channels
#define NGROUPS 16
#define GSIZE 16      // channels per group
#define GN_EPS 1e-5f

#define TOTHW   16800                 // 12800 + 3200 + 800
#define CLSBASE 0                     // cls_cat: [8, 16800, 20]
#define REGBASE 2688000               // reg_cat: [8, 67200, 1]
#define CTRBASE 3225600               // ctr_cat: [8, 16800, 1]

#define WELEM (CC * CC * 9)           // 589824 elements per tower conv layer

// scratch (device globals: no runtime allocation allowed)
__device__ float  g_bufA[NB * CC * 12800];
__device__ float  g_bufB[NB * CC * 12800];
__device__ float  g_stats[NB * NGROUPS * 2];        // mean, rstd per (n, group)
__device__ float2 g_part[16 * 104 * 8];             // per-block GN partials (max level0)
__device__ float  g_wT[4 * WELEM];                  // transposed tower weights [ci][k][co]

// ============================================================
// One-time weight transpose: w[co][ci][k] -> wt[ci][k][co]
// idx = ci*2304 + k*256 + co  (coalesced writes)
// ============================================================
__global__ __launch_bounds__(256) void wtrans(
    const float* __restrict__ w, float* __restrict__ wt)
{
    int idx = blockIdx.x * 256 + threadIdx.x;
    if (idx >= WELEM) return;
    int co = idx & 255;
    int t  = idx >> 8;          // ci*9 + k
    int k  = t % 9;
    int ci = t / 9;
    wt[idx] = w[co * 2304 + ci * 9 + k];
}

// ============================================================
// Tower conv: 3x3, Cin=256 -> Cout=256, pad 1, NCHW.
// Block: 128 out-channels x (8 rows x 16 cols). grid=(W/16,ceil(H/8),N*2).
// 256 threads: cog=tid>>4 (16), pxg=tid&15 (16).
// Thread: 8 CONSECUTIVE channels (cog*8 .. cog*8+7) x 8 rows.
// Weights read from pre-transposed wT[ci][k][co] (2 x LDS.128 per tap set).
// Optional GN(stats_in,gam,bet)+ReLU applied to input during load.
// Epilogue emits deterministic per-block GN partial sums (sum, sumsq).
// ============================================================
__global__ __launch_bounds__(256, 2) void conv3x3_t(
    const float* __restrict__ in, const float* __restrict__ wT,
    const float* __restrict__ bias, float* __restrict__ out,
    int H, int W,
    const float* __restrict__ stats_in,
    const float* __restrict__ gam, const float* __restrict__ bet,
    float2* __restrict__ part)
{
    const int tx  = blockIdx.x * 16;
    const int ty  = blockIdx.y * 8;
    const int n   = blockIdx.z >> 1;
    const int co0 = (blockIdx.z & 1) * 128;
    const int tid = threadIdx.x;
    const int cog = tid >> 4;
    const int pxg = tid & 15;

    __shared__ float Wt[8 * 9 * 128];   // [ci][k][co_local]  36.9KB
    __shared__ float Xs[8 * 200];       // [ci][row(10)][col pitch 20]
    __shared__ float redS[8][2][8], redQ[8][2][8];

    float acc[8][8];
#pragma unroll
    for (int i = 0; i < 8; i++)
#pragma unroll
        for (int r = 0; r < 8; r++) acc[i][r] = 0.0f;

    const float* inN = in + (size_t)n * CC * H * W;
    const float4* wT4 = reinterpret_cast<const float4*>(wT);
    float4* Wt4 = reinterpret_cast<float4*>(Wt);

#pragma unroll 1
    for (int ci0 = 0; ci0 < CC; ci0 += 8) {
        // ---- input tile (8 ci, 10x18 halo), normalize+ReLU in-bounds only ----
        for (int l = tid; l < 8 * 180; l += 256) {
            int ci  = l / 180;
            int rem = l - ci * 180;
            int ry  = rem / 18;
            int cx  = rem - ry * 18;
            int gy = ty - 1 + ry, gx = tx - 1 + cx;
            float v = 0.0f;
            if (gy >= 0 && gy < H && gx >= 0 && gx < W) {
                int c = ci0 + ci;
                v = inN[((size_t)c * H + gy) * W + gx];
                if (stats_in) {
                    int sg = (n * NGROUPS + (c >> 4)) * 2;
                    v = (v - stats_in[sg]) * stats_in[sg + 1] * gam[c] + bet[c];
                    v = fmaxf(v, 0.0f);
                }
            }
            Xs[ci * 200 + ry * 20 + cx] = v;
        }
        // ---- weight chunk: wT[ci0..+8][0..9][co0..+128], float4 coalesced ----
        {
            const int cb4 = co0 >> 2;
#pragma unroll
            for (int l4 = tid; l4 < 2304; l4 += 256) {
                int ci  = l4 / 288;
                int rem = l4 - ci * 288;
                int k   = rem >> 5;
                int c4  = rem & 31;
                Wt4[l4] = wT4[(size_t)(ci0 + ci) * 576 + k * 64 + cb4 + c4];
            }
        }
        __syncthreads();

#pragma unroll 1
        for (int ci = 0; ci < 8; ci++) {
            const float* xrow = &Xs[ci * 200 + pxg];
            const float* wrow = &Wt[ci * 1152 + cog * 8];
#pragma unroll
            for (int kx = 0; kx < 3; kx++) {
                float xc[10];
#pragma unroll
                for (int r = 0; r < 10; r++)
                    xc[r] = xrow[r * 20 + kx];
#pragma unroll
                for (int ky = 0; ky < 3; ky++) {
                    const int k = ky * 3 + kx;
                    const float4 wa = *reinterpret_cast<const float4*>(&wrow[k * 128]);
                    const float4 wb = *reinterpret_cast<const float4*>(&wrow[k * 128 + 4]);
#pragma unroll
                    for (int r = 0; r < 8; r++) {
                        const float x = xc[r + ky];
                        acc[0][r] += wa.x * x;
                        acc[1][r] += wa.y * x;
                        acc[2][r] += wa.z * x;
                        acc[3][r] += wa.w * x;
                        acc[4][r] += wb.x * x;
                        acc[5][r] += wb.y * x;
                        acc[6][r] += wb.z * x;
                        acc[7][r] += wb.w * x;
                    }
                }
            }
        }
        __syncthreads();
    }

    // ---- epilogue: bias, store, deterministic GN partials ----
    const int warp = tid >> 5, lane = tid & 31, halfw = lane >> 4;
#pragma unroll
    for (int i = 0; i < 8; i++) {
        const int co = co0 + cog * 8 + i;
        const float b = bias[co];
        float s = 0.0f, q = 0.0f;
        float* orow = out + (((size_t)n * CC + co) * H) * (size_t)W + tx + pxg;
#pragma unroll
        for (int r = 0; r < 8; r++) {
            int gy = ty + r;
            if (gy < H) {
                float v = acc[i][r] + b;
                orow[(size_t)gy * W] = v;
                s += v;
                q += v * v;
            }
        }
        // reduce over the 16 lanes sharing this (cog, i)
#pragma unroll
        for (int off = 8; off > 0; off >>= 1) {
            s += __shfl_down_sync(0xffffffffu, s, off, 16);
            q += __shfl_down_sync(0xffffffffu, q, off, 16);
        }
        if ((lane & 15) == 0) { redS[warp][halfw][i] = s; redQ[warp][halfw][i] = q; }
    }
    __syncthreads();
    // group g (0..7) <-> warp g: co range [co0+16g, co0+16g+15]
    if (tid < 8) {
        float S = 0.0f, Q = 0.0f;
#pragma unroll
        for (int h = 0; h < 2; h++)
#pragma unroll
            for (int i = 0; i < 8; i++) { S += redS[tid][h][i]; Q += redQ[tid][h][i]; }
        size_t pidx = ((size_t)blockIdx.z * gridDim.y + blockIdx.y) * gridDim.x + blockIdx.x;
        part[pidx * 8 + tid] = make_float2(S, Q);
    }
}

// ============================================================
// GN finalize: 128 blocks = (n, group). Sums the per-block partials.
// ============================================================
__global__ __launch_bounds__(256) void gn_finalize(
    const float2* __restrict__ part, float* __restrict__ stats,
    int GX, int GY, int HW)
{
    const int b = blockIdx.x;               // 0..127
    const int n = b >> 4, grp = b & 15;
    const int half = grp >> 3, i = grp & 7;
    const int bz = n * 2 + half;
    const int nb = GX * GY;

    float S = 0.0f, Q = 0.0f;
    for (int t = threadIdx.x; t < nb; t += 256) {
        float2 p = part[(size_t)(bz * nb + t) * 8 + i];
        S += p.x; Q += p.y;
    }
    __shared__ float sS[256], sQ[256];
    sS[threadIdx.x] = S; sQ[threadIdx.x] = Q;
    __syncthreads();
    for (int off = 128; off > 0; off >>= 1) {
        if (threadIdx.x < off) {
            sS[threadIdx.x] += sS[threadIdx.x + off];
            sQ[threadIdx.x] += sQ[threadIdx.x + off];
        }
        __syncthreads();
    }
    if (threadIdx.x == 0) {
        float cnt  = (float)(GSIZE * HW);
        float mean = sS[0] / cnt;
        float var  = sQ[0] / cnt - mean * mean;
        stats[2 * b]     = mean;
        stats[2 * b + 1] = rsqrtf(var + GN_EPS);
    }
}

// ============================================================
// Output conv: 3x3, Cin=256 -> COUT (small). Applies GN+ReLU to the
// (un-normalized) tower output during load, writes into the permuted
// concat layout.
// MODE 0: cls   MODE 1: reg(+relu)   MODE 2: ctr
// ============================================================
template <int COUT, int MODE>
__global__ __launch_bounds__(256) void outconv(
    const float* __restrict__ in, const float* __restrict__ w,
    const float* __restrict__ bias, float* __restrict__ out,
    int H, int W, int poff,
    const float* __restrict__ stats_in,
    const float* __restrict__ gam, const float* __restrict__ bet)
{
    const int tx = blockIdx.x * 16;
    const int ty = blockIdx.y * 8;
    const int n  = blockIdx.z;
    const int tid = threadIdx.x;
    const int px  = tid & 127;
    const int half = tid >> 7;
    const int row = px >> 4;
    const int col = px & 15;

    constexpr int COH = (COUT + 1) / 2;
    const int cobase = half * COH;
    const int conum  = (COUT - cobase) < COH ? (COUT - cobase) : COH;

    __shared__ float Ws[COUT * 72];
    __shared__ float Xs[8 * 200];

    float acc[COH];
#pragma unroll
    for (int c = 0; c < COH; c++) acc[c] = 0.0f;

    const float* inN = in + (size_t)n * CC * H * W;

#pragma unroll 1
    for (int ci0 = 0; ci0 < CC; ci0 += 8) {
        for (int l = tid; l < 8 * 180; l += 256) {
            int ci  = l / 180;
            int rem = l - ci * 180;
            int ry  = rem / 18;
            int cx  = rem - ry * 18;
            int gy = ty - 1 + ry, gx = tx - 1 + cx;
            float v = 0.0f;
            if (gy >= 0 && gy < H && gx >= 0 && gx < W) {
                int c = ci0 + ci;
                v = inN[((size_t)c * H + gy) * W + gx];
                int sg = (n * NGROUPS + (c >> 4)) * 2;
                v = (v - stats_in[sg]) * stats_in[sg + 1] * gam[c] + bet[c];
                v = fmaxf(v, 0.0f);
            }
            Xs[ci * 200 + ry * 20 + cx] = v;
        }
        const float* wg = w + (size_t)ci0 * 9;
        for (int l = tid; l < COUT * 72; l += 256) {
            int co = l / 72;
            int r  = l - co * 72;
            Ws[l] = wg[(size_t)co * 2304 + r];
        }
        __syncthreads();

#pragma unroll 1
        for (int ci = 0; ci < 8; ci++) {
            const float* xrow = &Xs[ci * 200];
#pragma unroll
            for (int k = 0; k < 9; k++) {
                const int ky = k / 3, kx = k - ky * 3;
                float x = xrow[(row + ky) * 20 + col + kx];
#pragma unroll
                for (int c = 0; c < COH; c++)
                    if (c < conum)
                        acc[c] += Ws[(cobase + c) * 72 + ci * 9 + k] * x;
            }
        }
        __syncthreads();
    }

    const int gy = ty + row;
    if (gy < H && conum > 0) {
        const int pix = poff + gy * W + tx + col;
        const size_t gp = (size_t)n * TOTHW + pix;
#pragma unroll
        for (int c = 0; c < COH; c++) {
            if (c >= conum) break;
            const int co = cobase + c;
            float v = acc[c] + bias[co];
            if (MODE == 0) {
                out[CLSBASE + gp * 20 + co] = v;
            } else if (MODE == 1) {
                out[REGBASE + gp * 4 + co] = fmaxf(v, 0.0f);
            } else {
                out[CTRBASE + gp] = v;
            }
        }
    }
}

// ============================================================
// host launcher
// ============================================================
extern "C" void kernel_launch(void* const* d_in, const int* in_sizes, int n_in,
                              void* d_out, int out_size)
{
    (void)in_sizes; (void)n_in; (void)out_size;

    const float* feat[3] = { (const float*)d_in[0], (const float*)d_in[1],
                             (const float*)d_in[2] };
    const float* cls_conv_w = (const float*)d_in[3];   // [2,256,256,3,3]
    const float* cls_conv_b = (const float*)d_in[4];   // [2,256]
    const float* cls_gn_g   = (const float*)d_in[5];
    const float* cls_gn_b   = (const float*)d_in[6];
    const float* cls_out_w  = (const float*)d_in[7];   // [20,256,3,3]
    const float* cls_out_b  = (const float*)d_in[8];
    const float* reg_conv_w = (const float*)d_in[9];
    const float* reg_conv_b = (const float*)d_in[10];
    const float* reg_gn_g   = (const float*)d_in[11];
    const float* reg_gn_b   = (const float*)d_in[12];
    const float* reg_out_w  = (const float*)d_in[13];  // [4,256,3,3]
    const float* reg_out_b  = (const float*)d_in[14];
    const float* ctr_w      = (const float*)d_in[15];  // [1,256,3,3]
    const float* ctr_b      = (const float*)d_in[16];

    float* out = (float*)d_out;

    float *bufA, *bufB, *stats, *wT;
    float2* part;
    cudaGetSymbolAddress((void**)&bufA, g_bufA);
    cudaGetSymbolAddress((void**)&bufB, g_bufB);
    cudaGetSymbolAddress((void**)&stats, g_stats);
    cudaGetSymbolAddress((void**)&part, g_part);
    cudaGetSymbolAddress((void**)&wT, g_wT);

    const size_t WSTRIDE = (size_t)WELEM;   // per-layer tower weight stride
    const int TGRID = (WELEM + 255) / 256;

    // one-time weight transposes (cheap; graph replays them, still cheap)
    wtrans<<<TGRID, 256>>>(cls_conv_w,           wT + 0 * WSTRIDE);
    wtrans<<<TGRID, 256>>>(cls_conv_w + WSTRIDE, wT + 1 * WSTRIDE);
    wtrans<<<TGRID, 256>>>(reg_conv_w,           wT + 2 * WSTRIDE);
    wtrans<<<TGRID, 256>>>(reg_conv_w + WSTRIDE, wT + 3 * WSTRIDE);

    const int LH[3] = {100, 50, 25};
    const int LW[3] = {128, 64, 32};
    const int LP[3] = {0, 12800, 16000};

    for (int L = 0; L < 3; L++) {
        const int H = LH[L], W = LW[L], HW = H * W, poff = LP[L];
        const int GX = W / 16, GY = (H + 7) / 8;
        dim3 cgrid(GX, GY, NB * 2);
        dim3 ogrid(GX, GY, NB);

        // ---- classification tower ----
        conv3x3_t<<<cgrid, 256>>>(feat[L], wT + 0 * WSTRIDE, cls_conv_b, bufA, H, W,
                                  nullptr, nullptr, nullptr, part);
        gn_finalize<<<NB * NGROUPS, 256>>>(part, stats, GX, GY, HW);
        conv3x3_t<<<cgrid, 256>>>(bufA, wT + 1 * WSTRIDE, cls_conv_b + CC, bufB, H, W,
                                  stats, cls_gn_g, cls_gn_b, part);
        gn_finalize<<<NB * NGROUPS, 256>>>(part, stats, GX, GY, HW);
        outconv<20, 0><<<ogrid, 256>>>(bufB, cls_out_w, cls_out_b, out, H, W, poff,
                                       stats, cls_gn_g + CC, cls_gn_b + CC);

        // ---- regression tower ----
        conv3x3_t<<<cgrid, 256>>>(feat[L], wT + 2 * WSTRIDE, reg_conv_b, bufA, H, W,
                                  nullptr, nullptr, nullptr, part);
        gn_finalize<<<NB * NGROUPS, 256>>>(part, stats, GX, GY, HW);
        conv3x3_t<<<cgrid, 256>>>(bufA, wT + 3 * WSTRIDE, reg_conv_b + CC, bufB, H, W,
                                  stats, reg_gn_g, reg_gn_b, part);
        gn_finalize<<<NB * NGROUPS, 256>>>(part, stats, GX, GY, HW);
        outconv<4, 1><<<ogrid, 256>>>(bufB, reg_out_w, reg_out_b, out, H, W, poff,
                                      stats, reg_gn_g + CC, reg_gn_b + CC);
        outconv<1, 2><<<ogrid, 256>>>(bufB, ctr_w, ctr_b, out, H, W, poff,
                                      stats, reg_gn_g + CC, reg_gn_b + CC);
    }
}

// round 6
// speedup vs baseline: 4.7385x; 2.3207x over previous
#include <cuda_runtime.h>
#include <cuda_bf16.h>
#include <math.h>
#include <stdint.h>

// ---------------- problem constants ----------------
#define NB 8
#define CC 256
#define NGROUPS 16
#define GSIZE 16
#define GN_EPS 1e-5f

#define TOTHW   16800
#define CLSBASE 0
#define REGBASE 2688000
#define CTRBASE 3225600

#define WELEM (CC * CC * 9)       // 589824 per tower layer

// padded-NHWC buffer capacity: level0 = 8*102*130*256 = 27,156,480 (+slack)
#define XCAP 27500000
#define YCAP 27160000

// scratch (device globals: no runtime allocation allowed; zero-initialized)
__device__ __align__(16) __nv_bfloat16 g_XFH[XCAP];
__device__ __align__(16) __nv_bfloat16 g_XFL[XCAP];
__device__ __align__(16) __nv_bfloat16 g_XTH[XCAP];
__device__ __align__(16) __nv_bfloat16 g_XTL[XCAP];
__device__ __align__(16) float g_YA[YCAP];
__device__ __align__(16) float g_YB[YCAP];
__device__ __align__(16) __nv_bfloat16 g_WH[4 * WELEM];   // [layer][tap][co][ci] hi
__device__ __align__(16) __nv_bfloat16 g_WL[4 * WELEM];   // lo
__device__ float  g_stats[NB * NGROUPS * 2];
__device__ float2 g_part[16 * 104 * 8];

// ---------------- PTX helpers (arch-agnostic: sm_80+ mma/ldmatrix) ----------
__device__ __forceinline__ uint32_t smem_u32(const void* p) {
    uint32_t a;
    asm("{ .reg .u64 t; cvta.to.shared.u64 t, %1; cvt.u32.u64 %0, t; }"
        : "=r"(a) : "l"(p));
    return a;
}
__device__ __forceinline__ void ldsm_x4(uint32_t& r0, uint32_t& r1,
                                        uint32_t& r2, uint32_t& r3, uint32_t a) {
    asm volatile("ldmatrix.sync.aligned.m8n8.x4.shared.b16 {%0,%1,%2,%3}, [%4];"
        : "=r"(r0), "=r"(r1), "=r"(r2), "=r"(r3) : "r"(a));
}
__device__ __forceinline__ void mma_bf16(float* d, const uint32_t* a,
                                         const uint32_t* b) {
    asm volatile("mma.sync.aligned.m16n8k16.row.col.f32.bf16.bf16.f32 "
        "{%0,%1,%2,%3}, {%4,%5,%6,%7}, {%8,%9}, {%0,%1,%2,%3};"
        : "+f"(d[0]), "+f"(d[1]), "+f"(d[2]), "+f"(d[3])
        : "r"(a[0]), "r"(a[1]), "r"(a[2]), "r"(a[3]), "r"(b[0]), "r"(b[1]));
}

// smem row pitch (bytes) for 64 ci bf16 (128B) + 16B pad: conflict-free ldmatrix
#define PITCH 144
#define OFF_AH 0
#define OFF_AL 18432
#define OFF_BH 36864
#define OFF_BL 55296
#define SMEMSZ 73728

// ============================================================
// wsplit: w[co][ci][tap] fp32 -> WH/WL[tap][co][ci] bf16 hi/lo
// ============================================================
__global__ __launch_bounds__(256) void wsplit(
    const float* __restrict__ w, __nv_bfloat16* __restrict__ WH,
    __nv_bfloat16* __restrict__ WL)
{
    int idx = blockIdx.x * 256 + threadIdx.x;
    if (idx >= WELEM) return;
    int tap = idx / 65536;
    int r   = idx - tap * 65536;
    int co  = r >> 8, ci = r & 255;
    float v = w[co * 2304 + ci * 9 + tap];
    __nv_bfloat16 h = __float2bfloat16(v);
    WH[idx] = h;
    WL[idx] = __float2bfloat16(v - __bfloat162float(h));
}

// ============================================================
// zerok: fill uint4 zeros
// ============================================================
__global__ __launch_bounds__(256) void zerok(uint4* __restrict__ p, size_t n16)
{
    size_t stride = (size_t)gridDim.x * 256;
    uint4 z = make_uint4(0, 0, 0, 0);
    for (size_t i = (size_t)blockIdx.x * 256 + threadIdx.x; i < n16; i += stride)
        p[i] = z;
}

// ============================================================
// featprep: NCHW fp32 -> padded NHWC bf16 hi/lo (32x32 smem transpose)
// grid (W/32, H, NB*8); block (32,32)
// ============================================================
__global__ __launch_bounds__(1024) void featprep(
    const float* __restrict__ feat, __nv_bfloat16* __restrict__ XH,
    __nv_bfloat16* __restrict__ XL, int H, int W, int Wp, int HpWp)
{
    __shared__ float tile[32][33];
    int xt = blockIdx.x, y = blockIdx.y;
    int n  = blockIdx.z >> 3, ct = blockIdx.z & 7;
    int tx = threadIdx.x, ty = threadIdx.y;

    tile[ty][tx] = feat[(((size_t)n * CC + ct * 32 + ty) * H + y) * W + xt * 32 + tx];
    __syncthreads();

    int c = ct * 32 + tx;
    int x = xt * 32 + ty;
    float v = tile[tx][ty];
    size_t a = ((size_t)n * HpWp + (size_t)(y + 1) * Wp + (x + 1)) * CC + c;
    __nv_bfloat16 h = __float2bfloat16(v);
    XH[a] = h;
    XL[a] = __float2bfloat16(v - __bfloat162float(h));
}

// ============================================================
// actk: Y (padded NHWC fp32) -> GN+ReLU -> split bf16 hi/lo; pads zero.
// ============================================================
__global__ __launch_bounds__(256) void actk(
    const float* __restrict__ Y, const float* __restrict__ stats,
    const float* __restrict__ gam, const float* __restrict__ bet,
    __nv_bfloat16* __restrict__ XH, __nv_bfloat16* __restrict__ XL,
    int H, int W, int Wp, int HpWp)
{
    size_t total = (size_t)NB * HpWp * CC;
    size_t stride = (size_t)gridDim.x * 256;
    for (size_t idx = (size_t)blockIdx.x * 256 + threadIdx.x; idx < total; idx += stride) {
        int c = (int)(idx & 255);
        size_t pix = idx >> 8;
        int n  = (int)(pix / HpWp);
        int pp = (int)(pix - (size_t)n * HpWp);
        int py = pp / Wp, px = pp - py * Wp;
        __nv_bfloat16 h = __float2bfloat16(0.0f), l = h;
        if (py >= 1 && py <= H && px >= 1 && px <= W) {
            float v = Y[idx];
            int sg = (n * NGROUPS + (c >> 4)) * 2;
            v = (v - stats[sg]) * stats[sg + 1] * gam[c] + bet[c];
            v = fmaxf(v, 0.0f);
            h = __float2bfloat16(v);
            l = __float2bfloat16(v - __bfloat162float(h));
        }
        XH[idx] = h;
        XL[idx] = l;
    }
}

// ============================================================
// convM: warp-mma 3x3 conv, Cin=256 -> 128 co per CTA, 128 px per CTA.
// grid (PT, 1, 16): z = n*2 + cohalf. 256 threads = 8 warps (4m x 2n).
// 3-term bf16 split: acc += Ah*Bh + Ah*Bl + Al*Bh (fp32 accum).
// Epilogue: +bias, store padded-NHWC fp32 Y, deterministic GN partials.
// ============================================================
__global__ __launch_bounds__(256, 2) void convM(
    const uint4* __restrict__ XH, const uint4* __restrict__ XL,
    const uint4* __restrict__ WHl, const uint4* __restrict__ WLl,
    const float* __restrict__ bias, float* __restrict__ Y,
    float2* __restrict__ part,
    int H, int W, int Wp, int lgW, int HW, int HpWp)
{
    extern __shared__ char smem[];
    const uint32_t sAH = smem_u32(smem + OFF_AH);
    const uint32_t sAL = smem_u32(smem + OFF_AL);
    const uint32_t sBH = smem_u32(smem + OFF_BH);
    const uint32_t sBL = smem_u32(smem + OFF_BL);

    const int tid = threadIdx.x, wid = tid >> 5, lane = tid & 31;
    const int warp_m = wid >> 1, warp_n = wid & 1;
    const int p0 = blockIdx.x * 128;
    const int z = blockIdx.z;
    const int n = z >> 1, co0 = (z & 1) * 128;
    const size_t nbase = (size_t)n * HpWp;

    float acc[2][8][4];
#pragma unroll
    for (int mt = 0; mt < 2; mt++)
#pragma unroll
        for (int nt = 0; nt < 8; nt++)
#pragma unroll
            for (int i = 0; i < 4; i++) acc[mt][nt][i] = 0.0f;

    // ldmatrix lane-address components
    const int lrow = lane & 7;
    const int matr = (lane >> 3) & 1;    // +8 on first-split dim
    const int matc = lane >> 4;          // +8 on second-split dim

#pragma unroll 1
    for (int tap = 0; tap < 9; tap++) {
        const int ky = tap / 3, kx = tap - ky * 3;
#pragma unroll 1
        for (int kc = 0; kc < 4; kc++) {          // 64 ci per chunk
            // ---- fill A (weights) [128 co][64 ci] hi/lo ----
#pragma unroll
            for (int t = tid; t < 1024; t += 256) {
                int row = t >> 3, v = t & 7;
                size_t g = (size_t)tap * 8192 + (size_t)(co0 + row) * 32 + kc * 8 + v;
                *reinterpret_cast<uint4*>(smem + OFF_AH + row * PITCH + v * 16) = WHl[g];
                *reinterpret_cast<uint4*>(smem + OFF_AL + row * PITCH + v * 16) = WLl[g];
            }
            // ---- fill B (pixels) [128 px][64 ci] hi/lo, tap-shifted ----
#pragma unroll
            for (int t = tid; t < 1024; t += 256) {
                int r = t >> 3, v = t & 7;
                int p = p0 + r;
                int x = p & (W - 1), y = p >> lgW;
                size_t src = (nbase + (size_t)(y + ky) * Wp + (x + kx)) * 32 + kc * 8 + v;
                *reinterpret_cast<uint4*>(smem + OFF_BH + r * PITCH + v * 16) = XH[src];
                *reinterpret_cast<uint4*>(smem + OFF_BL + r * PITCH + v * 16) = XL[src];
            }
            __syncthreads();

            const int m0 = warp_m * 32;
            const int n0 = warp_n * 64;
#pragma unroll
            for (int ks = 0; ks < 4; ks++) {
                uint32_t ah[2][4], al[2][4], bb[4][4];
                // A fragments: quadrants (m0,k0)(m8,k0)(m0,k8)(m8,k8)
#pragma unroll
                for (int mt = 0; mt < 2; mt++) {
                    uint32_t off = (uint32_t)((m0 + mt * 16 + matr * 8 + lrow) * PITCH
                                              + (ks * 16 + matc * 8) * 2);
                    ldsm_x4(ah[mt][0], ah[mt][1], ah[mt][2], ah[mt][3], sAH + off);
                    ldsm_x4(al[mt][0], al[mt][1], al[mt][2], al[mt][3], sAL + off);
                }
                // B hi fragments: quadrants (n0,k0)(n0,k8)(n8,k0)(n8,k8)
#pragma unroll
                for (int np = 0; np < 4; np++) {
                    uint32_t off = (uint32_t)((n0 + np * 16 + matc * 8 + lrow) * PITCH
                                              + (ks * 16 + matr * 8) * 2);
                    ldsm_x4(bb[np][0], bb[np][1], bb[np][2], bb[np][3], sBH + off);
                }
#pragma unroll
                for (int mt = 0; mt < 2; mt++)
#pragma unroll
                    for (int np = 0; np < 4; np++) {
                        mma_bf16(acc[mt][np * 2 + 0], ah[mt], &bb[np][0]);
                        mma_bf16(acc[mt][np * 2 + 1], ah[mt], &bb[np][2]);
                        mma_bf16(acc[mt][np * 2 + 0], al[mt], &bb[np][0]);
                        mma_bf16(acc[mt][np * 2 + 1], al[mt], &bb[np][2]);
                    }
                // B lo fragments (overwrite bb)
#pragma unroll
                for (int np = 0; np < 4; np++) {
                    uint32_t off = (uint32_t)((n0 + np * 16 + matc * 8 + lrow) * PITCH
                                              + (ks * 16 + matr * 8) * 2);
                    ldsm_x4(bb[np][0], bb[np][1], bb[np][2], bb[np][3], sBL + off);
                }
#pragma unroll
                for (int mt = 0; mt < 2; mt++)
#pragma unroll
                    for (int np = 0; np < 4; np++) {
                        mma_bf16(acc[mt][np * 2 + 0], ah[mt], &bb[np][0]);
                        mma_bf16(acc[mt][np * 2 + 1], ah[mt], &bb[np][2]);
                    }
            }
            __syncthreads();
        }
    }

    // ---- epilogue ----
    __shared__ float redS[8][2], redQ[8][2];
    const int qrow = lane >> 2, qcol = (lane & 3) * 2;
    float sg[2] = {0.0f, 0.0f}, qg[2] = {0.0f, 0.0f};

#pragma unroll
    for (int mt = 0; mt < 2; mt++) {
#pragma unroll
        for (int h8 = 0; h8 < 2; h8++) {
            const int col_ = co0 + warp_m * 32 + mt * 16 + qrow + h8 * 8;
            const float b = bias[col_];
#pragma unroll
            for (int nt = 0; nt < 8; nt++) {
#pragma unroll
                for (int c = 0; c < 2; c++) {
                    int p = p0 + warp_n * 64 + nt * 8 + qcol + c;
                    float v = acc[mt][nt][h8 * 2 + c] + b;
                    if (p < HW) {
                        int x = p & (W - 1), y = p >> lgW;
                        Y[(nbase + (size_t)(y + 1) * Wp + (x + 1)) * CC + col_] = v;
                        sg[mt] += v;
                        qg[mt] += v * v;
                    }
                }
            }
        }
    }
#pragma unroll
    for (int off = 16; off > 0; off >>= 1) {
#pragma unroll
        for (int mt = 0; mt < 2; mt++) {
            sg[mt] += __shfl_down_sync(0xffffffffu, sg[mt], off);
            qg[mt] += __shfl_down_sync(0xffffffffu, qg[mt], off);
        }
    }
    if (lane == 0) {
        redS[wid][0] = sg[0]; redS[wid][1] = sg[1];
        redQ[wid][0] = qg[0]; redQ[wid][1] = qg[1];
    }
    __syncthreads();
    if (tid < 8) {
        int wm = tid >> 1, mt = tid & 1;
        float S = redS[wm * 2][mt] + redS[wm * 2 + 1][mt];
        float Q = redQ[wm * 2][mt] + redQ[wm * 2 + 1][mt];
        size_t pidx = (size_t)z * gridDim.x + blockIdx.x;
        part[pidx * 8 + tid] = make_float2(S, Q);
    }
}

// ============================================================
// GN finalize: 128 blocks = (n, group), sums partials.
// ============================================================
__global__ __launch_bounds__(256) void gn_finalize(
    const float2* __restrict__ part, float* __restrict__ stats,
    int GX, int GY, int HW)
{
    const int b = blockIdx.x;
    const int n = b >> 4, grp = b & 15;
    const int half = grp >> 3, i = grp & 7;
    const int bz = n * 2 + half;
    const int nb = GX * GY;

    float S = 0.0f, Q = 0.0f;
    for (int t = threadIdx.x; t < nb; t += 256) {
        float2 p = part[(size_t)(bz * nb + t) * 8 + i];
        S += p.x; Q += p.y;
    }
    __shared__ float sS[256], sQ[256];
    sS[threadIdx.x] = S; sQ[threadIdx.x] = Q;
    __syncthreads();
    for (int off = 128; off > 0; off >>= 1) {
        if (threadIdx.x < off) {
            sS[threadIdx.x] += sS[threadIdx.x + off];
            sQ[threadIdx.x] += sQ[threadIdx.x + off];
        }
        __syncthreads();
    }
    if (threadIdx.x == 0) {
        float cnt  = (float)(GSIZE * HW);
        float mean = sS[0] / cnt;
        float var  = sQ[0] / cnt - mean * mean;
        stats[2 * b]     = mean;
        stats[2 * b + 1] = rsqrtf(var + GN_EPS);
    }
}

// ============================================================
// Output conv: reads padded-NHWC fp32 Y with GN+ReLU on load. Scalar.
// ============================================================
template <int COUT, int MODE>
__global__ __launch_bounds__(256) void outconv(
    const float* __restrict__ in, const float* __restrict__ w,
    const float* __restrict__ bias, float* __restrict__ out,
    int H, int W, int poff, int Wp, int HpWp,
    const float* __restrict__ stats_in,
    const float* __restrict__ gam, const float* __restrict__ bet)
{
    const int tx = blockIdx.x * 16;
    const int ty = blockIdx.y * 8;
    const int n  = blockIdx.z;
    const int tid = threadIdx.x;
    const int px  = tid & 127;
    const int half = tid >> 7;
    const int row = px >> 4;
    const int col = px & 15;

    constexpr int COH = (COUT + 1) / 2;
    const int cobase = half * COH;
    const int conum  = (COUT - cobase) < COH ? (COUT - cobase) : COH;

    __shared__ float Ws[COUT * 72];
    __shared__ float Xs[8 * 200];

    float acc[COH];
#pragma unroll
    for (int c = 0; c < COH; c++) acc[c] = 0.0f;

    const size_t nbase = (size_t)n * HpWp;

#pragma unroll 1
    for (int ci0 = 0; ci0 < CC; ci0 += 8) {
        for (int l = tid; l < 1440; l += 256) {       // 180 px * 8 ci, ci fastest
            int ci  = l & 7;
            int pxi = l >> 3;
            int ry  = pxi / 18;
            int cx  = pxi - ry * 18;
            int gy = ty - 1 + ry, gx = tx - 1 + cx;
            float v = 0.0f;
            if (gy >= 0 && gy < H && gx >= 0 && gx < W) {
                int c = ci0 + ci;
                v = in[(nbase + (size_t)(gy + 1) * Wp + (gx + 1)) * CC + c];
                int sg = (n * NGROUPS + (c >> 4)) * 2;
                v = (v - stats_in[sg]) * stats_in[sg + 1] * gam[c] + bet[c];
                v = fmaxf(v, 0.0f);
            }
            Xs[ci * 200 + ry * 20 + cx] = v;
        }
        const float* wg = w + (size_t)ci0 * 9;
        for (int l = tid; l < COUT * 72; l += 256) {
            int co = l / 72;
            int r  = l - co * 72;
            Ws[l] = wg[(size_t)co * 2304 + r];
        }
        __syncthreads();

#pragma unroll 1
        for (int ci = 0; ci < 8; ci++) {
            const float* xrow = &Xs[ci * 200];
#pragma unroll
            for (int k = 0; k < 9; k++) {
                const int ky = k / 3, kx = k - ky * 3;
                float x = xrow[(row + ky) * 20 + col + kx];
#pragma unroll
                for (int c = 0; c < COH; c++)
                    if (c < conum)
                        acc[c] += Ws[(cobase + c) * 72 + ci * 9 + k] * x;
            }
        }
        __syncthreads();
    }

    const int gy = ty + row;
    if (gy < H && conum > 0) {
        const int pix = poff + gy * W + tx + col;
        const size_t gp = (size_t)n * TOTHW + pix;
#pragma unroll
        for (int c = 0; c < COH; c++) {
            if (c >= conum) break;
            const int co = cobase + c;
            float v = acc[c] + bias[co];
            if (MODE == 0)      out[CLSBASE + gp * 20 + co] = v;
            else if (MODE == 1) out[REGBASE + gp * 4 + co] = fmaxf(v, 0.0f);
            else                out[CTRBASE + gp] = v;
        }
    }
}

// ============================================================
// host launcher
// ============================================================
extern "C" void kernel_launch(void* const* d_in, const int* in_sizes, int n_in,
                              void* d_out, int out_size)
{
    (void)in_sizes; (void)n_in; (void)out_size;

    const float* feat[3] = { (const float*)d_in[0], (const float*)d_in[1],
                             (const float*)d_in[2] };
    const float* cls_conv_w = (const float*)d_in[3];
    const float* cls_conv_b = (const float*)d_in[4];
    const float* cls_gn_g   = (const float*)d_in[5];
    const float* cls_gn_b   = (const float*)d_in[6];
    const float* cls_out_w  = (const float*)d_in[7];
    const float* cls_out_b  = (const float*)d_in[8];
    const float* reg_conv_w = (const float*)d_in[9];
    const float* reg_conv_b = (const float*)d_in[10];
    const float* reg_gn_g   = (const float*)d_in[11];
    const float* reg_gn_b   = (const float*)d_in[12];
    const float* reg_out_w  = (const float*)d_in[13];
    const float* reg_out_b  = (const float*)d_in[14];
    const float* ctr_w      = (const float*)d_in[15];
    const float* ctr_b      = (const float*)d_in[16];

    float* out = (float*)d_out;

    __nv_bfloat16 *XFH, *XFL, *XTH, *XTL, *WH, *WL;
    float *YA, *YB, *stats;
    float2* part;
    cudaGetSymbolAddress((void**)&XFH, g_XFH);
    cudaGetSymbolAddress((void**)&XFL, g_XFL);
    cudaGetSymbolAddress((void**)&XTH, g_XTH);
    cudaGetSymbolAddress((void**)&XTL, g_XTL);
    cudaGetSymbolAddress((void**)&YA, g_YA);
    cudaGetSymbolAddress((void**)&YB, g_YB);
    cudaGetSymbolAddress((void**)&WH, g_WH);
    cudaGetSymbolAddress((void**)&WL, g_WL);
    cudaGetSymbolAddress((void**)&stats, g_stats);
    cudaGetSymbolAddress((void**)&part, g_part);

    cudaFuncSetAttribute(convM, cudaFuncAttributeMaxDynamicSharedMemorySize, SMEMSZ);

    const int TGRID = (WELEM + 255) / 256;
    wsplit<<<TGRID, 256>>>(cls_conv_w,          WH + 0 * (size_t)WELEM, WL + 0 * (size_t)WELEM);
    wsplit<<<TGRID, 256>>>(cls_conv_w + WELEM,  WH + 1 * (size_t)WELEM, WL + 1 * (size_t)WELEM);
    wsplit<<<TGRID, 256>>>(reg_conv_w,          WH + 2 * (size_t)WELEM, WL + 2 * (size_t)WELEM);
    wsplit<<<TGRID, 256>>>(reg_conv_w + WELEM,  WH + 3 * (size_t)WELEM, WL + 3 * (size_t)WELEM);

    const int LH[3] = {100, 50, 25};
    const int LW[3] = {128, 64, 32};
    const int LG[3] = {7, 6, 5};
    const int LP[3] = {0, 12800, 16000};

    for (int L = 0; L < 3; L++) {
        const int H = LH[L], W = LW[L], lgW = LG[L];
        const int Hp = H + 2, Wp = W + 2, HpWp = Hp * Wp, HW = H * W;
        const int PT = (HW + 127) / 128;
        const int poff = LP[L];

        dim3 cgrid(PT, 1, 16);
        dim3 ogrid(W / 16, (H + 7) / 8, NB);
        dim3 fgrid(W / 32, H, NB * 8);
        dim3 fblk(32, 32);

        zerok<<<2048, 256>>>((uint4*)XFH, (size_t)XCAP / 8);
        zerok<<<2048, 256>>>((uint4*)XFL, (size_t)XCAP / 8);
        featprep<<<fgrid, fblk>>>(feat[L], XFH, XFL, H, W, Wp, HpWp);

        for (int tw = 0; tw < 2; tw++) {
            const __nv_bfloat16* wh0 = WH + (size_t)(tw * 2 + 0) * WELEM;
            const __nv_bfloat16* wl0 = WL + (size_t)(tw * 2 + 0) * WELEM;
            const __nv_bfloat16* wh1 = WH + (size_t)(tw * 2 + 1) * WELEM;
            const __nv_bfloat16* wl1 = WL + (size_t)(tw * 2 + 1) * WELEM;
            const float* cb = tw ? reg_conv_b : cls_conv_b;
            const float* gg = tw ? reg_gn_g   : cls_gn_g;
            const float* gb = tw ? reg_gn_b   : cls_gn_b;

            convM<<<cgrid, 256, SMEMSZ>>>(
                (const uint4*)XFH, (const uint4*)XFL,
                (const uint4*)wh0, (const uint4*)wl0,
                cb, YA, part, H, W, Wp, lgW, HW, HpWp);
            gn_finalize<<<NB * NGROUPS, 256>>>(part, stats, PT, 1, HW);
            actk<<<2048, 256>>>(YA, stats, gg, gb, XTH, XTL, H, W, Wp, HpWp);

            convM<<<cgrid, 256, SMEMSZ>>>(
                (const uint4*)XTH, (const uint4*)XTL,
                (const uint4*)wh1, (const uint4*)wl1,
                cb + CC, YB, part, H, W, Wp, lgW, HW, HpWp);
            gn_finalize<<<NB * NGROUPS, 256>>>(part, stats, PT, 1, HW);

            if (tw == 0) {
                outconv<20, 0><<<ogrid, 256>>>(YB, cls_out_w, cls_out_b, out,
                                               H, W, poff, Wp, HpWp,
                                               stats, gg + CC, gb + CC);
            } else {
                outconv<4, 1><<<ogrid, 256>>>(YB, reg_out_w, reg_out_b, out,
                                              H, W, poff, Wp, HpWp,
                                              stats, gg + CC, gb + CC);
                outconv<1, 2><<<ogrid, 256>>>(YB, ctr_w, ctr_b, out,
                                              H, W, poff, Wp, HpWp,
                                              stats, gg + CC, gb + CC);
            }
        }
    }
}

// round 7
// speedup vs baseline: 5.4028x; 1.1402x over previous
#include <cuda_runtime.h>
#include <cuda_bf16.h>
#include <math.h>
#include <stdint.h>

// ---------------- problem constants ----------------
#define NB 8
#define CC 256
#define NGROUPS 16
#define GSIZE 16
#define GN_EPS 1e-5f

#define TOTHW   16800
#define CLSBASE 0
#define REGBASE 2688000
#define CTRBASE 3225600

#define WELEM (CC * CC * 9)       // 589824 per tower layer
#define WOELEM (9 * 32 * 256)     // 73728 per head set

// padded-NHWC buffer capacity: level0 = 8*102*130*256 = 27,156,480 (+slack)
#define XCAP 27500000
#define YCAP 27160000

// scratch (device globals; zero-initialized, no runtime allocation)
__device__ __align__(16) __nv_bfloat16 g_XFH[XCAP];
__device__ __align__(16) __nv_bfloat16 g_XFL[XCAP];
__device__ __align__(16) __nv_bfloat16 g_XTH[XCAP];
__device__ __align__(16) __nv_bfloat16 g_XTL[XCAP];
__device__ __align__(16) float g_YA[YCAP];
__device__ __align__(16) float g_YB[YCAP];
__device__ __align__(16) __nv_bfloat16 g_WH[4 * WELEM];    // [layer][tap][co][ci] hi
__device__ __align__(16) __nv_bfloat16 g_WL[4 * WELEM];    // lo
__device__ __align__(16) __nv_bfloat16 g_WOH[2 * WOELEM];  // head weights hi
__device__ __align__(16) __nv_bfloat16 g_WOL[2 * WOELEM];  // lo
__device__ float  g_stats[NB * NGROUPS * 2];
__device__ float2 g_part[16 * 104 * 8];

// ---------------- PTX helpers (arch-agnostic sm_80+) ----------------
__device__ __forceinline__ uint32_t smem_u32(const void* p) {
    uint32_t a;
    asm("{ .reg .u64 t; cvta.to.shared.u64 t, %1; cvt.u32.u64 %0, t; }"
        : "=r"(a) : "l"(p));
    return a;
}
__device__ __forceinline__ void ldsm_x4(uint32_t& r0, uint32_t& r1,
                                        uint32_t& r2, uint32_t& r3, uint32_t a) {
    asm volatile("ldmatrix.sync.aligned.m8n8.x4.shared.b16 {%0,%1,%2,%3}, [%4];"
        : "=r"(r0), "=r"(r1), "=r"(r2), "=r"(r3) : "r"(a));
}
__device__ __forceinline__ void mma_bf16(float* d, const uint32_t* a,
                                         const uint32_t* b) {
    asm volatile("mma.sync.aligned.m16n8k16.row.col.f32.bf16.bf16.f32 "
        "{%0,%1,%2,%3}, {%4,%5,%6,%7}, {%8,%9}, {%0,%1,%2,%3};"
        : "+f"(d[0]), "+f"(d[1]), "+f"(d[2]), "+f"(d[3])
        : "r"(a[0]), "r"(a[1]), "r"(a[2]), "r"(a[3]), "r"(b[0]), "r"(b[1]));
}
__device__ __forceinline__ void cpa16(uint32_t d, const void* s) {
    asm volatile("cp.async.cg.shared.global [%0], [%1], 16;"
                 :: "r"(d), "l"(s) : "memory");
}
#define CPA_COMMIT() asm volatile("cp.async.commit_group;" ::: "memory")
#define CPA_WAIT1()  asm volatile("cp.async.wait_group 1;" ::: "memory")
#define CPA_WAIT0()  asm volatile("cp.async.wait_group 0;" ::: "memory")

// smem geometry: 144B pitch (conflict-free ldmatrix), two pipeline stages
#define PITCH 144
#define OAH 0
#define OAL 18432
#define OBH 36864
#define OBL 55296
#define STG_SZ 73728
#define SMEMSZ (2 * STG_SZ)      // 147456

// convO static smem offsets
#define QAH 0
#define QAL 4608
#define QBH 9216
#define QBL 27648
#define QSZ 46080

// ============================================================
// wsplit: w[co][ci][tap] fp32 -> WH/WL[tap][co][ci] bf16 hi/lo
// ============================================================
__global__ __launch_bounds__(256) void wsplit(
    const float* __restrict__ w, __nv_bfloat16* __restrict__ WH,
    __nv_bfloat16* __restrict__ WL)
{
    int idx = blockIdx.x * 256 + threadIdx.x;
    if (idx >= WELEM) return;
    int tap = idx / 65536;
    int r   = idx - tap * 65536;
    int co  = r >> 8, ci = r & 255;
    float v = w[co * 2304 + ci * 9 + tap];
    __nv_bfloat16 h = __float2bfloat16(v);
    WH[idx] = h;
    WL[idx] = __float2bfloat16(v - __bfloat162float(h));
}

// ============================================================
// woprep: pack head weights into [set][tap][row32][ci] hi/lo.
// set0: rows 0..19 = cls_out_w.  set1: rows 0..3 = reg_out_w, row4 = ctr_w.
// ============================================================
__global__ __launch_bounds__(256) void woprep(
    const float* __restrict__ clsw, const float* __restrict__ regw,
    const float* __restrict__ ctrw,
    __nv_bfloat16* __restrict__ WOH, __nv_bfloat16* __restrict__ WOL)
{
    int idx = blockIdx.x * 256 + threadIdx.x;
    if (idx >= 2 * WOELEM) return;
    int set = idx / WOELEM;
    int r   = idx - set * WOELEM;
    int tap = r / 8192;
    int r2  = r - tap * 8192;
    int row = r2 >> 8, ci = r2 & 255;
    float v = 0.0f;
    if (set == 0) {
        if (row < 20) v = clsw[(row * 256 + ci) * 9 + tap];
    } else {
        if (row < 4)       v = regw[(row * 256 + ci) * 9 + tap];
        else if (row == 4) v = ctrw[ci * 9 + tap];
    }
    __nv_bfloat16 h = __float2bfloat16(v);
    WOH[idx] = h;
    WOL[idx] = __float2bfloat16(v - __bfloat162float(h));
}

// ============================================================
// zerok: fill uint4 zeros
// ============================================================
__global__ __launch_bounds__(256) void zerok(uint4* __restrict__ p, size_t n16)
{
    size_t stride = (size_t)gridDim.x * 256;
    uint4 z = make_uint4(0, 0, 0, 0);
    for (size_t i = (size_t)blockIdx.x * 256 + threadIdx.x; i < n16; i += stride)
        p[i] = z;
}

// ============================================================
// featprep: NCHW fp32 -> padded NHWC bf16 hi/lo (32x32 smem transpose)
// ============================================================
__global__ __launch_bounds__(1024) void featprep(
    const float* __restrict__ feat, __nv_bfloat16* __restrict__ XH,
    __nv_bfloat16* __restrict__ XL, int H, int W, int Wp, int HpWp)
{
    __shared__ float tile[32][33];
    int xt = blockIdx.x, y = blockIdx.y;
    int n  = blockIdx.z >> 3, ct = blockIdx.z & 7;
    int tx = threadIdx.x, ty = threadIdx.y;

    tile[ty][tx] = feat[(((size_t)n * CC + ct * 32 + ty) * H + y) * W + xt * 32 + tx];
    __syncthreads();

    int c = ct * 32 + tx;
    int x = xt * 32 + ty;
    float v = tile[tx][ty];
    size_t a = ((size_t)n * HpWp + (size_t)(y + 1) * Wp + (x + 1)) * CC + c;
    __nv_bfloat16 h = __float2bfloat16(v);
    XH[a] = h;
    XL[a] = __float2bfloat16(v - __bfloat162float(h));
}

// ============================================================
// actk: Y (padded NHWC fp32) -> GN+ReLU -> split bf16 hi/lo; pads zero.
// ============================================================
__global__ __launch_bounds__(256) void actk(
    const float* __restrict__ Y, const float* __restrict__ stats,
    const float* __restrict__ gam, const float* __restrict__ bet,
    __nv_bfloat16* __restrict__ XH, __nv_bfloat16* __restrict__ XL,
    int H, int W, int Wp, int HpWp)
{
    size_t total = (size_t)NB * HpWp * CC;
    size_t stride = (size_t)gridDim.x * 256;
    for (size_t idx = (size_t)blockIdx.x * 256 + threadIdx.x; idx < total; idx += stride) {
        int c = (int)(idx & 255);
        size_t pix = idx >> 8;
        int n  = (int)(pix / HpWp);
        int pp = (int)(pix - (size_t)n * HpWp);
        int py = pp / Wp, px = pp - py * Wp;
        __nv_bfloat16 h = __float2bfloat16(0.0f), l = h;
        if (py >= 1 && py <= H && px >= 1 && px <= W) {
            float v = Y[idx];
            int sg = (n * NGROUPS + (c >> 4)) * 2;
            v = (v - stats[sg]) * stats[sg + 1] * gam[c] + bet[c];
            v = fmaxf(v, 0.0f);
            h = __float2bfloat16(v);
            l = __float2bfloat16(v - __bfloat162float(h));
        }
        XH[idx] = h;
        XL[idx] = l;
    }
}

// ============================================================
// convM: warp-mma 3x3 conv, cp.async double-buffered pipeline.
// CTA = 128co x 128px, 8 warps (4m x 2n), 1 CTA/SM (144KB smem).
// 36 chunks = 9 taps x 4 ci-chunks of 64. 3-term bf16 split.
// ============================================================
__global__ __launch_bounds__(256) void convM(
    const uint4* __restrict__ XH, const uint4* __restrict__ XL,
    const uint4* __restrict__ WHl, const uint4* __restrict__ WLl,
    const float* __restrict__ bias, float* __restrict__ Y,
    float2* __restrict__ part,
    int H, int W, int Wp, int lgW, int HW, int HpWp)
{
    extern __shared__ char smem[];
    const uint32_t sb0 = smem_u32(smem);

    const int tid = threadIdx.x, wid = tid >> 5, lane = tid & 31;
    const int warp_m = wid >> 1, warp_n = wid & 1;
    const int p0 = blockIdx.x * 128;
    const int z = blockIdx.z;
    const int n = z >> 1, co0 = (z & 1) * 128;
    const size_t nbase = (size_t)n * HpWp;

    float acc[2][8][4];
#pragma unroll
    for (int mt = 0; mt < 2; mt++)
#pragma unroll
        for (int nt = 0; nt < 8; nt++)
#pragma unroll
            for (int i = 0; i < 4; i++) acc[mt][nt][i] = 0.0f;

    const int lrow = lane & 7;
    const int matr = (lane >> 3) & 1;
    const int matc = lane >> 4;

    // ---- async fill of one (tap, kc) chunk into a stage ----
    auto fill = [&](int c, uint32_t sbase) {
        const int tap = c >> 2, kc = c & 3;
        const int ky = tap / 3, kx = tap - ky * 3;
#pragma unroll
        for (int t = tid; t < 1024; t += 256) {
            int row = t >> 3, v = t & 7;
            uint32_t d = sbase + (uint32_t)(row * PITCH + v * 16);
            size_t g = (size_t)tap * 8192 + (size_t)(co0 + row) * 32 + kc * 8 + v;
            cpa16(d + OAH, WHl + g);
            cpa16(d + OAL, WLl + g);
            int p = p0 + row;
            int x = p & (W - 1), y = p >> lgW;
            size_t src = (nbase + (size_t)(y + ky) * Wp + (x + kx)) * 32 + kc * 8 + v;
            cpa16(d + OBH, XH + src);
            cpa16(d + OBL, XL + src);
        }
        CPA_COMMIT();
    };

    fill(0, sb0);

#pragma unroll 1
    for (int c = 0; c < 36; c++) {
        if (c + 1 < 36) {
            fill(c + 1, sb0 + (uint32_t)(((c + 1) & 1) * STG_SZ));
            CPA_WAIT1();
        } else {
            CPA_WAIT0();
        }
        __syncthreads();

        const uint32_t base = sb0 + (uint32_t)((c & 1) * STG_SZ);
        const uint32_t sAH = base + OAH, sAL = base + OAL;
        const uint32_t sBH = base + OBH, sBL = base + OBL;
        const int m0 = warp_m * 32;
        const int n0 = warp_n * 64;
#pragma unroll
        for (int ks = 0; ks < 4; ks++) {
            uint32_t ah[2][4], al[2][4], bb[4][4];
#pragma unroll
            for (int mt = 0; mt < 2; mt++) {
                uint32_t off = (uint32_t)((m0 + mt * 16 + matr * 8 + lrow) * PITCH
                                          + (ks * 16 + matc * 8) * 2);
                ldsm_x4(ah[mt][0], ah[mt][1], ah[mt][2], ah[mt][3], sAH + off);
                ldsm_x4(al[mt][0], al[mt][1], al[mt][2], al[mt][3], sAL + off);
            }
#pragma unroll
            for (int np = 0; np < 4; np++) {
                uint32_t off = (uint32_t)((n0 + np * 16 + matc * 8 + lrow) * PITCH
                                          + (ks * 16 + matr * 8) * 2);
                ldsm_x4(bb[np][0], bb[np][1], bb[np][2], bb[np][3], sBH + off);
            }
#pragma unroll
            for (int mt = 0; mt < 2; mt++)
#pragma unroll
                for (int np = 0; np < 4; np++) {
                    mma_bf16(acc[mt][np * 2 + 0], ah[mt], &bb[np][0]);
                    mma_bf16(acc[mt][np * 2 + 1], ah[mt], &bb[np][2]);
                    mma_bf16(acc[mt][np * 2 + 0], al[mt], &bb[np][0]);
                    mma_bf16(acc[mt][np * 2 + 1], al[mt], &bb[np][2]);
                }
#pragma unroll
            for (int np = 0; np < 4; np++) {
                uint32_t off = (uint32_t)((n0 + np * 16 + matc * 8 + lrow) * PITCH
                                          + (ks * 16 + matr * 8) * 2);
                ldsm_x4(bb[np][0], bb[np][1], bb[np][2], bb[np][3], sBL + off);
            }
#pragma unroll
            for (int mt = 0; mt < 2; mt++)
#pragma unroll
                for (int np = 0; np < 4; np++) {
                    mma_bf16(acc[mt][np * 2 + 0], ah[mt], &bb[np][0]);
                    mma_bf16(acc[mt][np * 2 + 1], ah[mt], &bb[np][2]);
                }
        }
        __syncthreads();
    }

    // ---- epilogue: bias, store padded NHWC fp32, deterministic GN partials ----
    __shared__ float redS[8][2], redQ[8][2];
    const int qrow = lane >> 2, qcol = (lane & 3) * 2;
    float sg[2] = {0.0f, 0.0f}, qg[2] = {0.0f, 0.0f};

#pragma unroll
    for (int mt = 0; mt < 2; mt++) {
#pragma unroll
        for (int h8 = 0; h8 < 2; h8++) {
            const int col_ = co0 + warp_m * 32 + mt * 16 + qrow + h8 * 8;
            const float b = bias[col_];
#pragma unroll
            for (int nt = 0; nt < 8; nt++) {
#pragma unroll
                for (int cc2 = 0; cc2 < 2; cc2++) {
                    int p = p0 + warp_n * 64 + nt * 8 + qcol + cc2;
                    float v = acc[mt][nt][h8 * 2 + cc2] + b;
                    if (p < HW) {
                        int x = p & (W - 1), y = p >> lgW;
                        Y[(nbase + (size_t)(y + 1) * Wp + (x + 1)) * CC + col_] = v;
                        sg[mt] += v;
                        qg[mt] += v * v;
                    }
                }
            }
        }
    }
#pragma unroll
    for (int off = 16; off > 0; off >>= 1) {
#pragma unroll
        for (int mt = 0; mt < 2; mt++) {
            sg[mt] += __shfl_down_sync(0xffffffffu, sg[mt], off);
            qg[mt] += __shfl_down_sync(0xffffffffu, qg[mt], off);
        }
    }
    if (lane == 0) {
        redS[wid][0] = sg[0]; redS[wid][1] = sg[1];
        redQ[wid][0] = qg[0]; redQ[wid][1] = qg[1];
    }
    __syncthreads();
    if (tid < 8) {
        int wm = tid >> 1, mt = tid & 1;
        float S = redS[wm * 2][mt] + redS[wm * 2 + 1][mt];
        float Q = redQ[wm * 2][mt] + redQ[wm * 2 + 1][mt];
        size_t pidx = (size_t)z * gridDim.x + blockIdx.x;
        part[pidx * 8 + tid] = make_float2(S, Q);
    }
}

// ============================================================
// convO: head convs as warp-mma, M=32 (cls: 20 rows / reg: 4 + ctr: 1).
// CTA = 32co x 128px, 8 warps each 32co x 16px. grid (PT, 1, NB).
// mode 0 = cls head; mode 1 = reg+ctr heads.
// ============================================================
__global__ __launch_bounds__(256) void convO(
    const uint4* __restrict__ XH, const uint4* __restrict__ XL,
    const uint4* __restrict__ WOH, const uint4* __restrict__ WOL,
    const float* __restrict__ clsb, const float* __restrict__ regb,
    const float* __restrict__ ctrb, float* __restrict__ out,
    int H, int W, int Wp, int lgW, int HW, int HpWp, int poff, int mode)
{
    __shared__ __align__(16) char smem[QSZ];
    const uint32_t sb = smem_u32(smem);
    const uint32_t sAH = sb + QAH, sAL = sb + QAL;
    const uint32_t sBH = sb + QBH, sBL = sb + QBL;

    const int tid = threadIdx.x, wid = tid >> 5, lane = tid & 31;
    const int p0 = blockIdx.x * 128;
    const int n = blockIdx.z;
    const size_t nbase = (size_t)n * HpWp;

    float acc[2][2][4];
#pragma unroll
    for (int mt = 0; mt < 2; mt++)
#pragma unroll
        for (int nt = 0; nt < 2; nt++)
#pragma unroll
            for (int i = 0; i < 4; i++) acc[mt][nt][i] = 0.0f;

    const int lrow = lane & 7;
    const int matr = (lane >> 3) & 1;
    const int matc = lane >> 4;

#pragma unroll 1
    for (int tap = 0; tap < 9; tap++) {
        const int ky = tap / 3, kx = tap - ky * 3;
#pragma unroll 1
        for (int kc = 0; kc < 4; kc++) {
            // A: 32 rows x 64 ci (256 uint4 each hi/lo)
            if (tid < 256) {
                int row = tid >> 3, v = tid & 7;
                size_t g = (size_t)tap * 1024 + (size_t)row * 32 + kc * 8 + v;
                *reinterpret_cast<uint4*>(smem + QAH + row * PITCH + v * 16) = WOH[g];
                *reinterpret_cast<uint4*>(smem + QAL + row * PITCH + v * 16) = WOL[g];
            }
            // B: 128 px x 64 ci
#pragma unroll
            for (int t = tid; t < 1024; t += 256) {
                int r = t >> 3, v = t & 7;
                int p = p0 + r;
                int x = p & (W - 1), y = p >> lgW;
                size_t src = (nbase + (size_t)(y + ky) * Wp + (x + kx)) * 32 + kc * 8 + v;
                *reinterpret_cast<uint4*>(smem + QBH + r * PITCH + v * 16) = XH[src];
                *reinterpret_cast<uint4*>(smem + QBL + r * PITCH + v * 16) = XL[src];
            }
            __syncthreads();

            const int n0 = wid * 16;
#pragma unroll
            for (int ks = 0; ks < 4; ks++) {
                uint32_t ah[2][4], al[2][4], bh[4], bl[4];
#pragma unroll
                for (int mt = 0; mt < 2; mt++) {
                    uint32_t off = (uint32_t)((mt * 16 + matr * 8 + lrow) * PITCH
                                              + (ks * 16 + matc * 8) * 2);
                    ldsm_x4(ah[mt][0], ah[mt][1], ah[mt][2], ah[mt][3], sAH + off);
                    ldsm_x4(al[mt][0], al[mt][1], al[mt][2], al[mt][3], sAL + off);
                }
                uint32_t offB = (uint32_t)((n0 + matc * 8 + lrow) * PITCH
                                           + (ks * 16 + matr * 8) * 2);
                ldsm_x4(bh[0], bh[1], bh[2], bh[3], sBH + offB);
                ldsm_x4(bl[0], bl[1], bl[2], bl[3], sBL + offB);
#pragma unroll
                for (int mt = 0; mt < 2; mt++) {
                    mma_bf16(acc[mt][0], ah[mt], &bh[0]);
                    mma_bf16(acc[mt][1], ah[mt], &bh[2]);
                    mma_bf16(acc[mt][0], al[mt], &bh[0]);
                    mma_bf16(acc[mt][1], al[mt], &bh[2]);
                    mma_bf16(acc[mt][0], ah[mt], &bl[0]);
                    mma_bf16(acc[mt][1], ah[mt], &bl[2]);
                }
            }
            __syncthreads();
        }
    }

    // ---- epilogue: scatter into concat output layout ----
    const int qrow = lane >> 2, qcol = (lane & 3) * 2;
#pragma unroll
    for (int mt = 0; mt < 2; mt++) {
#pragma unroll
        for (int h8 = 0; h8 < 2; h8++) {
            const int row = mt * 16 + h8 * 8 + qrow;
#pragma unroll
            for (int nt = 0; nt < 2; nt++) {
#pragma unroll
                for (int cc2 = 0; cc2 < 2; cc2++) {
                    int p = p0 + wid * 16 + nt * 8 + qcol + cc2;
                    if (p >= HW) continue;
                    float v = acc[mt][nt][h8 * 2 + cc2];
                    int x = p & (W - 1), y = p >> lgW;
                    size_t gp = (size_t)n * TOTHW + poff + (size_t)y * W + x;
                    if (mode == 0) {
                        if (row < 20) out[CLSBASE + gp * 20 + row] = v + clsb[row];
                    } else {
                        if (row < 4)
                            out[REGBASE + gp * 4 + row] = fmaxf(v + regb[row], 0.0f);
                        else if (row == 4)
                            out[CTRBASE + gp] = v + ctrb[0];
                    }
                }
            }
        }
    }
}

// ============================================================
// GN finalize: 128 blocks = (n, group), sums partials.
// ============================================================
__global__ __launch_bounds__(256) void gn_finalize(
    const float2* __restrict__ part, float* __restrict__ stats,
    int GX, int GY, int HW)
{
    const int b = blockIdx.x;
    const int n = b >> 4, grp = b & 15;
    const int half = grp >> 3, i = grp & 7;
    const int bz = n * 2 + half;
    const int nb = GX * GY;

    float S = 0.0f, Q = 0.0f;
    for (int t = threadIdx.x; t < nb; t += 256) {
        float2 p = part[(size_t)(bz * nb + t) * 8 + i];
        S += p.x; Q += p.y;
    }
    __shared__ float sS[256], sQ[256];
    sS[threadIdx.x] = S; sQ[threadIdx.x] = Q;
    __syncthreads();
    for (int off = 128; off > 0; off >>= 1) {
        if (threadIdx.x < off) {
            sS[threadIdx.x] += sS[threadIdx.x + off];
            sQ[threadIdx.x] += sQ[threadIdx.x + off];
        }
        __syncthreads();
    }
    if (threadIdx.x == 0) {
        float cnt  = (float)(GSIZE * HW);
        float mean = sS[0] / cnt;
        float var  = sQ[0] / cnt - mean * mean;
        stats[2 * b]     = mean;
        stats[2 * b + 1] = rsqrtf(var + GN_EPS);
    }
}

// ============================================================
// host launcher
// ============================================================
extern "C" void kernel_launch(void* const* d_in, const int* in_sizes, int n_in,
                              void* d_out, int out_size)
{
    (void)in_sizes; (void)n_in; (void)out_size;

    const float* feat[3] = { (const float*)d_in[0], (const float*)d_in[1],
                             (const float*)d_in[2] };
    const float* cls_conv_w = (const float*)d_in[3];
    const float* cls_conv_b = (const float*)d_in[4];
    const float* cls_gn_g   = (const float*)d_in[5];
    const float* cls_gn_b   = (const float*)d_in[6];
    const float* cls_out_w  = (const float*)d_in[7];
    const float* cls_out_b  = (const float*)d_in[8];
    const float* reg_conv_w = (const float*)d_in[9];
    const float* reg_conv_b = (const float*)d_in[10];
    const float* reg_gn_g   = (const float*)d_in[11];
    const float* reg_gn_b   = (const float*)d_in[12];
    const float* reg_out_w  = (const float*)d_in[13];
    const float* reg_out_b  = (const float*)d_in[14];
    const float* ctr_w      = (const float*)d_in[15];
    const float* ctr_b      = (const float*)d_in[16];

    float* out = (float*)d_out;

    __nv_bfloat16 *XFH, *XFL, *XTH, *XTL, *WH, *WL, *WOH, *WOL;
    float *YA, *YB, *stats;
    float2* part;
    cudaGetSymbolAddress((void**)&XFH, g_XFH);
    cudaGetSymbolAddress((void**)&XFL, g_XFL);
    cudaGetSymbolAddress((void**)&XTH, g_XTH);
    cudaGetSymbolAddress((void**)&XTL, g_XTL);
    cudaGetSymbolAddress((void**)&YA, g_YA);
    cudaGetSymbolAddress((void**)&YB, g_YB);
    cudaGetSymbolAddress((void**)&WH, g_WH);
    cudaGetSymbolAddress((void**)&WL, g_WL);
    cudaGetSymbolAddress((void**)&WOH, g_WOH);
    cudaGetSymbolAddress((void**)&WOL, g_WOL);
    cudaGetSymbolAddress((void**)&stats, g_stats);
    cudaGetSymbolAddress((void**)&part, g_part);

    cudaFuncSetAttribute(convM, cudaFuncAttributeMaxDynamicSharedMemorySize, SMEMSZ);

    const int TGRID = (WELEM + 255) / 256;
    wsplit<<<TGRID, 256>>>(cls_conv_w,          WH + 0 * (size_t)WELEM, WL + 0 * (size_t)WELEM);
    wsplit<<<TGRID, 256>>>(cls_conv_w + WELEM,  WH + 1 * (size_t)WELEM, WL + 1 * (size_t)WELEM);
    wsplit<<<TGRID, 256>>>(reg_conv_w,          WH + 2 * (size_t)WELEM, WL + 2 * (size_t)WELEM);
    wsplit<<<TGRID, 256>>>(reg_conv_w + WELEM,  WH + 3 * (size_t)WELEM, WL + 3 * (size_t)WELEM);
    woprep<<<(2 * WOELEM + 255) / 256, 256>>>(cls_out_w, reg_out_w, ctr_w, WOH, WOL);

    const int LH[3] = {100, 50, 25};
    const int LW[3] = {128, 64, 32};
    const int LG[3] = {7, 6, 5};
    const int LP[3] = {0, 12800, 16000};

    for (int L = 0; L < 3; L++) {
        const int H = LH[L], W = LW[L], lgW = LG[L];
        const int Hp = H + 2, Wp = W + 2, HpWp = Hp * Wp, HW = H * W;
        const int PT = (HW + 127) / 128;
        const int poff = LP[L];
        const size_t used16 = (size_t)NB * HpWp * CC / 8;

        dim3 cgrid(PT, 1, 16);
        dim3 hgrid(PT, 1, NB);
        dim3 fgrid(W / 32, H, NB * 8);
        dim3 fblk(32, 32);

        zerok<<<2048, 256>>>((uint4*)XFH, used16);
        zerok<<<2048, 256>>>((uint4*)XFL, used16);
        featprep<<<fgrid, fblk>>>(feat[L], XFH, XFL, H, W, Wp, HpWp);

        for (int tw = 0; tw < 2; tw++) {
            const __nv_bfloat16* wh0 = WH + (size_t)(tw * 2 + 0) * WELEM;
            const __nv_bfloat16* wl0 = WL + (size_t)(tw * 2 + 0) * WELEM;
            const __nv_bfloat16* wh1 = WH + (size_t)(tw * 2 + 1) * WELEM;
            const __nv_bfloat16* wl1 = WL + (size_t)(tw * 2 + 1) * WELEM;
            const float* cb = tw ? reg_conv_b : cls_conv_b;
            const float* gg = tw ? reg_gn_g   : cls_gn_g;
            const float* gb = tw ? reg_gn_b   : cls_gn_b;

            convM<<<cgrid, 256, SMEMSZ>>>(
                (const uint4*)XFH, (const uint4*)XFL,
                (const uint4*)wh0, (const uint4*)wl0,
                cb, YA, part, H, W, Wp, lgW, HW, HpWp);
            gn_finalize<<<NB * NGROUPS, 256>>>(part, stats, PT, 1, HW);
            actk<<<2048, 256>>>(YA, stats, gg, gb, XTH, XTL, H, W, Wp, HpWp);

            convM<<<cgrid, 256, SMEMSZ>>>(
                (const uint4*)XTH, (const uint4*)XTL,
                (const uint4*)wh1, (const uint4*)wl1,
                cb + CC, YB, part, H, W, Wp, lgW, HW, HpWp);
            gn_finalize<<<NB * NGROUPS, 256>>>(part, stats, PT, 1, HW);
            actk<<<2048, 256>>>(YB, stats, gg + CC, gb + CC, XTH, XTL, H, W, Wp, HpWp);

            const uint4* woh = (const uint4*)(WOH + (size_t)tw * WOELEM);
            const uint4* wol = (const uint4*)(WOL + (size_t)tw * WOELEM);
            convO<<<hgrid, 256>>>((const uint4*)XTH, (const uint4*)XTL, woh, wol,
                                  cls_out_b, reg_out_b, ctr_b, out,
                                  H, W, Wp, lgW, HW, HpWp, poff, tw);
        }
    }
}

// round 8
// speedup vs baseline: 5.5263x; 1.0228x over previous
#include <cuda_runtime.h>
#include <cuda_bf16.h>
#include <math.h>
#include <stdint.h>

// ---------------- problem constants ----------------
#define NB 8
#define CC 256
#define NGROUPS 16
#define GSIZE 16
#define GN_EPS 1e-5f

#define TOTHW   16800
#define CLSBASE 0
#define REGBASE 2688000
#define CTRBASE 3225600

#define WELEM (CC * CC * 9)       // 589824 per tower layer
#define WOELEM (9 * 32 * 256)     // 73728 per head set

#define XCAP 27500000
#define YCAP 27160000

// scratch (device globals; zero-initialized, no runtime allocation)
__device__ __align__(16) __nv_bfloat16 g_XFH[XCAP];
__device__ __align__(16) __nv_bfloat16 g_XFL[XCAP];
__device__ __align__(16) __nv_bfloat16 g_XTH[XCAP];
__device__ __align__(16) __nv_bfloat16 g_XTL[XCAP];
__device__ __align__(16) float g_YA[YCAP];
__device__ __align__(16) float g_YB[YCAP];
__device__ __align__(16) __nv_bfloat16 g_WH[4 * WELEM];
__device__ __align__(16) __nv_bfloat16 g_WL[4 * WELEM];
__device__ __align__(16) __nv_bfloat16 g_WOH[2 * WOELEM];
__device__ __align__(16) __nv_bfloat16 g_WOL[2 * WOELEM];
__device__ float  g_stats[NB * NGROUPS * 2];
__device__ float2 g_part[16 * 104 * 8];

// ---------------- PTX helpers (arch-agnostic sm_80+) ----------------
__device__ __forceinline__ uint32_t smem_u32(const void* p) {
    uint32_t a;
    asm("{ .reg .u64 t; cvta.to.shared.u64 t, %1; cvt.u32.u64 %0, t; }"
        : "=r"(a) : "l"(p));
    return a;
}
__device__ __forceinline__ void ldsm_x4(uint32_t& r0, uint32_t& r1,
                                        uint32_t& r2, uint32_t& r3, uint32_t a) {
    asm volatile("ldmatrix.sync.aligned.m8n8.x4.shared.b16 {%0,%1,%2,%3}, [%4];"
        : "=r"(r0), "=r"(r1), "=r"(r2), "=r"(r3) : "r"(a));
}
__device__ __forceinline__ void mma_bf16(float* d, const uint32_t* a,
                                         const uint32_t* b) {
    asm volatile("mma.sync.aligned.m16n8k16.row.col.f32.bf16.bf16.f32 "
        "{%0,%1,%2,%3}, {%4,%5,%6,%7}, {%8,%9}, {%0,%1,%2,%3};"
        : "+f"(d[0]), "+f"(d[1]), "+f"(d[2]), "+f"(d[3])
        : "r"(a[0]), "r"(a[1]), "r"(a[2]), "r"(a[3]), "r"(b[0]), "r"(b[1]));
}
__device__ __forceinline__ void cpa16(uint32_t d, const void* s) {
    asm volatile("cp.async.cg.shared.global [%0], [%1], 16;"
                 :: "r"(d), "l"(s) : "memory");
}
// zero-fill variant: bytes beyond src_sz are written as 0
__device__ __forceinline__ void cpa16z(uint32_t d, const void* s, uint32_t src_sz) {
    asm volatile("cp.async.cg.shared.global [%0], [%1], 16, %2;"
                 :: "r"(d), "l"(s), "r"(src_sz) : "memory");
}
#define CPA_COMMIT() asm volatile("cp.async.commit_group;" ::: "memory")
#define CPA_WAIT0()  asm volatile("cp.async.wait_group 0;" ::: "memory")

// ---- convM smem geometry (dynamic): A 2-stage hi/lo + B halo hi/lo ----
#define PITCH 144
#define ASTG  18432                 // one A buffer (128 rows x 144B)
#define OB_H  73728                 // after 4 A buffers
#define OB_L  148608                // OB_H + 520*144
#define SMEMSZ2 223488              // OB_L + 520*144

// convO static smem offsets
#define QAH 0
#define QAL 4608
#define QBH 9216
#define QBL 27648
#define QSZ 46080

// ============================================================
// wsplit: w[co][ci][tap] fp32 -> WH/WL[tap][co][ci] bf16 hi/lo
// ============================================================
__global__ __launch_bounds__(256) void wsplit(
    const float* __restrict__ w, __nv_bfloat16* __restrict__ WH,
    __nv_bfloat16* __restrict__ WL)
{
    int idx = blockIdx.x * 256 + threadIdx.x;
    if (idx >= WELEM) return;
    int tap = idx / 65536;
    int r   = idx - tap * 65536;
    int co  = r >> 8, ci = r & 255;
    float v = w[co * 2304 + ci * 9 + tap];
    __nv_bfloat16 h = __float2bfloat16(v);
    WH[idx] = h;
    WL[idx] = __float2bfloat16(v - __bfloat162float(h));
}

// ============================================================
// woprep: head weights -> [set][tap][row32][ci] hi/lo
// ============================================================
__global__ __launch_bounds__(256) void woprep(
    const float* __restrict__ clsw, const float* __restrict__ regw,
    const float* __restrict__ ctrw,
    __nv_bfloat16* __restrict__ WOH, __nv_bfloat16* __restrict__ WOL)
{
    int idx = blockIdx.x * 256 + threadIdx.x;
    if (idx >= 2 * WOELEM) return;
    int set = idx / WOELEM;
    int r   = idx - set * WOELEM;
    int tap = r / 8192;
    int r2  = r - tap * 8192;
    int row = r2 >> 8, ci = r2 & 255;
    float v = 0.0f;
    if (set == 0) {
        if (row < 20) v = clsw[(row * 256 + ci) * 9 + tap];
    } else {
        if (row < 4)       v = regw[(row * 256 + ci) * 9 + tap];
        else if (row == 4) v = ctrw[ci * 9 + tap];
    }
    __nv_bfloat16 h = __float2bfloat16(v);
    WOH[idx] = h;
    WOL[idx] = __float2bfloat16(v - __bfloat162float(h));
}

// ============================================================
// zerok
// ============================================================
__global__ __launch_bounds__(256) void zerok(uint4* __restrict__ p, size_t n16)
{
    size_t stride = (size_t)gridDim.x * 256;
    uint4 z = make_uint4(0, 0, 0, 0);
    for (size_t i = (size_t)blockIdx.x * 256 + threadIdx.x; i < n16; i += stride)
        p[i] = z;
}

// ============================================================
// featprep: NCHW fp32 -> padded NHWC bf16 hi/lo
// ============================================================
__global__ __launch_bounds__(1024) void featprep(
    const float* __restrict__ feat, __nv_bfloat16* __restrict__ XH,
    __nv_bfloat16* __restrict__ XL, int H, int W, int Wp, int HpWp)
{
    __shared__ float tile[32][33];
    int xt = blockIdx.x, y = blockIdx.y;
    int n  = blockIdx.z >> 3, ct = blockIdx.z & 7;
    int tx = threadIdx.x, ty = threadIdx.y;

    tile[ty][tx] = feat[(((size_t)n * CC + ct * 32 + ty) * H + y) * W + xt * 32 + tx];
    __syncthreads();

    int c = ct * 32 + tx;
    int x = xt * 32 + ty;
    float v = tile[tx][ty];
    size_t a = ((size_t)n * HpWp + (size_t)(y + 1) * Wp + (x + 1)) * CC + c;
    __nv_bfloat16 h = __float2bfloat16(v);
    XH[a] = h;
    XL[a] = __float2bfloat16(v - __bfloat162float(h));
}

// ============================================================
// actk: GN+ReLU+split; pads zero.
// ============================================================
__global__ __launch_bounds__(256) void actk(
    const float* __restrict__ Y, const float* __restrict__ stats,
    const float* __restrict__ gam, const float* __restrict__ bet,
    __nv_bfloat16* __restrict__ XH, __nv_bfloat16* __restrict__ XL,
    int H, int W, int Wp, int HpWp)
{
    size_t total = (size_t)NB * HpWp * CC;
    size_t stride = (size_t)gridDim.x * 256;
    for (size_t idx = (size_t)blockIdx.x * 256 + threadIdx.x; idx < total; idx += stride) {
        int c = (int)(idx & 255);
        size_t pix = idx >> 8;
        int n  = (int)(pix / HpWp);
        int pp = (int)(pix - (size_t)n * HpWp);
        int py = pp / Wp, px = pp - py * Wp;
        __nv_bfloat16 h = __float2bfloat16(0.0f), l = h;
        if (py >= 1 && py <= H && px >= 1 && px <= W) {
            float v = Y[idx];
            int sg = (n * NGROUPS + (c >> 4)) * 2;
            v = (v - stats[sg]) * stats[sg + 1] * gam[c] + bet[c];
            v = fmaxf(v, 0.0f);
            h = __float2bfloat16(v);
            l = __float2bfloat16(v - __bfloat162float(h));
        }
        XH[idx] = h;
        XL[idx] = l;
    }
}

// ============================================================
// convM: warp-mma 3x3 conv, halo-resident B.
// CTA = 128co x 256px, 512 threads = 16 warps (4m x 4n), 1 CTA/SM.
// Per 64-ci chunk: B halo ((R+2)*Wp rows) loaded ONCE, 9 taps served by
// row-offset ldmatrix addressing. A double-buffered per tap (cp.async).
// 3-term bf16 split; deterministic GN partials in epilogue.
// grid (PT, 1, 16): z = n*2 + cohalf.
// ============================================================
__global__ __launch_bounds__(512) void convM(
    const uint4* __restrict__ XH, const uint4* __restrict__ XL,
    const uint4* __restrict__ WHl, const uint4* __restrict__ WLl,
    const float* __restrict__ bias, float* __restrict__ Y,
    float2* __restrict__ part,
    int H, int W, int Wp, int lgW, int HW, int HpWp)
{
    extern __shared__ char smem[];
    const uint32_t sb = smem_u32(smem);

    const int tid = threadIdx.x, wid = tid >> 5, lane = tid & 31;
    const int warp_m = wid >> 2, warp_n = wid & 3;
    const int p0 = blockIdx.x * 256;
    const int z = blockIdx.z;
    const int n = z >> 1, co0 = (z & 1) * 128;
    const size_t nbase = (size_t)n * HpWp;

    const int R  = 256 >> lgW;          // image rows per tile
    const int BR = (R + 2) * Wp;        // halo rows in smem
    const int pstart = (p0 >> lgW) * Wp; // padded pixel index of halo row 0

    float acc[2][8][4];
#pragma unroll
    for (int mt = 0; mt < 2; mt++)
#pragma unroll
        for (int nt = 0; nt < 8; nt++)
#pragma unroll
            for (int i = 0; i < 4; i++) acc[mt][nt][i] = 0.0f;

    const int lrow = lane & 7;
    const int matr = (lane >> 3) & 1;
    const int matc = lane >> 4;

    // per-warp n-dim pixel indices for the 4 np fragments (tile-relative)
    int rnp[4];
#pragma unroll
    for (int np = 0; np < 4; np++)
        rnp[np] = warp_n * 64 + np * 16 + matc * 8 + lrow;

    auto fillA = [&](int tap, int stage) {
        const uint32_t abase = sb + (uint32_t)(stage * 2 * ASTG);
#pragma unroll
        for (int t = tid; t < 1024; t += 512) {
            int row = t >> 3, v = t & 7;
            uint32_t d = abase + (uint32_t)(row * PITCH + v * 16);
            size_t g = (size_t)tap * 8192 + (size_t)(co0 + row) * 32 + v;  // kc added by caller ptr
            cpa16(d, WHl + g);
            cpa16(d + ASTG, WLl + g);
        }
    };

#pragma unroll 1
    for (int kc = 0; kc < 4; kc++) {
        const uint4* WHk = WHl + kc * 8;
        const uint4* WLk = WLl + kc * 8;
        // ---- B halo fill (once per kc) ----
        for (int t = tid; t < BR * 8; t += 512) {
            int hr = t >> 3, v = t & 7;
            uint32_t d = sb + OB_H + (uint32_t)(hr * PITCH + v * 16);
            int gpix = pstart + hr;
            uint32_t ok = (gpix < HpWp) ? 16u : 0u;
            size_t src = (nbase + gpix) * 32 + kc * 8 + v;
            cpa16z(d, XH + src, ok);
            cpa16z(d + (OB_L - OB_H), XL + src, ok);
        }
        // ---- A tap 0 ----
        {
            const uint32_t abase = sb;
#pragma unroll
            for (int t = tid; t < 1024; t += 512) {
                int row = t >> 3, v = t & 7;
                uint32_t d = abase + (uint32_t)(row * PITCH + v * 16);
                size_t g = (size_t)(co0 + row) * 32 + v;
                cpa16(d, WHk + g);
                cpa16(d + ASTG, WLk + g);
            }
        }
        CPA_COMMIT();
        CPA_WAIT0();
        __syncthreads();

#pragma unroll 1
        for (int tap = 0; tap < 9; tap++) {
            if (tap < 8) {
                const uint32_t abase = sb + (uint32_t)((((tap + 1) & 1)) * 2 * ASTG);
#pragma unroll
                for (int t = tid; t < 1024; t += 512) {
                    int row = t >> 3, v = t & 7;
                    uint32_t d = abase + (uint32_t)(row * PITCH + v * 16);
                    size_t g = (size_t)(tap + 1) * 8192 + (size_t)(co0 + row) * 32 + v;
                    cpa16(d, WHk + g);
                    cpa16(d + ASTG, WLk + g);
                }
                CPA_COMMIT();
            }

            const int ky = tap / 3, kx = tap - ky * 3;
            // B row byte-offsets for this tap
            uint32_t bOff[4];
#pragma unroll
            for (int np = 0; np < 4; np++) {
                int r = rnp[np];
                int sr = ((r >> lgW) + ky) * Wp + (r & (W - 1)) + kx;
                bOff[np] = (uint32_t)(sr * PITCH);
            }
            const uint32_t sAH = sb + (uint32_t)((tap & 1) * 2 * ASTG);
            const uint32_t sAL = sAH + ASTG;
            const uint32_t sBH = sb + OB_H;
            const uint32_t sBL = sb + OB_L;
            const int m0 = warp_m * 32;

#pragma unroll
            for (int ks = 0; ks < 4; ks++) {
                uint32_t ah[2][4], al[2][4], bb[4][4];
#pragma unroll
                for (int mt = 0; mt < 2; mt++) {
                    uint32_t off = (uint32_t)((m0 + mt * 16 + matr * 8 + lrow) * PITCH
                                              + (ks * 16 + matc * 8) * 2);
                    ldsm_x4(ah[mt][0], ah[mt][1], ah[mt][2], ah[mt][3], sAH + off);
                    ldsm_x4(al[mt][0], al[mt][1], al[mt][2], al[mt][3], sAL + off);
                }
                const uint32_t kb = (uint32_t)((ks * 16 + matr * 8) * 2);
#pragma unroll
                for (int np = 0; np < 4; np++)
                    ldsm_x4(bb[np][0], bb[np][1], bb[np][2], bb[np][3],
                            sBH + bOff[np] + kb);
#pragma unroll
                for (int mt = 0; mt < 2; mt++)
#pragma unroll
                    for (int np = 0; np < 4; np++) {
                        mma_bf16(acc[mt][np * 2 + 0], ah[mt], &bb[np][0]);
                        mma_bf16(acc[mt][np * 2 + 1], ah[mt], &bb[np][2]);
                        mma_bf16(acc[mt][np * 2 + 0], al[mt], &bb[np][0]);
                        mma_bf16(acc[mt][np * 2 + 1], al[mt], &bb[np][2]);
                    }
#pragma unroll
                for (int np = 0; np < 4; np++)
                    ldsm_x4(bb[np][0], bb[np][1], bb[np][2], bb[np][3],
                            sBL + bOff[np] + kb);
#pragma unroll
                for (int mt = 0; mt < 2; mt++)
#pragma unroll
                    for (int np = 0; np < 4; np++) {
                        mma_bf16(acc[mt][np * 2 + 0], ah[mt], &bb[np][0]);
                        mma_bf16(acc[mt][np * 2 + 1], ah[mt], &bb[np][2]);
                    }
            }
            if (tap < 8) CPA_WAIT0();
            __syncthreads();
        }
    }

    // ---- epilogue: bias, store padded NHWC fp32, deterministic GN partials ----
    __shared__ float redS[16][2], redQ[16][2];
    const int qrow = lane >> 2, qcol = (lane & 3) * 2;
    float sg[2] = {0.0f, 0.0f}, qg[2] = {0.0f, 0.0f};

#pragma unroll
    for (int mt = 0; mt < 2; mt++) {
#pragma unroll
        for (int h8 = 0; h8 < 2; h8++) {
            const int col_ = co0 + warp_m * 32 + mt * 16 + qrow + h8 * 8;
            const float b = bias[col_];
#pragma unroll
            for (int nt = 0; nt < 8; nt++) {
#pragma unroll
                for (int cc2 = 0; cc2 < 2; cc2++) {
                    int p = p0 + warp_n * 64 + nt * 8 + qcol + cc2;
                    float v = acc[mt][nt][h8 * 2 + cc2] + b;
                    if (p < HW) {
                        int x = p & (W - 1), y = p >> lgW;
                        Y[(nbase + (size_t)(y + 1) * Wp + (x + 1)) * CC + col_] = v;
                        sg[mt] += v;
                        qg[mt] += v * v;
                    }
                }
            }
        }
    }
#pragma unroll
    for (int off = 16; off > 0; off >>= 1) {
#pragma unroll
        for (int mt = 0; mt < 2; mt++) {
            sg[mt] += __shfl_down_sync(0xffffffffu, sg[mt], off);
            qg[mt] += __shfl_down_sync(0xffffffffu, qg[mt], off);
        }
    }
    if (lane == 0) {
        redS[wid][0] = sg[0]; redS[wid][1] = sg[1];
        redQ[wid][0] = qg[0]; redQ[wid][1] = qg[1];
    }
    __syncthreads();
    if (tid < 8) {
        int wm = tid >> 1, mt = tid & 1;
        float S = 0.0f, Q = 0.0f;
#pragma unroll
        for (int wn = 0; wn < 4; wn++) {
            S += redS[wm * 4 + wn][mt];
            Q += redQ[wm * 4 + wn][mt];
        }
        size_t pidx = (size_t)z * gridDim.x + blockIdx.x;
        part[pidx * 8 + tid] = make_float2(S, Q);
    }
}

// ============================================================
// convO: head convs (cls 20 / reg 4 + ctr 1), 32co x 128px CTA.
// ============================================================
__global__ __launch_bounds__(256) void convO(
    const uint4* __restrict__ XH, const uint4* __restrict__ XL,
    const uint4* __restrict__ WOH, const uint4* __restrict__ WOL,
    const float* __restrict__ clsb, const float* __restrict__ regb,
    const float* __restrict__ ctrb, float* __restrict__ out,
    int H, int W, int Wp, int lgW, int HW, int HpWp, int poff, int mode)
{
    __shared__ __align__(16) char smem[QSZ];
    const uint32_t sb = smem_u32(smem);
    const uint32_t sAH = sb + QAH, sAL = sb + QAL;
    const uint32_t sBH = sb + QBH, sBL = sb + QBL;

    const int tid = threadIdx.x, wid = tid >> 5, lane = tid & 31;
    const int p0 = blockIdx.x * 128;
    const int n = blockIdx.z;
    const size_t nbase = (size_t)n * HpWp;

    float acc[2][2][4];
#pragma unroll
    for (int mt = 0; mt < 2; mt++)
#pragma unroll
        for (int nt = 0; nt < 2; nt++)
#pragma unroll
            for (int i = 0; i < 4; i++) acc[mt][nt][i] = 0.0f;

    const int lrow = lane & 7;
    const int matr = (lane >> 3) & 1;
    const int matc = lane >> 4;

#pragma unroll 1
    for (int tap = 0; tap < 9; tap++) {
        const int ky = tap / 3, kx = tap - ky * 3;
#pragma unroll 1
        for (int kc = 0; kc < 4; kc++) {
            if (tid < 256) {
                int row = tid >> 3, v = tid & 7;
                size_t g = (size_t)tap * 1024 + (size_t)row * 32 + kc * 8 + v;
                *reinterpret_cast<uint4*>(smem + QAH + row * PITCH + v * 16) = WOH[g];
                *reinterpret_cast<uint4*>(smem + QAL + row * PITCH + v * 16) = WOL[g];
            }
#pragma unroll
            for (int t = tid; t < 1024; t += 256) {
                int r = t >> 3, v = t & 7;
                int p = p0 + r;
                int x = p & (W - 1), y = p >> lgW;
                size_t src = (nbase + (size_t)(y + ky) * Wp + (x + kx)) * 32 + kc * 8 + v;
                *reinterpret_cast<uint4*>(smem + QBH + r * PITCH + v * 16) = XH[src];
                *reinterpret_cast<uint4*>(smem + QBL + r * PITCH + v * 16) = XL[src];
            }
            __syncthreads();

            const int n0 = wid * 16;
#pragma unroll
            for (int ks = 0; ks < 4; ks++) {
                uint32_t ah[2][4], al[2][4], bh[4], bl[4];
#pragma unroll
                for (int mt = 0; mt < 2; mt++) {
                    uint32_t off = (uint32_t)((mt * 16 + matr * 8 + lrow) * PITCH
                                              + (ks * 16 + matc * 8) * 2);
                    ldsm_x4(ah[mt][0], ah[mt][1], ah[mt][2], ah[mt][3], sAH + off);
                    ldsm_x4(al[mt][0], al[mt][1], al[mt][2], al[mt][3], sAL + off);
                }
                uint32_t offB = (uint32_t)((n0 + matc * 8 + lrow) * PITCH
                                           + (ks * 16 + matr * 8) * 2);
                ldsm_x4(bh[0], bh[1], bh[2], bh[3], sBH + offB);
                ldsm_x4(bl[0], bl[1], bl[2], bl[3], sBL + offB);
#pragma unroll
                for (int mt = 0; mt < 2; mt++) {
                    mma_bf16(acc[mt][0], ah[mt], &bh[0]);
                    mma_bf16(acc[mt][1], ah[mt], &bh[2]);
                    mma_bf16(acc[mt][0], al[mt], &bh[0]);
                    mma_bf16(acc[mt][1], al[mt], &bh[2]);
                    mma_bf16(acc[mt][0], ah[mt], &bl[0]);
                    mma_bf16(acc[mt][1], ah[mt], &bl[2]);
                }
            }
            __syncthreads();
        }
    }

    const int qrow = lane >> 2, qcol = (lane & 3) * 2;
#pragma unroll
    for (int mt = 0; mt < 2; mt++) {
#pragma unroll
        for (int h8 = 0; h8 < 2; h8++) {
            const int row = mt * 16 + h8 * 8 + qrow;
#pragma unroll
            for (int nt = 0; nt < 2; nt++) {
#pragma unroll
                for (int cc2 = 0; cc2 < 2; cc2++) {
                    int p = p0 + wid * 16 + nt * 8 + qcol + cc2;
                    if (p >= HW) continue;
                    float v = acc[mt][nt][h8 * 2 + cc2];
                    int x = p & (W - 1), y = p >> lgW;
                    size_t gp = (size_t)n * TOTHW + poff + (size_t)y * W + x;
                    if (mode == 0) {
                        if (row < 20) out[CLSBASE + gp * 20 + row] = v + clsb[row];
                    } else {
                        if (row < 4)
                            out[REGBASE + gp * 4 + row] = fmaxf(v + regb[row], 0.0f);
                        else if (row == 4)
                            out[CTRBASE + gp] = v + ctrb[0];
                    }
                }
            }
        }
    }
}

// ============================================================
// GN finalize
// ============================================================
__global__ __launch_bounds__(256) void gn_finalize(
    const float2* __restrict__ part, float* __restrict__ stats,
    int GX, int GY, int HW)
{
    const int b = blockIdx.x;
    const int n = b >> 4, grp = b & 15;
    const int half = grp >> 3, i = grp & 7;
    const int bz = n * 2 + half;
    const int nb = GX * GY;

    float S = 0.0f, Q = 0.0f;
    for (int t = threadIdx.x; t < nb; t += 256) {
        float2 p = part[(size_t)(bz * nb + t) * 8 + i];
        S += p.x; Q += p.y;
    }
    __shared__ float sS[256], sQ[256];
    sS[threadIdx.x] = S; sQ[threadIdx.x] = Q;
    __syncthreads();
    for (int off = 128; off > 0; off >>= 1) {
        if (threadIdx.x < off) {
            sS[threadIdx.x] += sS[threadIdx.x + off];
            sQ[threadIdx.x] += sQ[threadIdx.x + off];
        }
        __syncthreads();
    }
    if (threadIdx.x == 0) {
        float cnt  = (float)(GSIZE * HW);
        float mean = sS[0] / cnt;
        float var  = sQ[0] / cnt - mean * mean;
        stats[2 * b]     = mean;
        stats[2 * b + 1] = rsqrtf(var + GN_EPS);
    }
}

// ============================================================
// host launcher
// ============================================================
extern "C" void kernel_launch(void* const* d_in, const int* in_sizes, int n_in,
                              void* d_out, int out_size)
{
    (void)in_sizes; (void)n_in; (void)out_size;

    const float* feat[3] = { (const float*)d_in[0], (const float*)d_in[1],
                             (const float*)d_in[2] };
    const float* cls_conv_w = (const float*)d_in[3];
    const float* cls_conv_b = (const float*)d_in[4];
    const float* cls_gn_g   = (const float*)d_in[5];
    const float* cls_gn_b   = (const float*)d_in[6];
    const float* cls_out_w  = (const float*)d_in[7];
    const float* cls_out_b  = (const float*)d_in[8];
    const float* reg_conv_w = (const float*)d_in[9];
    const float* reg_conv_b = (const float*)d_in[10];
    const float* reg_gn_g   = (const float*)d_in[11];
    const float* reg_gn_b   = (const float*)d_in[12];
    const float* reg_out_w  = (const float*)d_in[13];
    const float* reg_out_b  = (const float*)d_in[14];
    const float* ctr_w      = (const float*)d_in[15];
    const float* ctr_b      = (const float*)d_in[16];

    float* out = (float*)d_out;

    __nv_bfloat16 *XFH, *XFL, *XTH, *XTL, *WH, *WL, *WOH, *WOL;
    float *YA, *YB, *stats;
    float2* part;
    cudaGetSymbolAddress((void**)&XFH, g_XFH);
    cudaGetSymbolAddress((void**)&XFL, g_XFL);
    cudaGetSymbolAddress((void**)&XTH, g_XTH);
    cudaGetSymbolAddress((void**)&XTL, g_XTL);
    cudaGetSymbolAddress((void**)&YA, g_YA);
    cudaGetSymbolAddress((void**)&YB, g_YB);
    cudaGetSymbolAddress((void**)&WH, g_WH);
    cudaGetSymbolAddress((void**)&WL, g_WL);
    cudaGetSymbolAddress((void**)&WOH, g_WOH);
    cudaGetSymbolAddress((void**)&WOL, g_WOL);
    cudaGetSymbolAddress((void**)&stats, g_stats);
    cudaGetSymbolAddress((void**)&part, g_part);

    cudaFuncSetAttribute(convM, cudaFuncAttributeMaxDynamicSharedMemorySize, SMEMSZ2);

    const int TGRID = (WELEM + 255) / 256;
    wsplit<<<TGRID, 256>>>(cls_conv_w,          WH + 0 * (size_t)WELEM, WL + 0 * (size_t)WELEM);
    wsplit<<<TGRID, 256>>>(cls_conv_w + WELEM,  WH + 1 * (size_t)WELEM, WL + 1 * (size_t)WELEM);
    wsplit<<<TGRID, 256>>>(reg_conv_w,          WH + 2 * (size_t)WELEM, WL + 2 * (size_t)WELEM);
    wsplit<<<TGRID, 256>>>(reg_conv_w + WELEM,  WH + 3 * (size_t)WELEM, WL + 3 * (size_t)WELEM);
    woprep<<<(2 * WOELEM + 255) / 256, 256>>>(cls_out_w, reg_out_w, ctr_w, WOH, WOL);

    const int LH[3] = {100, 50, 25};
    const int LW[3] = {128, 64, 32};
    const int LG[3] = {7, 6, 5};
    const int LP[3] = {0, 12800, 16000};

    for (int L = 0; L < 3; L++) {
        const int H = LH[L], W = LW[L], lgW = LG[L];
        const int Hp = H + 2, Wp = W + 2, HpWp = Hp * Wp, HW = H * W;
        const int PT  = (HW + 255) / 256;       // convM tiles
        const int PTO = (HW + 127) / 128;       // convO tiles
        const int poff = LP[L];
        const size_t used16 = (size_t)NB * HpWp * CC / 8;

        dim3 cgrid(PT, 1, 16);
        dim3 hgrid(PTO, 1, NB);
        dim3 fgrid(W / 32, H, NB * 8);
        dim3 fblk(32, 32);

        zerok<<<2048, 256>>>((uint4*)XFH, used16);
        zerok<<<2048, 256>>>((uint4*)XFL, used16);
        featprep<<<fgrid, fblk>>>(feat[L], XFH, XFL, H, W, Wp, HpWp);

        for (int tw = 0; tw < 2; tw++) {
            const __nv_bfloat16* wh0 = WH + (size_t)(tw * 2 + 0) * WELEM;
            const __nv_bfloat16* wl0 = WL + (size_t)(tw * 2 + 0) * WELEM;
            const __nv_bfloat16* wh1 = WH + (size_t)(tw * 2 + 1) * WELEM;
            const __nv_bfloat16* wl1 = WL + (size_t)(tw * 2 + 1) * WELEM;
            const float* cb = tw ? reg_conv_b : cls_conv_b;
            const float* gg = tw ? reg_gn_g   : cls_gn_g;
            const float* gb = tw ? reg_gn_b   : cls_gn_b;

            convM<<<cgrid, 512, SMEMSZ2>>>(
                (const uint4*)XFH, (const uint4*)XFL,
                (const uint4*)wh0, (const uint4*)wl0,
                cb, YA, part, H, W, Wp, lgW, HW, HpWp);
            gn_finalize<<<NB * NGROUPS, 256>>>(part, stats, PT, 1, HW);
            actk<<<2048, 256>>>(YA, stats, gg, gb, XTH, XTL, H, W, Wp, HpWp);

            convM<<<cgrid, 512, SMEMSZ2>>>(
                (const uint4*)XTH, (const uint4*)XTL,
                (const uint4*)wh1, (const uint4*)wl1,
                cb + CC, YB, part, H, W, Wp, lgW, HW, HpWp);
            gn_finalize<<<NB * NGROUPS, 256>>>(part, stats, PT, 1, HW);
            actk<<<2048, 256>>>(YB, stats, gg + CC, gb + CC, XTH, XTL, H, W, Wp, HpWp);

            const uint4* woh = (const uint4*)(WOH + (size_t)tw * WOELEM);
            const uint4* wol = (const uint4*)(WOL + (size_t)tw * WOELEM);
            convO<<<hgrid, 256>>>((const uint4*)XTH, (const uint4*)XTL, woh, wol,
                                  cls_out_b, reg_out_b, ctr_b, out,
                                  H, W, Wp, lgW, HW, HpWp, poff, tw);
        }
    }
}

// round 10
// speedup vs baseline: 6.5597x; 1.1870x over previous
#include <cuda_runtime.h>
#include <cuda_bf16.h>
#include <math.h>
#include <stdint.h>

// ---------------- problem constants ----------------
#define NB 8
#define CC 256
#define NGROUPS 16
#define GSIZE 16
#define GN_EPS 1e-5f

#define TOTHW   16800
#define CLSBASE 0
#define REGBASE 2688000
#define CTRBASE 3225600

#define WELEM  (CC * CC * 9)      // 589824 bf16 per tower layer
#define WOELEM (9 * 32 * 256)     // 73728 per head set

#define XCAP 27160000             // fp32 padded NHWC capacity (L0 = 27,156,480)

// scratch (device globals; zero-initialized, no runtime allocation)
__device__ __align__(16) float g_XF[XCAP];
__device__ __align__(16) float g_Y[4][XCAP];          // YAc, YAr, YBc, YBr
__device__ __align__(16) __nv_bfloat16 g_WH[4 * WELEM];
__device__ __align__(16) __nv_bfloat16 g_WL[4 * WELEM];
__device__ __align__(16) __nv_bfloat16 g_WOH[2 * WOELEM];
__device__ __align__(16) __nv_bfloat16 g_WOL[2 * WOELEM];
__device__ float  g_ssv[2 * 2 * 2048];   // [conv][tower][n*256+c] scale
__device__ float  g_shv[2 * 2 * 2048];   // shift
__device__ float2 g_part[32 * 52 * 8];

// ---------------- PTX helpers (arch-agnostic sm_80+) ----------------
__device__ __forceinline__ uint32_t smem_u32(const void* p) {
    uint32_t a;
    asm("{ .reg .u64 t; cvta.to.shared.u64 t, %1; cvt.u32.u64 %0, t; }"
        : "=r"(a) : "l"(p));
    return a;
}
__device__ __forceinline__ void ldsm_x4(uint32_t& r0, uint32_t& r1,
                                        uint32_t& r2, uint32_t& r3, uint32_t a) {
    asm volatile("ldmatrix.sync.aligned.m8n8.x4.shared.b16 {%0,%1,%2,%3}, [%4];"
        : "=r"(r0), "=r"(r1), "=r"(r2), "=r"(r3) : "r"(a));
}
__device__ __forceinline__ void mma_bf16(float* d, const uint32_t* a,
                                         const uint32_t* b) {
    asm volatile("mma.sync.aligned.m16n8k16.row.col.f32.bf16.bf16.f32 "
        "{%0,%1,%2,%3}, {%4,%5,%6,%7}, {%8,%9}, {%0,%1,%2,%3};"
        : "+f"(d[0]), "+f"(d[1]), "+f"(d[2]), "+f"(d[3])
        : "r"(a[0]), "r"(a[1]), "r"(a[2]), "r"(a[3]), "r"(b[0]), "r"(b[1]));
}
__device__ __forceinline__ void cpa16(uint32_t d, const void* s) {
    asm volatile("cp.async.cg.shared.global [%0], [%1], 16;"
                 :: "r"(d), "l"(s) : "memory");
}
#define CPA_COMMIT() asm volatile("cp.async.commit_group;" ::: "memory")
#define CPA_WAIT0()  asm volatile("cp.async.wait_group 0;" ::: "memory")

__device__ __forceinline__ uint32_t pkbf(__nv_bfloat16 a, __nv_bfloat16 b) {
    __nv_bfloat162 t = __halves2bfloat162(a, b);
    return *reinterpret_cast<uint32_t*>(&t);
}

// ---- convM smem geometry (dynamic) ----
#define PITCH 144
#define ASTG  18432                  // one A buffer (128 rows x 144B)
#define OB_H  73728                  // 4 A buffers
#define OB_L  148608                 // OB_H + 520*144
#define OSS   223488                 // OB_L + 520*144
#define OSH   224512
#define CM_DYN 225536

// ---- convO smem geometry (dynamic) ----
#define ASTG_O 4608                  // 32 rows x 144B
#define OB_H_O 18432                 // 4 A buffers
#define OB_L_O 93312
#define OSS_O  168192
#define OSH_O  169216
#define CO_DYN 170240

// ============================================================
// wsplit: w[co][ci][tap] fp32 -> WH/WL[tap][co][ci] bf16 hi/lo
// ============================================================
__global__ __launch_bounds__(256) void wsplit(
    const float* __restrict__ w, __nv_bfloat16* __restrict__ WH,
    __nv_bfloat16* __restrict__ WL)
{
    int idx = blockIdx.x * 256 + threadIdx.x;
    if (idx >= WELEM) return;
    int tap = idx / 65536;
    int r   = idx - tap * 65536;
    int co  = r >> 8, ci = r & 255;
    float v = w[co * 2304 + ci * 9 + tap];
    __nv_bfloat16 h = __float2bfloat16(v);
    WH[idx] = h;
    WL[idx] = __float2bfloat16(v - __bfloat162float(h));
}

// ============================================================
// woprep: head weights -> [set][tap][row32][ci] hi/lo
// ============================================================
__global__ __launch_bounds__(256) void woprep(
    const float* __restrict__ clsw, const float* __restrict__ regw,
    const float* __restrict__ ctrw,
    __nv_bfloat16* __restrict__ WOH, __nv_bfloat16* __restrict__ WOL)
{
    int idx = blockIdx.x * 256 + threadIdx.x;
    if (idx >= 2 * WOELEM) return;
    int set = idx / WOELEM;
    int r   = idx - set * WOELEM;
    int tap = r / 8192;
    int r2  = r - tap * 8192;
    int row = r2 >> 8, ci = r2 & 255;
    float v = 0.0f;
    if (set == 0) {
        if (row < 20) v = clsw[(row * 256 + ci) * 9 + tap];
    } else {
        if (row < 4)       v = regw[(row * 256 + ci) * 9 + tap];
        else if (row == 4) v = ctrw[ci * 9 + tap];
    }
    __nv_bfloat16 h = __float2bfloat16(v);
    WOH[idx] = h;
    WOL[idx] = __float2bfloat16(v - __bfloat162float(h));
}

// ============================================================
// zeropad: zero border pixels (all channels) of a padded NHWC fp32 buffer
// ============================================================
__global__ __launch_bounds__(256) void zeropad(
    float4* __restrict__ buf, int H, int W, int Wp, int HpWp)
{
    int bc = 2 * Wp + 2 * H;
    int total = NB * bc * 64;
    int idx = blockIdx.x * 256 + threadIdx.x;
    if (idx >= total) return;
    int ch4 = idx & 63;
    int r   = idx >> 6;
    int n   = r / bc;
    int b   = r - n * bc;
    int py, px;
    if (b < Wp)           { py = 0;     px = b; }
    else if (b < 2 * Wp)  { py = H + 1; px = b - Wp; }
    else {
        int rr = b - 2 * Wp;
        py = 1 + (rr >> 1);
        px = (rr & 1) ? (W + 1) : 0;
    }
    buf[((size_t)n * HpWp + (size_t)py * Wp + px) * 64 + ch4] =
        make_float4(0.f, 0.f, 0.f, 0.f);
}

// ============================================================
// featprep: NCHW fp32 -> padded NHWC fp32 (32x32 smem transpose)
// ============================================================
__global__ __launch_bounds__(1024) void featprep(
    const float* __restrict__ feat, float* __restrict__ XF,
    int H, int W, int Wp, int HpWp)
{
    __shared__ float tile[32][33];
    int xt = blockIdx.x, y = blockIdx.y;
    int n  = blockIdx.z >> 3, ct = blockIdx.z & 7;
    int tx = threadIdx.x, ty = threadIdx.y;

    tile[ty][tx] = feat[(((size_t)n * CC + ct * 32 + ty) * H + y) * W + xt * 32 + tx];
    __syncthreads();

    int c = ct * 32 + tx;
    int x = xt * 32 + ty;
    XF[((size_t)n * HpWp + (size_t)(y + 1) * Wp + (x + 1)) * CC + c] = tile[tx][ty];
}

// ============================================================
// convM: warp-mma 3x3 conv, halo-resident B with fused GN+split on load.
// GN applied ONLY to interior pixels; padding stays exactly zero.
// CTA = 128co x 256px, 512 threads = 16 warps (4m x 4n), 1 CTA/SM.
// grid (PT, 1, 32): z = tower*16 + n*2 + cohalf.
// ============================================================
__global__ __launch_bounds__(512) void convM(
    const float4* __restrict__ inC, const float4* __restrict__ inR,
    const uint4* __restrict__ WHb, const uint4* __restrict__ WLb, int layer,
    const float* __restrict__ clscb, const float* __restrict__ regcb,
    const float* __restrict__ ssv, const float* __restrict__ shv,   // may be null
    float* __restrict__ outC, float* __restrict__ outR,
    float2* __restrict__ part,
    int H, int W, int Wp, int lgW, int HW, int HpWp)
{
    extern __shared__ char smem[];
    const uint32_t sb = smem_u32(smem);

    const int tid = threadIdx.x, wid = tid >> 5, lane = tid & 31;
    const int warp_m = wid >> 2, warp_n = wid & 3;
    const int p0 = blockIdx.x * 256;
    const int z = blockIdx.z;
    const int tower = z >> 4, zz = z & 15;
    const int n = zz >> 1, co0 = (zz & 1) * 128;
    const size_t nbase = (size_t)n * HpWp;

    const float4* in = tower ? inR : inC;
    float* Y = tower ? outR : outC;
    const uint4* WHl = WHb + (size_t)(tower * 2 + layer) * (WELEM / 8);
    const uint4* WLl = WLb + (size_t)(tower * 2 + layer) * (WELEM / 8);
    const float* bias = (tower ? regcb : clscb) + layer * CC;

    const int R  = 256 >> lgW;
    const int BR = (R + 2) * Wp;
    const int prow0 = p0 >> lgW;          // padded row of halo row 0
    const int pstart = prow0 * Wp;

    float* sS = (float*)(smem + OSS);
    float* sHh = (float*)(smem + OSH);
    if (ssv && tid < 256) {
        sS[tid]  = ssv[tower * 2048 + n * 256 + tid];
        sHh[tid] = shv[tower * 2048 + n * 256 + tid];
    }
    __syncthreads();

    float acc[2][8][4];
#pragma unroll
    for (int mt = 0; mt < 2; mt++)
#pragma unroll
        for (int nt = 0; nt < 8; nt++)
#pragma unroll
            for (int i = 0; i < 4; i++) acc[mt][nt][i] = 0.0f;

    const int lrow = lane & 7;
    const int matr = (lane >> 3) & 1;
    const int matc = lane >> 4;

    int rnp[4];
#pragma unroll
    for (int np = 0; np < 4; np++)
        rnp[np] = warp_n * 64 + np * 16 + matc * 8 + lrow;

#pragma unroll 1
    for (int kc = 0; kc < 4; kc++) {
        // ---- B halo fill: fp32 -> (GN+ReLU interior-only) -> bf16 hi/lo ----
        {
            const int lim = BR * 16;
#pragma unroll 1
            for (int t0 = tid; t0 < lim; t0 += 2048) {
                float4 xa[4];
#pragma unroll
                for (int u = 0; u < 4; u++) {
                    int t = t0 + u * 512;
                    xa[u] = make_float4(0.f, 0.f, 0.f, 0.f);
                    if (t < lim) {
                        int hr = t >> 4, v = t & 15;
                        int gpix = pstart + hr;
                        if (gpix < HpWp)
                            xa[u] = in[(size_t)(nbase + gpix) * 64 + (kc << 4) + v];
                    }
                }
#pragma unroll
                for (int u = 0; u < 4; u++) {
                    int t = t0 + u * 512;
                    if (t >= lim) break;
                    int hr = t >> 4, v = t & 15;
                    float4 x = xa[u];
                    if (ssv) {
                        int hd = hr / Wp;
                        int gx = hr - hd * Wp;
                        int gy = prow0 + hd;
                        if (gy >= 1 && gy <= H && gx >= 1 && gx <= W) {
                            int c = (kc << 6) + (v << 2);
                            x.x = fmaxf(fmaf(x.x, sS[c+0], sHh[c+0]), 0.f);
                            x.y = fmaxf(fmaf(x.y, sS[c+1], sHh[c+1]), 0.f);
                            x.z = fmaxf(fmaf(x.z, sS[c+2], sHh[c+2]), 0.f);
                            x.w = fmaxf(fmaf(x.w, sS[c+3], sHh[c+3]), 0.f);
                        } else {
                            x = make_float4(0.f, 0.f, 0.f, 0.f);
                        }
                    }
                    __nv_bfloat16 h0 = __float2bfloat16(x.x);
                    __nv_bfloat16 h1 = __float2bfloat16(x.y);
                    __nv_bfloat16 h2 = __float2bfloat16(x.z);
                    __nv_bfloat16 h3 = __float2bfloat16(x.w);
                    __nv_bfloat16 l0 = __float2bfloat16(x.x - __bfloat162float(h0));
                    __nv_bfloat16 l1 = __float2bfloat16(x.y - __bfloat162float(h1));
                    __nv_bfloat16 l2 = __float2bfloat16(x.z - __bfloat162float(h2));
                    __nv_bfloat16 l3 = __float2bfloat16(x.w - __bfloat162float(h3));
                    uint32_t base = (uint32_t)(hr * PITCH + (v << 3));
                    *reinterpret_cast<uint2*>(smem + OB_H + base) =
                        make_uint2(pkbf(h0, h1), pkbf(h2, h3));
                    *reinterpret_cast<uint2*>(smem + OB_L + base) =
                        make_uint2(pkbf(l0, l1), pkbf(l2, l3));
                }
            }
        }
        // ---- A tap 0 prefetch (stage 0) ----
#pragma unroll
        for (int t = tid; t < 1024; t += 512) {
            int row = t >> 3, v = t & 7;
            uint32_t d = sb + (uint32_t)(row * PITCH + v * 16);
            size_t g = (size_t)(co0 + row) * 32 + kc * 8 + v;
            cpa16(d, WHl + g);
            cpa16(d + ASTG, WLl + g);
        }
        CPA_COMMIT();
        CPA_WAIT0();
        __syncthreads();

#pragma unroll 1
        for (int tap = 0; tap < 9; tap++) {
            if (tap < 8) {
                const uint32_t abase = sb + (uint32_t)(((tap + 1) & 1) * 2 * ASTG);
#pragma unroll
                for (int t = tid; t < 1024; t += 512) {
                    int row = t >> 3, v = t & 7;
                    uint32_t d = abase + (uint32_t)(row * PITCH + v * 16);
                    size_t g = (size_t)(tap + 1) * 8192 + (size_t)(co0 + row) * 32 + kc * 8 + v;
                    cpa16(d, WHl + g);
                    cpa16(d + ASTG, WLl + g);
                }
                CPA_COMMIT();
            }

            const int ky = tap / 3, kx = tap - ky * 3;
            uint32_t bOff[4];
#pragma unroll
            for (int np = 0; np < 4; np++) {
                int r = rnp[np];
                int sr = ((r >> lgW) + ky) * Wp + (r & (W - 1)) + kx;
                bOff[np] = (uint32_t)(sr * PITCH);
            }
            const uint32_t sAH = sb + (uint32_t)((tap & 1) * 2 * ASTG);
            const uint32_t sAL = sAH + ASTG;
            const uint32_t sBH = sb + OB_H;
            const uint32_t sBL = sb + OB_L;
            const int m0 = warp_m * 32;

#pragma unroll
            for (int ks = 0; ks < 4; ks++) {
                uint32_t ah[2][4], al[2][4], bb[4][4];
#pragma unroll
                for (int mt = 0; mt < 2; mt++) {
                    uint32_t off = (uint32_t)((m0 + mt * 16 + matr * 8 + lrow) * PITCH
                                              + (ks * 16 + matc * 8) * 2);
                    ldsm_x4(ah[mt][0], ah[mt][1], ah[mt][2], ah[mt][3], sAH + off);
                    ldsm_x4(al[mt][0], al[mt][1], al[mt][2], al[mt][3], sAL + off);
                }
                const uint32_t kb = (uint32_t)((ks * 16 + matr * 8) * 2);
#pragma unroll
                for (int np = 0; np < 4; np++)
                    ldsm_x4(bb[np][0], bb[np][1], bb[np][2], bb[np][3],
                            sBH + bOff[np] + kb);
#pragma unroll
                for (int mt = 0; mt < 2; mt++)
#pragma unroll
                    for (int np = 0; np < 4; np++) {
                        mma_bf16(acc[mt][np * 2 + 0], ah[mt], &bb[np][0]);
                        mma_bf16(acc[mt][np * 2 + 1], ah[mt], &bb[np][2]);
                        mma_bf16(acc[mt][np * 2 + 0], al[mt], &bb[np][0]);
                        mma_bf16(acc[mt][np * 2 + 1], al[mt], &bb[np][2]);
                    }
#pragma unroll
                for (int np = 0; np < 4; np++)
                    ldsm_x4(bb[np][0], bb[np][1], bb[np][2], bb[np][3],
                            sBL + bOff[np] + kb);
#pragma unroll
                for (int mt = 0; mt < 2; mt++)
#pragma unroll
                    for (int np = 0; np < 4; np++) {
                        mma_bf16(acc[mt][np * 2 + 0], ah[mt], &bb[np][0]);
                        mma_bf16(acc[mt][np * 2 + 1], ah[mt], &bb[np][2]);
                    }
            }
            if (tap < 8) CPA_WAIT0();
            __syncthreads();
        }
    }

    // ---- epilogue: bias, store fp32 padded NHWC, deterministic GN partials ----
    __shared__ float redS[16][2], redQ[16][2];
    const int qrow = lane >> 2, qcol = (lane & 3) * 2;
    float sg[2] = {0.0f, 0.0f}, qg[2] = {0.0f, 0.0f};

#pragma unroll
    for (int mt = 0; mt < 2; mt++) {
#pragma unroll
        for (int h8 = 0; h8 < 2; h8++) {
            const int col_ = co0 + warp_m * 32 + mt * 16 + qrow + h8 * 8;
            const float b = bias[col_];
#pragma unroll
            for (int nt = 0; nt < 8; nt++) {
#pragma unroll
                for (int cc2 = 0; cc2 < 2; cc2++) {
                    int p = p0 + warp_n * 64 + nt * 8 + qcol + cc2;
                    float v = acc[mt][nt][h8 * 2 + cc2] + b;
                    if (p < HW) {
                        int x = p & (W - 1), y = p >> lgW;
                        Y[(nbase + (size_t)(y + 1) * Wp + (x + 1)) * CC + col_] = v;
                        sg[mt] += v;
                        qg[mt] += v * v;
                    }
                }
            }
        }
    }
#pragma unroll
    for (int off = 16; off > 0; off >>= 1) {
#pragma unroll
        for (int mt = 0; mt < 2; mt++) {
            sg[mt] += __shfl_down_sync(0xffffffffu, sg[mt], off);
            qg[mt] += __shfl_down_sync(0xffffffffu, qg[mt], off);
        }
    }
    if (lane == 0) {
        redS[wid][0] = sg[0]; redS[wid][1] = sg[1];
        redQ[wid][0] = qg[0]; redQ[wid][1] = qg[1];
    }
    __syncthreads();
    if (tid < 8) {
        int wm = tid >> 1, mt = tid & 1;
        float S = 0.0f, Q = 0.0f;
#pragma unroll
        for (int wn = 0; wn < 4; wn++) {
            S += redS[wm * 4 + wn][mt];
            Q += redQ[wm * 4 + wn][mt];
        }
        size_t pidx = (size_t)z * gridDim.x + blockIdx.x;
        part[pidx * 8 + tid] = make_float2(S, Q);
    }
}

// ============================================================
// gn_finalize2: 256 blocks = (tower, n, group). Emits per-channel
// scale = rstd*gamma, shift = beta - mean*scale.
// ============================================================
__global__ __launch_bounds__(256) void gn_finalize2(
    const float2* __restrict__ part, int PT, int HW,
    const float* __restrict__ clsg, const float* __restrict__ clsbt,
    const float* __restrict__ regg, const float* __restrict__ regbt,
    float* __restrict__ oss, float* __restrict__ osh)
{
    const int b = blockIdx.x;
    const int tower = b >> 7, r = b & 127;
    const int n = r >> 4, grp = r & 15;
    const int half = grp >> 3, i = grp & 7;
    const int z = tower * 16 + n * 2 + half;

    float S = 0.0f, Q = 0.0f;
    for (int t = threadIdx.x; t < PT; t += 256) {
        float2 p = part[(size_t)(z * PT + t) * 8 + i];
        S += p.x; Q += p.y;
    }
    __shared__ float sS[256], sQ[256];
    sS[threadIdx.x] = S; sQ[threadIdx.x] = Q;
    __syncthreads();
    for (int off = 128; off > 0; off >>= 1) {
        if (threadIdx.x < off) {
            sS[threadIdx.x] += sS[threadIdx.x + off];
            sQ[threadIdx.x] += sQ[threadIdx.x + off];
        }
        __syncthreads();
    }
    if (threadIdx.x < 16) {
        float cnt  = (float)(GSIZE * HW);
        float mean = sS[0] / cnt;
        float var  = sQ[0] / cnt - mean * mean;
        float rstd = rsqrtf(var + GN_EPS);
        int c = grp * 16 + threadIdx.x;
        float gam = tower ? regg[c] : clsg[c];
        float bet = tower ? regbt[c] : clsbt[c];
        float scale = rstd * gam;
        oss[tower * 2048 + n * 256 + c] = scale;
        osh[tower * 2048 + n * 256 + c] = bet - mean * scale;
    }
}

// ============================================================
// convO: head convs, halo-B, 32co x 256px CTA, 256 threads = 8 warps.
// grid (PT, 1, 16): z = n*2 + mode. mode 0 = cls, 1 = reg+ctr.
// GN applied interior-only; padding stays zero.
// ============================================================
__global__ __launch_bounds__(256) void convO(
    const float4* __restrict__ inC, const float4* __restrict__ inR,
    const uint4* __restrict__ WOHb, const uint4* __restrict__ WOLb,
    const float* __restrict__ ssv, const float* __restrict__ shv,
    const float* __restrict__ clsb, const float* __restrict__ regb,
    const float* __restrict__ ctrb, float* __restrict__ out,
    int H, int W, int Wp, int lgW, int HW, int HpWp, int poff)
{
    extern __shared__ char smem[];
    const uint32_t sb = smem_u32(smem);

    const int tid = threadIdx.x, wid = tid >> 5, lane = tid & 31;
    const int p0 = blockIdx.x * 256;
    const int z = blockIdx.z;
    const int n = z >> 1, mode = z & 1;
    const size_t nbase = (size_t)n * HpWp;

    const float4* in = mode ? inR : inC;
    const uint4* WHl = WOHb + (size_t)mode * (WOELEM / 8);
    const uint4* WLl = WOLb + (size_t)mode * (WOELEM / 8);

    const int R  = 256 >> lgW;
    const int BR = (R + 2) * Wp;
    const int prow0 = p0 >> lgW;
    const int pstart = prow0 * Wp;

    float* sS = (float*)(smem + OSS_O);
    float* sHh = (float*)(smem + OSH_O);
    if (tid < 256) {
        sS[tid]  = ssv[mode * 2048 + n * 256 + tid];
        sHh[tid] = shv[mode * 2048 + n * 256 + tid];
    }
    __syncthreads();

    float acc[2][4][4];
#pragma unroll
    for (int mt = 0; mt < 2; mt++)
#pragma unroll
        for (int nt = 0; nt < 4; nt++)
#pragma unroll
            for (int i = 0; i < 4; i++) acc[mt][nt][i] = 0.0f;

    const int lrow = lane & 7;
    const int matr = (lane >> 3) & 1;
    const int matc = lane >> 4;

    int rnp[2];
#pragma unroll
    for (int np = 0; np < 2; np++)
        rnp[np] = wid * 32 + np * 16 + matc * 8 + lrow;

#pragma unroll 1
    for (int kc = 0; kc < 4; kc++) {
        // ---- B halo fill (fp32 + interior-only GN + split) ----
        {
            const int lim = BR * 16;
#pragma unroll 1
            for (int t0 = tid; t0 < lim; t0 += 1024) {
                float4 xa[4];
#pragma unroll
                for (int u = 0; u < 4; u++) {
                    int t = t0 + u * 256;
                    xa[u] = make_float4(0.f, 0.f, 0.f, 0.f);
                    if (t < lim) {
                        int hr = t >> 4, v = t & 15;
                        int gpix = pstart + hr;
                        if (gpix < HpWp)
                            xa[u] = in[(size_t)(nbase + gpix) * 64 + (kc << 4) + v];
                    }
                }
#pragma unroll
                for (int u = 0; u < 4; u++) {
                    int t = t0 + u * 256;
                    if (t >= lim) break;
                    int hr = t >> 4, v = t & 15;
                    float4 x = xa[u];
                    int hd = hr / Wp;
                    int gx = hr - hd * Wp;
                    int gy = prow0 + hd;
                    if (gy >= 1 && gy <= H && gx >= 1 && gx <= W) {
                        int c = (kc << 6) + (v << 2);
                        x.x = fmaxf(fmaf(x.x, sS[c+0], sHh[c+0]), 0.f);
                        x.y = fmaxf(fmaf(x.y, sS[c+1], sHh[c+1]), 0.f);
                        x.z = fmaxf(fmaf(x.z, sS[c+2], sHh[c+2]), 0.f);
                        x.w = fmaxf(fmaf(x.w, sS[c+3], sHh[c+3]), 0.f);
                    } else {
                        x = make_float4(0.f, 0.f, 0.f, 0.f);
                    }
                    __nv_bfloat16 h0 = __float2bfloat16(x.x);
                    __nv_bfloat16 h1 = __float2bfloat16(x.y);
                    __nv_bfloat16 h2 = __float2bfloat16(x.z);
                    __nv_bfloat16 h3 = __float2bfloat16(x.w);
                    __nv_bfloat16 l0 = __float2bfloat16(x.x - __bfloat162float(h0));
                    __nv_bfloat16 l1 = __float2bfloat16(x.y - __bfloat162float(h1));
                    __nv_bfloat16 l2 = __float2bfloat16(x.z - __bfloat162float(h2));
                    __nv_bfloat16 l3 = __float2bfloat16(x.w - __bfloat162float(h3));
                    uint32_t base = (uint32_t)(hr * PITCH + (v << 3));
                    *reinterpret_cast<uint2*>(smem + OB_H_O + base) =
                        make_uint2(pkbf(h0, h1), pkbf(h2, h3));
                    *reinterpret_cast<uint2*>(smem + OB_L_O + base) =
                        make_uint2(pkbf(l0, l1), pkbf(l2, l3));
                }
            }
        }
        // ---- A tap 0 prefetch ----
        {
            int row = tid >> 3, v = tid & 7;
            uint32_t d = sb + (uint32_t)(row * PITCH + v * 16);
            size_t g = (size_t)row * 32 + kc * 8 + v;
            cpa16(d, WHl + g);
            cpa16(d + ASTG_O, WLl + g);
        }
        CPA_COMMIT();
        CPA_WAIT0();
        __syncthreads();

#pragma unroll 1
        for (int tap = 0; tap < 9; tap++) {
            if (tap < 8) {
                const uint32_t abase = sb + (uint32_t)(((tap + 1) & 1) * 2 * ASTG_O);
                int row = tid >> 3, v = tid & 7;
                uint32_t d = abase + (uint32_t)(row * PITCH + v * 16);
                size_t g = (size_t)(tap + 1) * 1024 + (size_t)row * 32 + kc * 8 + v;
                cpa16(d, WHl + g);
                cpa16(d + ASTG_O, WLl + g);
                CPA_COMMIT();
            }

            const int ky = tap / 3, kx = tap - ky * 3;
            uint32_t bOff[2];
#pragma unroll
            for (int np = 0; np < 2; np++) {
                int r = rnp[np];
                int sr = ((r >> lgW) + ky) * Wp + (r & (W - 1)) + kx;
                bOff[np] = (uint32_t)(sr * PITCH);
            }
            const uint32_t sAH = sb + (uint32_t)((tap & 1) * 2 * ASTG_O);
            const uint32_t sAL = sAH + ASTG_O;
            const uint32_t sBH = sb + OB_H_O;
            const uint32_t sBL = sb + OB_L_O;

#pragma unroll
            for (int ks = 0; ks < 4; ks++) {
                uint32_t ah[2][4], al[2][4], bb[2][4];
#pragma unroll
                for (int mt = 0; mt < 2; mt++) {
                    uint32_t off = (uint32_t)((mt * 16 + matr * 8 + lrow) * PITCH
                                              + (ks * 16 + matc * 8) * 2);
                    ldsm_x4(ah[mt][0], ah[mt][1], ah[mt][2], ah[mt][3], sAH + off);
                    ldsm_x4(al[mt][0], al[mt][1], al[mt][2], al[mt][3], sAL + off);
                }
                const uint32_t kb = (uint32_t)((ks * 16 + matr * 8) * 2);
#pragma unroll
                for (int np = 0; np < 2; np++)
                    ldsm_x4(bb[np][0], bb[np][1], bb[np][2], bb[np][3],
                            sBH + bOff[np] + kb);
#pragma unroll
                for (int mt = 0; mt < 2; mt++)
#pragma unroll
                    for (int np = 0; np < 2; np++) {
                        mma_bf16(acc[mt][np * 2 + 0], ah[mt], &bb[np][0]);
                        mma_bf16(acc[mt][np * 2 + 1], ah[mt], &bb[np][2]);
                        mma_bf16(acc[mt][np * 2 + 0], al[mt], &bb[np][0]);
                        mma_bf16(acc[mt][np * 2 + 1], al[mt], &bb[np][2]);
                    }
#pragma unroll
                for (int np = 0; np < 2; np++)
                    ldsm_x4(bb[np][0], bb[np][1], bb[np][2], bb[np][3],
                            sBL + bOff[np] + kb);
#pragma unroll
                for (int mt = 0; mt < 2; mt++)
#pragma unroll
                    for (int np = 0; np < 2; np++) {
                        mma_bf16(acc[mt][np * 2 + 0], ah[mt], &bb[np][0]);
                        mma_bf16(acc[mt][np * 2 + 1], ah[mt], &bb[np][2]);
                    }
            }
            if (tap < 8) CPA_WAIT0();
            __syncthreads();
        }
    }

    // ---- epilogue: scatter into concat output layout ----
    const int qrow = lane >> 2, qcol = (lane & 3) * 2;
#pragma unroll
    for (int mt = 0; mt < 2; mt++) {
#pragma unroll
        for (int h8 = 0; h8 < 2; h8++) {
            const int row = mt * 16 + h8 * 8 + qrow;
#pragma unroll
            for (int nt = 0; nt < 4; nt++) {
#pragma unroll
                for (int cc2 = 0; cc2 < 2; cc2++) {
                    int p = p0 + wid * 32 + nt * 8 + qcol + cc2;
                    if (p >= HW) continue;
                    float v = acc[mt][nt][h8 * 2 + cc2];
                    int x = p & (W - 1), y = p >> lgW;
                    size_t gp = (size_t)n * TOTHW + poff + (size_t)y * W + x;
                    if (mode == 0) {
                        if (row < 20) out[CLSBASE + gp * 20 + row] = v + clsb[row];
                    } else {
                        if (row < 4)
                            out[REGBASE + gp * 4 + row] = fmaxf(v + regb[row], 0.0f);
                        else if (row == 4)
                            out[CTRBASE + gp] = v + ctrb[0];
                    }
                }
            }
        }
    }
}

// ============================================================
// host launcher
// ============================================================
extern "C" void kernel_launch(void* const* d_in, const int* in_sizes, int n_in,
                              void* d_out, int out_size)
{
    (void)in_sizes; (void)n_in; (void)out_size;

    const float* feat[3] = { (const float*)d_in[0], (const float*)d_in[1],
                             (const float*)d_in[2] };
    const float* cls_conv_w = (const float*)d_in[3];
    const float* cls_conv_b = (const float*)d_in[4];
    const float* cls_gn_g   = (const float*)d_in[5];
    const float* cls_gn_b   = (const float*)d_in[6];
    const float* cls_out_w  = (const float*)d_in[7];
    const float* cls_out_b  = (const float*)d_in[8];
    const float* reg_conv_w = (const float*)d_in[9];
    const float* reg_conv_b = (const float*)d_in[10];
    const float* reg_gn_g   = (const float*)d_in[11];
    const float* reg_gn_b   = (const float*)d_in[12];
    const float* reg_out_w  = (const float*)d_in[13];
    const float* reg_out_b  = (const float*)d_in[14];
    const float* ctr_w      = (const float*)d_in[15];
    const float* ctr_b      = (const float*)d_in[16];

    float* out = (float*)d_out;

    float *XF, *Y0, *Y1, *Y2, *Y3, *ssv, *shv;
    __nv_bfloat16 *WH, *WL, *WOH, *WOL;
    float2* part;
    cudaGetSymbolAddress((void**)&XF, g_XF);
    {
        float* ybase;
        cudaGetSymbolAddress((void**)&ybase, g_Y);
        Y0 = ybase;
        Y1 = ybase + (size_t)XCAP;
        Y2 = ybase + 2 * (size_t)XCAP;
        Y3 = ybase + 3 * (size_t)XCAP;
    }
    cudaGetSymbolAddress((void**)&WH, g_WH);
    cudaGetSymbolAddress((void**)&WL, g_WL);
    cudaGetSymbolAddress((void**)&WOH, g_WOH);
    cudaGetSymbolAddress((void**)&WOL, g_WOL);
    cudaGetSymbolAddress((void**)&ssv, g_ssv);
    cudaGetSymbolAddress((void**)&shv, g_shv);
    cudaGetSymbolAddress((void**)&part, g_part);

    cudaFuncSetAttribute(convM, cudaFuncAttributeMaxDynamicSharedMemorySize, CM_DYN);
    cudaFuncSetAttribute(convO, cudaFuncAttributeMaxDynamicSharedMemorySize, CO_DYN);

    const int TGRID = (WELEM + 255) / 256;
    wsplit<<<TGRID, 256>>>(cls_conv_w,          WH + 0 * (size_t)WELEM, WL + 0 * (size_t)WELEM);
    wsplit<<<TGRID, 256>>>(cls_conv_w + WELEM,  WH + 1 * (size_t)WELEM, WL + 1 * (size_t)WELEM);
    wsplit<<<TGRID, 256>>>(reg_conv_w,          WH + 2 * (size_t)WELEM, WL + 2 * (size_t)WELEM);
    wsplit<<<TGRID, 256>>>(reg_conv_w + WELEM,  WH + 3 * (size_t)WELEM, WL + 3 * (size_t)WELEM);
    woprep<<<(2 * WOELEM + 255) / 256, 256>>>(cls_out_w, reg_out_w, ctr_w, WOH, WOL);

    const int LH[3] = {100, 50, 25};
    const int LW[3] = {128, 64, 32};
    const int LG[3] = {7, 6, 5};
    const int LP[3] = {0, 12800, 16000};

    for (int L = 0; L < 3; L++) {
        const int H = LH[L], W = LW[L], lgW = LG[L];
        const int Hp = H + 2, Wp = W + 2, HpWp = Hp * Wp, HW = H * W;
        const int PT = (HW + 255) / 256;
        const int poff = LP[L];

        const int zpN = (NB * (2 * Wp + 2 * H) * 64 + 255) / 256;
        zeropad<<<zpN, 256>>>((float4*)XF, H, W, Wp, HpWp);
        zeropad<<<zpN, 256>>>((float4*)Y0, H, W, Wp, HpWp);
        zeropad<<<zpN, 256>>>((float4*)Y1, H, W, Wp, HpWp);
        zeropad<<<zpN, 256>>>((float4*)Y2, H, W, Wp, HpWp);
        zeropad<<<zpN, 256>>>((float4*)Y3, H, W, Wp, HpWp);

        dim3 fgrid(W / 32, H, NB * 8);
        featprep<<<fgrid, dim3(32, 32)>>>(feat[L], XF, H, W, Wp, HpWp);

        dim3 cgrid(PT, 1, 32);
        dim3 ogrid(PT, 1, 16);

        // conv layer 1 (both towers)
        convM<<<cgrid, 512, CM_DYN>>>(
            (const float4*)XF, (const float4*)XF,
            (const uint4*)WH, (const uint4*)WL, 0,
            cls_conv_b, reg_conv_b, nullptr, nullptr,
            Y0, Y1, part, H, W, Wp, lgW, HW, HpWp);
        gn_finalize2<<<256, 256>>>(part, PT, HW,
            cls_gn_g, cls_gn_b, reg_gn_g, reg_gn_b,
            ssv + 0 * 4096, shv + 0 * 4096);

        // conv layer 2 (both towers), GN of layer 1 fused on load
        convM<<<cgrid, 512, CM_DYN>>>(
            (const float4*)Y0, (const float4*)Y1,
            (const uint4*)WH, (const uint4*)WL, 1,
            cls_conv_b, reg_conv_b, ssv + 0 * 4096, shv + 0 * 4096,
            Y2, Y3, part, H, W, Wp, lgW, HW, HpWp);
        gn_finalize2<<<256, 256>>>(part, PT, HW,
            cls_gn_g + CC, cls_gn_b + CC, reg_gn_g + CC, reg_gn_b + CC,
            ssv + 1 * 4096, shv + 1 * 4096);

        // heads (both sets), GN of layer 2 fused on load
        convO<<<ogrid, 256, CO_DYN>>>(
            (const float4*)Y2, (const float4*)Y3,
            (const uint4*)WOH, (const uint4*)WOL,
            ssv + 1 * 4096, shv + 1 * 4096,
            cls_out_b, reg_out_b, ctr_b, out,
            H, W, Wp, lgW, HW, HpWp, poff);
    }
}

// round 11
// speedup vs baseline: 9.0353x; 1.3774x over previous
#include <cuda_runtime.h>
#include <cuda_bf16.h>
#include <cuda_fp16.h>
#include <math.h>
#include <stdint.h>

// ---------------- problem constants ----------------
#define NB 8
#define CC 256
#define NGROUPS 16
#define GSIZE 16
#define GN_EPS 1e-5f

#define TOTHW   16800
#define CLSBASE 0
#define REGBASE 2688000
#define CTRBASE 3225600

#define WELEM  (CC * CC * 9)      // 589824 fp16 per tower layer
#define WOELEM (9 * 32 * 256)     // 73728 per head set

#define XCAP 27160000             // fp32 padded NHWC capacity (L0 = 27,156,480)

// scratch (device globals; zero-initialized, no runtime allocation)
__device__ __align__(16) float g_XF[XCAP];
__device__ __align__(16) float g_Y[4][XCAP];          // YAc, YAr, YBc, YBr
__device__ __align__(16) __half g_WF[4 * WELEM];      // tower weights fp16 [l][tap][co][ci]
__device__ __align__(16) __half g_WOF[2 * WOELEM];    // head weights fp16
__device__ float  g_ssv[2 * 2 * 2048];   // [conv][tower][n*256+c] scale
__device__ float  g_shv[2 * 2 * 2048];   // shift
__device__ float2 g_part[32 * 52 * 8];

// ---------------- PTX helpers (arch-agnostic sm_80+) ----------------
__device__ __forceinline__ uint32_t smem_u32(const void* p) {
    uint32_t a;
    asm("{ .reg .u64 t; cvta.to.shared.u64 t, %1; cvt.u32.u64 %0, t; }"
        : "=r"(a) : "l"(p));
    return a;
}
__device__ __forceinline__ void ldsm_x4(uint32_t& r0, uint32_t& r1,
                                        uint32_t& r2, uint32_t& r3, uint32_t a) {
    asm volatile("ldmatrix.sync.aligned.m8n8.x4.shared.b16 {%0,%1,%2,%3}, [%4];"
        : "=r"(r0), "=r"(r1), "=r"(r2), "=r"(r3) : "r"(a));
}
__device__ __forceinline__ void mma_f16(float* d, const uint32_t* a,
                                        const uint32_t* b) {
    asm volatile("mma.sync.aligned.m16n8k16.row.col.f32.f16.f16.f32 "
        "{%0,%1,%2,%3}, {%4,%5,%6,%7}, {%8,%9}, {%0,%1,%2,%3};"
        : "+f"(d[0]), "+f"(d[1]), "+f"(d[2]), "+f"(d[3])
        : "r"(a[0]), "r"(a[1]), "r"(a[2]), "r"(a[3]), "r"(b[0]), "r"(b[1]));
}
__device__ __forceinline__ void cpa16(uint32_t d, const void* s) {
    asm volatile("cp.async.cg.shared.global [%0], [%1], 16;"
                 :: "r"(d), "l"(s) : "memory");
}
#define CPA_COMMIT() asm volatile("cp.async.commit_group;" ::: "memory")
#define CPA_WAIT0()  asm volatile("cp.async.wait_group 0;" ::: "memory")

__device__ __forceinline__ uint32_t pkh(__half a, __half b) {
    __half2 t = __halves2half2(a, b);
    return *reinterpret_cast<uint32_t*>(&t);
}

// ---- convM smem geometry (dynamic): A 2-stage (hi only) + B halo hi/lo ----
#define PITCH 144
#define ASTG  18432                  // one A buffer (128 rows x 144B)
#define OB_H  36864                  // after 2 A stages
#define OB_L  111744                 // OB_H + 520*144
#define OSS   186624                 // OB_L + 520*144
#define OSH   187648
#define CM_DYN 188672

// ---- convO smem geometry (dynamic) ----
#define ASTG_O 4608                  // 32 rows x 144B
#define OB_H_O 9216                  // after 2 A stages
#define OB_L_O 84096                 // + 520*144
#define OSS_O  158976
#define OSH_O  160000
#define CO_DYN 161024

// ============================================================
// wprep: w[co][ci][tap] fp32 -> WF[tap][co][ci] fp16
// ============================================================
__global__ __launch_bounds__(256) void wprep(
    const float* __restrict__ w, __half* __restrict__ WF)
{
    int idx = blockIdx.x * 256 + threadIdx.x;
    if (idx >= WELEM) return;
    int tap = idx / 65536;
    int r   = idx - tap * 65536;
    int co  = r >> 8, ci = r & 255;
    WF[idx] = __float2half_rn(w[co * 2304 + ci * 9 + tap]);
}

// ============================================================
// woprep: head weights -> [set][tap][row32][ci] fp16
// ============================================================
__global__ __launch_bounds__(256) void woprep(
    const float* __restrict__ clsw, const float* __restrict__ regw,
    const float* __restrict__ ctrw, __half* __restrict__ WOF)
{
    int idx = blockIdx.x * 256 + threadIdx.x;
    if (idx >= 2 * WOELEM) return;
    int set = idx / WOELEM;
    int r   = idx - set * WOELEM;
    int tap = r / 8192;
    int r2  = r - tap * 8192;
    int row = r2 >> 8, ci = r2 & 255;
    float v = 0.0f;
    if (set == 0) {
        if (row < 20) v = clsw[(row * 256 + ci) * 9 + tap];
    } else {
        if (row < 4)       v = regw[(row * 256 + ci) * 9 + tap];
        else if (row == 4) v = ctrw[ci * 9 + tap];
    }
    WOF[idx] = __float2half_rn(v);
}

// ============================================================
// zeropad: zero border pixels (all channels) of padded NHWC fp32 buffer
// ============================================================
__global__ __launch_bounds__(256) void zeropad(
    float4* __restrict__ buf, int H, int W, int Wp, int HpWp)
{
    int bc = 2 * Wp + 2 * H;
    int total = NB * bc * 64;
    int idx = blockIdx.x * 256 + threadIdx.x;
    if (idx >= total) return;
    int ch4 = idx & 63;
    int r   = idx >> 6;
    int n   = r / bc;
    int b   = r - n * bc;
    int py, px;
    if (b < Wp)           { py = 0;     px = b; }
    else if (b < 2 * Wp)  { py = H + 1; px = b - Wp; }
    else {
        int rr = b - 2 * Wp;
        py = 1 + (rr >> 1);
        px = (rr & 1) ? (W + 1) : 0;
    }
    buf[((size_t)n * HpWp + (size_t)py * Wp + px) * 64 + ch4] =
        make_float4(0.f, 0.f, 0.f, 0.f);
}

// ============================================================
// featprep: NCHW fp32 -> padded NHWC fp32 (32x32 smem transpose)
// ============================================================
__global__ __launch_bounds__(1024) void featprep(
    const float* __restrict__ feat, float* __restrict__ XF,
    int H, int W, int Wp, int HpWp)
{
    __shared__ float tile[32][33];
    int xt = blockIdx.x, y = blockIdx.y;
    int n  = blockIdx.z >> 3, ct = blockIdx.z & 7;
    int tx = threadIdx.x, ty = threadIdx.y;

    tile[ty][tx] = feat[(((size_t)n * CC + ct * 32 + ty) * H + y) * W + xt * 32 + tx];
    __syncthreads();

    int c = ct * 32 + tx;
    int x = xt * 32 + ty;
    XF[((size_t)n * HpWp + (size_t)(y + 1) * Wp + (x + 1)) * CC + c] = tile[tx][ty];
}

// ============================================================
// convM: warp-mma 3x3 conv, halo-resident B (fp16 hi/lo) with fused
// GN+split on load (interior-only); weights single fp16.
// Per K-step: acc += W*Bh + W*Bl  (2 MMAs, fp32 accum).
// CTA = 128co x 256px, 512 threads = 16 warps (4m x 4n), 1 CTA/SM.
// grid (PT, 1, 32): z = tower*16 + n*2 + cohalf.
// ============================================================
__global__ __launch_bounds__(512) void convM(
    const float4* __restrict__ inC, const float4* __restrict__ inR,
    const uint4* __restrict__ WFb, int layer,
    const float* __restrict__ clscb, const float* __restrict__ regcb,
    const float* __restrict__ ssv, const float* __restrict__ shv,   // may be null
    float* __restrict__ outC, float* __restrict__ outR,
    float2* __restrict__ part,
    int H, int W, int Wp, int lgW, int HW, int HpWp)
{
    extern __shared__ char smem[];
    const uint32_t sb = smem_u32(smem);

    const int tid = threadIdx.x, wid = tid >> 5, lane = tid & 31;
    const int warp_m = wid >> 2, warp_n = wid & 3;
    const int p0 = blockIdx.x * 256;
    const int z = blockIdx.z;
    const int tower = z >> 4, zz = z & 15;
    const int n = zz >> 1, co0 = (zz & 1) * 128;
    const size_t nbase = (size_t)n * HpWp;

    const float4* in = tower ? inR : inC;
    float* Y = tower ? outR : outC;
    const uint4* WFl = WFb + (size_t)(tower * 2 + layer) * (WELEM / 8);
    const float* bias = (tower ? regcb : clscb) + layer * CC;

    const int R  = 256 >> lgW;
    const int BR = (R + 2) * Wp;
    const int prow0 = p0 >> lgW;
    const int pstart = prow0 * Wp;

    float* sS = (float*)(smem + OSS);
    float* sHh = (float*)(smem + OSH);
    if (ssv && tid < 256) {
        sS[tid]  = ssv[tower * 2048 + n * 256 + tid];
        sHh[tid] = shv[tower * 2048 + n * 256 + tid];
    }
    __syncthreads();

    float acc[2][8][4];
#pragma unroll
    for (int mt = 0; mt < 2; mt++)
#pragma unroll
        for (int nt = 0; nt < 8; nt++)
#pragma unroll
            for (int i = 0; i < 4; i++) acc[mt][nt][i] = 0.0f;

    const int lrow = lane & 7;
    const int matr = (lane >> 3) & 1;
    const int matc = lane >> 4;

    int rnp[4];
#pragma unroll
    for (int np = 0; np < 4; np++)
        rnp[np] = warp_n * 64 + np * 16 + matc * 8 + lrow;

#pragma unroll 1
    for (int kc = 0; kc < 4; kc++) {
        // ---- B halo fill: fp32 -> (GN+ReLU interior-only) -> fp16 hi/lo ----
        {
            const int lim = BR * 16;
#pragma unroll 1
            for (int t0 = tid; t0 < lim; t0 += 2048) {
                float4 xa[4];
#pragma unroll
                for (int u = 0; u < 4; u++) {
                    int t = t0 + u * 512;
                    xa[u] = make_float4(0.f, 0.f, 0.f, 0.f);
                    if (t < lim) {
                        int hr = t >> 4, v = t & 15;
                        int gpix = pstart + hr;
                        if (gpix < HpWp)
                            xa[u] = in[(size_t)(nbase + gpix) * 64 + (kc << 4) + v];
                    }
                }
#pragma unroll
                for (int u = 0; u < 4; u++) {
                    int t = t0 + u * 512;
                    if (t >= lim) break;
                    int hr = t >> 4, v = t & 15;
                    float4 x = xa[u];
                    if (ssv) {
                        int hd = hr / Wp;
                        int gx = hr - hd * Wp;
                        int gy = prow0 + hd;
                        if (gy >= 1 && gy <= H && gx >= 1 && gx <= W) {
                            int c = (kc << 6) + (v << 2);
                            x.x = fmaxf(fmaf(x.x, sS[c+0], sHh[c+0]), 0.f);
                            x.y = fmaxf(fmaf(x.y, sS[c+1], sHh[c+1]), 0.f);
                            x.z = fmaxf(fmaf(x.z, sS[c+2], sHh[c+2]), 0.f);
                            x.w = fmaxf(fmaf(x.w, sS[c+3], sHh[c+3]), 0.f);
                        } else {
                            x = make_float4(0.f, 0.f, 0.f, 0.f);
                        }
                    }
                    __half h0 = __float2half_rn(x.x);
                    __half h1 = __float2half_rn(x.y);
                    __half h2 = __float2half_rn(x.z);
                    __half h3 = __float2half_rn(x.w);
                    __half l0 = __float2half_rn(x.x - __half2float(h0));
                    __half l1 = __float2half_rn(x.y - __half2float(h1));
                    __half l2 = __float2half_rn(x.z - __half2float(h2));
                    __half l3 = __float2half_rn(x.w - __half2float(h3));
                    uint32_t base = (uint32_t)(hr * PITCH + (v << 3));
                    *reinterpret_cast<uint2*>(smem + OB_H + base) =
                        make_uint2(pkh(h0, h1), pkh(h2, h3));
                    *reinterpret_cast<uint2*>(smem + OB_L + base) =
                        make_uint2(pkh(l0, l1), pkh(l2, l3));
                }
            }
        }
        // ---- A tap 0 prefetch (stage 0) ----
#pragma unroll
        for (int t = tid; t < 1024; t += 512) {
            int row = t >> 3, v = t & 7;
            uint32_t d = sb + (uint32_t)(row * PITCH + v * 16);
            size_t g = (size_t)(co0 + row) * 32 + kc * 8 + v;
            cpa16(d, WFl + g);
        }
        CPA_COMMIT();
        CPA_WAIT0();
        __syncthreads();

#pragma unroll 1
        for (int tap = 0; tap < 9; tap++) {
            if (tap < 8) {
                const uint32_t abase = sb + (uint32_t)(((tap + 1) & 1) * ASTG);
#pragma unroll
                for (int t = tid; t < 1024; t += 512) {
                    int row = t >> 3, v = t & 7;
                    uint32_t d = abase + (uint32_t)(row * PITCH + v * 16);
                    size_t g = (size_t)(tap + 1) * 8192 + (size_t)(co0 + row) * 32 + kc * 8 + v;
                    cpa16(d, WFl + g);
                }
                CPA_COMMIT();
            }

            const int ky = tap / 3, kx = tap - ky * 3;
            uint32_t bOff[4];
#pragma unroll
            for (int np = 0; np < 4; np++) {
                int r = rnp[np];
                int sr = ((r >> lgW) + ky) * Wp + (r & (W - 1)) + kx;
                bOff[np] = (uint32_t)(sr * PITCH);
            }
            const uint32_t sAH = sb + (uint32_t)((tap & 1) * ASTG);
            const uint32_t sBH = sb + OB_H;
            const uint32_t sBL = sb + OB_L;
            const int m0 = warp_m * 32;

#pragma unroll
            for (int ks = 0; ks < 4; ks++) {
                uint32_t ah[2][4], bb[4][4];
#pragma unroll
                for (int mt = 0; mt < 2; mt++) {
                    uint32_t off = (uint32_t)((m0 + mt * 16 + matr * 8 + lrow) * PITCH
                                              + (ks * 16 + matc * 8) * 2);
                    ldsm_x4(ah[mt][0], ah[mt][1], ah[mt][2], ah[mt][3], sAH + off);
                }
                const uint32_t kb = (uint32_t)((ks * 16 + matr * 8) * 2);
#pragma unroll
                for (int np = 0; np < 4; np++)
                    ldsm_x4(bb[np][0], bb[np][1], bb[np][2], bb[np][3],
                            sBH + bOff[np] + kb);
#pragma unroll
                for (int mt = 0; mt < 2; mt++)
#pragma unroll
                    for (int np = 0; np < 4; np++) {
                        mma_f16(acc[mt][np * 2 + 0], ah[mt], &bb[np][0]);
                        mma_f16(acc[mt][np * 2 + 1], ah[mt], &bb[np][2]);
                    }
#pragma unroll
                for (int np = 0; np < 4; np++)
                    ldsm_x4(bb[np][0], bb[np][1], bb[np][2], bb[np][3],
                            sBL + bOff[np] + kb);
#pragma unroll
                for (int mt = 0; mt < 2; mt++)
#pragma unroll
                    for (int np = 0; np < 4; np++) {
                        mma_f16(acc[mt][np * 2 + 0], ah[mt], &bb[np][0]);
                        mma_f16(acc[mt][np * 2 + 1], ah[mt], &bb[np][2]);
                    }
            }
            if (tap < 8) CPA_WAIT0();
            __syncthreads();
        }
    }

    // ---- epilogue: bias, store fp32 padded NHWC, deterministic GN partials ----
    __shared__ float redS[16][2], redQ[16][2];
    const int qrow = lane >> 2, qcol = (lane & 3) * 2;
    float sg[2] = {0.0f, 0.0f}, qg[2] = {0.0f, 0.0f};

#pragma unroll
    for (int mt = 0; mt < 2; mt++) {
#pragma unroll
        for (int h8 = 0; h8 < 2; h8++) {
            const int col_ = co0 + warp_m * 32 + mt * 16 + qrow + h8 * 8;
            const float b = bias[col_];
#pragma unroll
            for (int nt = 0; nt < 8; nt++) {
#pragma unroll
                for (int cc2 = 0; cc2 < 2; cc2++) {
                    int p = p0 + warp_n * 64 + nt * 8 + qcol + cc2;
                    float v = acc[mt][nt][h8 * 2 + cc2] + b;
                    if (p < HW) {
                        int x = p & (W - 1), y = p >> lgW;
                        Y[(nbase + (size_t)(y + 1) * Wp + (x + 1)) * CC + col_] = v;
                        sg[mt] += v;
                        qg[mt] += v * v;
                    }
                }
            }
        }
    }
#pragma unroll
    for (int off = 16; off > 0; off >>= 1) {
#pragma unroll
        for (int mt = 0; mt < 2; mt++) {
            sg[mt] += __shfl_down_sync(0xffffffffu, sg[mt], off);
            qg[mt] += __shfl_down_sync(0xffffffffu, qg[mt], off);
        }
    }
    if (lane == 0) {
        redS[wid][0] = sg[0]; redS[wid][1] = sg[1];
        redQ[wid][0] = qg[0]; redQ[wid][1] = qg[1];
    }
    __syncthreads();
    if (tid < 8) {
        int wm = tid >> 1, mt = tid & 1;
        float S = 0.0f, Q = 0.0f;
#pragma unroll
        for (int wn = 0; wn < 4; wn++) {
            S += redS[wm * 4 + wn][mt];
            Q += redQ[wm * 4 + wn][mt];
        }
        size_t pidx = (size_t)z * gridDim.x + blockIdx.x;
        part[pidx * 8 + tid] = make_float2(S, Q);
    }
}

// ============================================================
// gn_finalize2: 256 blocks = (tower, n, group). Emits per-channel
// scale = rstd*gamma, shift = beta - mean*scale.
// ============================================================
__global__ __launch_bounds__(256) void gn_finalize2(
    const float2* __restrict__ part, int PT, int HW,
    const float* __restrict__ clsg, const float* __restrict__ clsbt,
    const float* __restrict__ regg, const float* __restrict__ regbt,
    float* __restrict__ oss, float* __restrict__ osh)
{
    const int b = blockIdx.x;
    const int tower = b >> 7, r = b & 127;
    const int n = r >> 4, grp = r & 15;
    const int half = grp >> 3, i = grp & 7;
    const int z = tower * 16 + n * 2 + half;

    float S = 0.0f, Q = 0.0f;
    for (int t = threadIdx.x; t < PT; t += 256) {
        float2 p = part[(size_t)(z * PT + t) * 8 + i];
        S += p.x; Q += p.y;
    }
    __shared__ float sS[256], sQ[256];
    sS[threadIdx.x] = S; sQ[threadIdx.x] = Q;
    __syncthreads();
    for (int off = 128; off > 0; off >>= 1) {
        if (threadIdx.x < off) {
            sS[threadIdx.x] += sS[threadIdx.x + off];
            sQ[threadIdx.x] += sQ[threadIdx.x + off];
        }
        __syncthreads();
    }
    if (threadIdx.x < 16) {
        float cnt  = (float)(GSIZE * HW);
        float mean = sS[0] / cnt;
        float var  = sQ[0] / cnt - mean * mean;
        float rstd = rsqrtf(var + GN_EPS);
        int c = grp * 16 + threadIdx.x;
        float gam = tower ? regg[c] : clsg[c];
        float bet = tower ? regbt[c] : clsbt[c];
        float scale = rstd * gam;
        oss[tower * 2048 + n * 256 + c] = scale;
        osh[tower * 2048 + n * 256 + c] = bet - mean * scale;
    }
}

// ============================================================
// convO: head convs, halo-B fp16 hi/lo, weights single fp16.
// 32co x 256px CTA, 256 threads = 8 warps. grid (PT, 1, 16).
// ============================================================
__global__ __launch_bounds__(256) void convO(
    const float4* __restrict__ inC, const float4* __restrict__ inR,
    const uint4* __restrict__ WOFb,
    const float* __restrict__ ssv, const float* __restrict__ shv,
    const float* __restrict__ clsb, const float* __restrict__ regb,
    const float* __restrict__ ctrb, float* __restrict__ out,
    int H, int W, int Wp, int lgW, int HW, int HpWp, int poff)
{
    extern __shared__ char smem[];
    const uint32_t sb = smem_u32(smem);

    const int tid = threadIdx.x, wid = tid >> 5, lane = tid & 31;
    const int p0 = blockIdx.x * 256;
    const int z = blockIdx.z;
    const int n = z >> 1, mode = z & 1;
    const size_t nbase = (size_t)n * HpWp;

    const float4* in = mode ? inR : inC;
    const uint4* WFl = WOFb + (size_t)mode * (WOELEM / 8);

    const int R  = 256 >> lgW;
    const int BR = (R + 2) * Wp;
    const int prow0 = p0 >> lgW;
    const int pstart = prow0 * Wp;

    float* sS = (float*)(smem + OSS_O);
    float* sHh = (float*)(smem + OSH_O);
    if (tid < 256) {
        sS[tid]  = ssv[mode * 2048 + n * 256 + tid];
        sHh[tid] = shv[mode * 2048 + n * 256 + tid];
    }
    __syncthreads();

    float acc[2][4][4];
#pragma unroll
    for (int mt = 0; mt < 2; mt++)
#pragma unroll
        for (int nt = 0; nt < 4; nt++)
#pragma unroll
            for (int i = 0; i < 4; i++) acc[mt][nt][i] = 0.0f;

    const int lrow = lane & 7;
    const int matr = (lane >> 3) & 1;
    const int matc = lane >> 4;

    int rnp[2];
#pragma unroll
    for (int np = 0; np < 2; np++)
        rnp[np] = wid * 32 + np * 16 + matc * 8 + lrow;

#pragma unroll 1
    for (int kc = 0; kc < 4; kc++) {
        // ---- B halo fill (fp32 + interior-only GN + fp16 split) ----
        {
            const int lim = BR * 16;
#pragma unroll 1
            for (int t0 = tid; t0 < lim; t0 += 1024) {
                float4 xa[4];
#pragma unroll
                for (int u = 0; u < 4; u++) {
                    int t = t0 + u * 256;
                    xa[u] = make_float4(0.f, 0.f, 0.f, 0.f);
                    if (t < lim) {
                        int hr = t >> 4, v = t & 15;
                        int gpix = pstart + hr;
                        if (gpix < HpWp)
                            xa[u] = in[(size_t)(nbase + gpix) * 64 + (kc << 4) + v];
                    }
                }
#pragma unroll
                for (int u = 0; u < 4; u++) {
                    int t = t0 + u * 256;
                    if (t >= lim) break;
                    int hr = t >> 4, v = t & 15;
                    float4 x = xa[u];
                    int hd = hr / Wp;
                    int gx = hr - hd * Wp;
                    int gy = prow0 + hd;
                    if (gy >= 1 && gy <= H && gx >= 1 && gx <= W) {
                        int c = (kc << 6) + (v << 2);
                        x.x = fmaxf(fmaf(x.x, sS[c+0], sHh[c+0]), 0.f);
                        x.y = fmaxf(fmaf(x.y, sS[c+1], sHh[c+1]), 0.f);
                        x.z = fmaxf(fmaf(x.z, sS[c+2], sHh[c+2]), 0.f);
                        x.w = fmaxf(fmaf(x.w, sS[c+3], sHh[c+3]), 0.f);
                    } else {
                        x = make_float4(0.f, 0.f, 0.f, 0.f);
                    }
                    __half h0 = __float2half_rn(x.x);
                    __half h1 = __float2half_rn(x.y);
                    __half h2 = __float2half_rn(x.z);
                    __half h3 = __float2half_rn(x.w);
                    __half l0 = __float2half_rn(x.x - __half2float(h0));
                    __half l1 = __float2half_rn(x.y - __half2float(h1));
                    __half l2 = __float2half_rn(x.z - __half2float(h2));
                    __half l3 = __float2half_rn(x.w - __half2float(h3));
                    uint32_t base = (uint32_t)(hr * PITCH + (v << 3));
                    *reinterpret_cast<uint2*>(smem + OB_H_O + base) =
                        make_uint2(pkh(h0, h1), pkh(h2, h3));
                    *reinterpret_cast<uint2*>(smem + OB_L_O + base) =
                        make_uint2(pkh(l0, l1), pkh(l2, l3));
                }
            }
        }
        // ---- A tap 0 prefetch ----
        {
            int row = tid >> 3, v = tid & 7;
            uint32_t d = sb + (uint32_t)(row * PITCH + v * 16);
            size_t g = (size_t)row * 32 + kc * 8 + v;
            cpa16(d, WFl + g);
        }
        CPA_COMMIT();
        CPA_WAIT0();
        __syncthreads();

#pragma unroll 1
        for (int tap = 0; tap < 9; tap++) {
            if (tap < 8) {
                const uint32_t abase = sb + (uint32_t)(((tap + 1) & 1) * ASTG_O);
                int row = tid >> 3, v = tid & 7;
                uint32_t d = abase + (uint32_t)(row * PITCH + v * 16);
                size_t g = (size_t)(tap + 1) * 1024 + (size_t)row * 32 + kc * 8 + v;
                cpa16(d, WFl + g);
                CPA_COMMIT();
            }

            const int ky = tap / 3, kx = tap - ky * 3;
            uint32_t bOff[2];
#pragma unroll
            for (int np = 0; np < 2; np++) {
                int r = rnp[np];
                int sr = ((r >> lgW) + ky) * Wp + (r & (W - 1)) + kx;
                bOff[np] = (uint32_t)(sr * PITCH);
            }
            const uint32_t sAH = sb + (uint32_t)((tap & 1) * ASTG_O);
            const uint32_t sBH = sb + OB_H_O;
            const uint32_t sBL = sb + OB_L_O;

#pragma unroll
            for (int ks = 0; ks < 4; ks++) {
                uint32_t ah[2][4], bb[2][4];
#pragma unroll
                for (int mt = 0; mt < 2; mt++) {
                    uint32_t off = (uint32_t)((mt * 16 + matr * 8 + lrow) * PITCH
                                              + (ks * 16 + matc * 8) * 2);
                    ldsm_x4(ah[mt][0], ah[mt][1], ah[mt][2], ah[mt][3], sAH + off);
                }
                const uint32_t kb = (uint32_t)((ks * 16 + matr * 8) * 2);
#pragma unroll
                for (int np = 0; np < 2; np++)
                    ldsm_x4(bb[np][0], bb[np][1], bb[np][2], bb[np][3],
                            sBH + bOff[np] + kb);
#pragma unroll
                for (int mt = 0; mt < 2; mt++)
#pragma unroll
                    for (int np = 0; np < 2; np++) {
                        mma_f16(acc[mt][np * 2 + 0], ah[mt], &bb[np][0]);
                        mma_f16(acc[mt][np * 2 + 1], ah[mt], &bb[np][2]);
                    }
#pragma unroll
                for (int np = 0; np < 2; np++)
                    ldsm_x4(bb[np][0], bb[np][1], bb[np][2], bb[np][3],
                            sBL + bOff[np] + kb);
#pragma unroll
                for (int mt = 0; mt < 2; mt++)
#pragma unroll
                    for (int np = 0; np < 2; np++) {
                        mma_f16(acc[mt][np * 2 + 0], ah[mt], &bb[np][0]);
                        mma_f16(acc[mt][np * 2 + 1], ah[mt], &bb[np][2]);
                    }
            }
            if (tap < 8) CPA_WAIT0();
            __syncthreads();
        }
    }

    // ---- epilogue: scatter into concat output layout ----
    const int qrow = lane >> 2, qcol = (lane & 3) * 2;
#pragma unroll
    for (int mt = 0; mt < 2; mt++) {
#pragma unroll
        for (int h8 = 0; h8 < 2; h8++) {
            const int row = mt * 16 + h8 * 8 + qrow;
#pragma unroll
            for (int nt = 0; nt < 4; nt++) {
#pragma unroll
                for (int cc2 = 0; cc2 < 2; cc2++) {
                    int p = p0 + wid * 32 + nt * 8 + qcol + cc2;
                    if (p >= HW) continue;
                    float v = acc[mt][nt][h8 * 2 + cc2];
                    int x = p & (W - 1), y = p >> lgW;
                    size_t gp = (size_t)n * TOTHW + poff + (size_t)y * W + x;
                    if (mode == 0) {
                        if (row < 20) out[CLSBASE + gp * 20 + row] = v + clsb[row];
                    } else {
                        if (row < 4)
                            out[REGBASE + gp * 4 + row] = fmaxf(v + regb[row], 0.0f);
                        else if (row == 4)
                            out[CTRBASE + gp] = v + ctrb[0];
                    }
                }
            }
        }
    }
}

// ============================================================
// host launcher
// ============================================================
extern "C" void kernel_launch(void* const* d_in, const int* in_sizes, int n_in,
                              void* d_out, int out_size)
{
    (void)in_sizes; (void)n_in; (void)out_size;

    const float* feat[3] = { (const float*)d_in[0], (const float*)d_in[1],
                             (const float*)d_in[2] };
    const float* cls_conv_w = (const float*)d_in[3];
    const float* cls_conv_b = (const float*)d_in[4];
    const float* cls_gn_g   = (const float*)d_in[5];
    const float* cls_gn_b   = (const float*)d_in[6];
    const float* cls_out_w  = (const float*)d_in[7];
    const float* cls_out_b  = (const float*)d_in[8];
    const float* reg_conv_w = (const float*)d_in[9];
    const float* reg_conv_b = (const float*)d_in[10];
    const float* reg_gn_g   = (const float*)d_in[11];
    const float* reg_gn_b   = (const float*)d_in[12];
    const float* reg_out_w  = (const float*)d_in[13];
    const float* reg_out_b  = (const float*)d_in[14];
    const float* ctr_w      = (const float*)d_in[15];
    const float* ctr_b      = (const float*)d_in[16];

    float* out = (float*)d_out;

    float *XF, *Y0, *Y1, *Y2, *Y3, *ssv, *shv;
    __half *WF, *WOF;
    float2* part;
    cudaGetSymbolAddress((void**)&XF, g_XF);
    {
        float* ybase;
        cudaGetSymbolAddress((void**)&ybase, g_Y);
        Y0 = ybase;
        Y1 = ybase + (size_t)XCAP;
        Y2 = ybase + 2 * (size_t)XCAP;
        Y3 = ybase + 3 * (size_t)XCAP;
    }
    cudaGetSymbolAddress((void**)&WF, g_WF);
    cudaGetSymbolAddress((void**)&WOF, g_WOF);
    cudaGetSymbolAddress((void**)&ssv, g_ssv);
    cudaGetSymbolAddress((void**)&shv, g_shv);
    cudaGetSymbolAddress((void**)&part, g_part);

    cudaFuncSetAttribute(convM, cudaFuncAttributeMaxDynamicSharedMemorySize, CM_DYN);
    cudaFuncSetAttribute(convO, cudaFuncAttributeMaxDynamicSharedMemorySize, CO_DYN);

    const int TGRID = (WELEM + 255) / 256;
    wprep<<<TGRID, 256>>>(cls_conv_w,          WF + 0 * (size_t)WELEM);
    wprep<<<TGRID, 256>>>(cls_conv_w + WELEM,  WF + 1 * (size_t)WELEM);
    wprep<<<TGRID, 256>>>(reg_conv_w,          WF + 2 * (size_t)WELEM);
    wprep<<<TGRID, 256>>>(reg_conv_w + WELEM,  WF + 3 * (size_t)WELEM);
    woprep<<<(2 * WOELEM + 255) / 256, 256>>>(cls_out_w, reg_out_w, ctr_w, WOF);

    const int LH[3] = {100, 50, 25};
    const int LW[3] = {128, 64, 32};
    const int LG[3] = {7, 6, 5};
    const int LP[3] = {0, 12800, 16000};

    for (int L = 0; L < 3; L++) {
        const int H = LH[L], W = LW[L], lgW = LG[L];
        const int Hp = H + 2, Wp = W + 2, HpWp = Hp * Wp, HW = H * W;
        const int PT = (HW + 255) / 256;
        const int poff = LP[L];

        const int zpN = (NB * (2 * Wp + 2 * H) * 64 + 255) / 256;
        zeropad<<<zpN, 256>>>((float4*)XF, H, W, Wp, HpWp);
        zeropad<<<zpN, 256>>>((float4*)Y0, H, W, Wp, HpWp);
        zeropad<<<zpN, 256>>>((float4*)Y1, H, W, Wp, HpWp);
        zeropad<<<zpN, 256>>>((float4*)Y2, H, W, Wp, HpWp);
        zeropad<<<zpN, 256>>>((float4*)Y3, H, W, Wp, HpWp);

        dim3 fgrid(W / 32, H, NB * 8);
        featprep<<<fgrid, dim3(32, 32)>>>(feat[L], XF, H, W, Wp, HpWp);

        dim3 cgrid(PT, 1, 32);
        dim3 ogrid(PT, 1, 16);

        // conv layer 1 (both towers)
        convM<<<cgrid, 512, CM_DYN>>>(
            (const float4*)XF, (const float4*)XF,
            (const uint4*)WF, 0,
            cls_conv_b, reg_conv_b, nullptr, nullptr,
            Y0, Y1, part, H, W, Wp, lgW, HW, HpWp);
        gn_finalize2<<<256, 256>>>(part, PT, HW,
            cls_gn_g, cls_gn_b, reg_gn_g, reg_gn_b,
            ssv + 0 * 4096, shv + 0 * 4096);

        // conv layer 2 (both towers), GN of layer 1 fused on load
        convM<<<cgrid, 512, CM_DYN>>>(
            (const float4*)Y0, (const float4*)Y1,
            (const uint4*)WF, 1,
            cls_conv_b, reg_conv_b, ssv + 0 * 4096, shv + 0 * 4096,
            Y2, Y3, part, H, W, Wp, lgW, HW, HpWp);
        gn_finalize2<<<256, 256>>>(part, PT, HW,
            cls_gn_g + CC, cls_gn_b + CC, reg_gn_g + CC, reg_gn_b + CC,
            ssv + 1 * 4096, shv + 1 * 4096);

        // heads (both sets), GN of layer 2 fused on load
        convO<<<ogrid, 256, CO_DYN>>>(
            (const float4*)Y2, (const float4*)Y3,
            (const uint4*)WOF,
            ssv + 1 * 4096, shv + 1 * 4096,
            cls_out_b, reg_out_b, ctr_b, out,
            H, W, Wp, lgW, HW, HpWp, poff);
    }
}

// round 12
// speedup vs baseline: 11.3003x; 1.2507x over previous
#include <cuda_runtime.h>
#include <cuda_fp16.h>
#include <math.h>
#include <stdint.h>

// ---------------- problem constants ----------------
#define NB 8
#define CC 256
#define NGROUPS 16
#define GSIZE 16
#define GN_EPS 1e-5f

#define TOTHW   16800
#define CLSBASE 0
#define REGBASE 2688000
#define CTRBASE 3225600

#define WELEM  (CC * CC * 9)      // 589824 fp16 per tower layer
#define WOELEM (9 * 32 * 256)     // 73728 per head set

#define TOTPT 67                  // 50 + 13 + 4 px-tiles across levels
#define XCAP2 36070000            // all-level fp32 padded NHWC (36,065,280 used)

// per-level compile-time tables
__constant__ int cH[3]    = {100, 50, 25};
__constant__ int cW[3]    = {128, 64, 32};
__constant__ int cLgW[3]  = {7, 6, 5};
__constant__ int cWp[3]   = {130, 66, 34};
__constant__ int cHpWp[3] = {13260, 3432, 918};
__constant__ int cHW[3]   = {12800, 3200, 800};
__constant__ int cPT[3]   = {50, 13, 4};
__constant__ int cSegA[3] = {0, 50, 63};
__constant__ int cPoff[3] = {0, 12800, 16000};
__constant__ unsigned long long cXpix[3] = {0ull, 106080ull, 133536ull};

// scratch (device globals; zero-initialized, no runtime allocation)
__device__ __align__(16) float g_XF[XCAP2];
__device__ __align__(16) float g_Y[4][XCAP2];
__device__ __align__(16) __half g_WF[4 * WELEM];
__device__ __align__(16) __half g_WOF[2 * WOELEM];
__device__ float  g_ssv[2 * 3 * 2 * 2048];   // [conv][level][tower][n*256+c]
__device__ float  g_shv[2 * 3 * 2 * 2048];
__device__ float2 g_part[32 * TOTPT * 8];

// ---------------- PTX helpers (arch-agnostic sm_80+) ----------------
__device__ __forceinline__ uint32_t smem_u32(const void* p) {
    uint32_t a;
    asm("{ .reg .u64 t; cvta.to.shared.u64 t, %1; cvt.u32.u64 %0, t; }"
        : "=r"(a) : "l"(p));
    return a;
}
__device__ __forceinline__ void ldsm_x4(uint32_t& r0, uint32_t& r1,
                                        uint32_t& r2, uint32_t& r3, uint32_t a) {
    asm volatile("ldmatrix.sync.aligned.m8n8.x4.shared.b16 {%0,%1,%2,%3}, [%4];"
        : "=r"(r0), "=r"(r1), "=r"(r2), "=r"(r3) : "r"(a));
}
__device__ __forceinline__ void mma_f16(float* d, const uint32_t* a,
                                        const uint32_t* b) {
    asm volatile("mma.sync.aligned.m16n8k16.row.col.f32.f16.f16.f32 "
        "{%0,%1,%2,%3}, {%4,%5,%6,%7}, {%8,%9}, {%0,%1,%2,%3};"
        : "+f"(d[0]), "+f"(d[1]), "+f"(d[2]), "+f"(d[3])
        : "r"(a[0]), "r"(a[1]), "r"(a[2]), "r"(a[3]), "r"(b[0]), "r"(b[1]));
}
__device__ __forceinline__ void cpa16(uint32_t d, const void* s) {
    asm volatile("cp.async.cg.shared.global [%0], [%1], 16;"
                 :: "r"(d), "l"(s) : "memory");
}
#define CPA_COMMIT() asm volatile("cp.async.commit_group;" ::: "memory")
#define CPA_WAIT0()  asm volatile("cp.async.wait_group 0;" ::: "memory")

__device__ __forceinline__ uint32_t pkh(__half a, __half b) {
    __half2 t = __halves2half2(a, b);
    return *reinterpret_cast<uint32_t*>(&t);
}

// ---- convM smem geometry (dynamic): A 2-stage + B halo hi/lo ----
#define PITCH 144
#define ASTG  18432
#define OB_H  36864
#define OB_L  111744
#define OSS   186624
#define OSH   187648
#define CM_DYN 188672

// ---- convO smem geometry (dynamic) ----
#define ASTG_O 4608
#define OB_H_O 9216
#define OB_L_O 84096
#define OSS_O  158976
#define OSH_O  160000
#define CO_DYN 161024

// ============================================================
// wprep: w[co][ci][tap] fp32 -> WF[tap][co][ci] fp16
// ============================================================
__global__ __launch_bounds__(256) void wprep(
    const float* __restrict__ w, __half* __restrict__ WF)
{
    int idx = blockIdx.x * 256 + threadIdx.x;
    if (idx >= WELEM) return;
    int tap = idx / 65536;
    int r   = idx - tap * 65536;
    int co  = r >> 8, ci = r & 255;
    WF[idx] = __float2half_rn(w[co * 2304 + ci * 9 + tap]);
}

// ============================================================
// woprep: head weights -> [set][tap][row32][ci] fp16
// ============================================================
__global__ __launch_bounds__(256) void woprep(
    const float* __restrict__ clsw, const float* __restrict__ regw,
    const float* __restrict__ ctrw, __half* __restrict__ WOF)
{
    int idx = blockIdx.x * 256 + threadIdx.x;
    if (idx >= 2 * WOELEM) return;
    int set = idx / WOELEM;
    int r   = idx - set * WOELEM;
    int tap = r / 8192;
    int r2  = r - tap * 8192;
    int row = r2 >> 8, ci = r2 & 255;
    float v = 0.0f;
    if (set == 0) {
        if (row < 20) v = clsw[(row * 256 + ci) * 9 + tap];
    } else {
        if (row < 4)       v = regw[(row * 256 + ci) * 9 + tap];
        else if (row == 4) v = ctrw[ci * 9 + tap];
    }
    WOF[idx] = __float2half_rn(v);
}

// ============================================================
// zeropad: zero border pixels of one level's padded NHWC fp32 buffer
// ============================================================
__global__ __launch_bounds__(256) void zeropad(
    float4* __restrict__ buf, int H, int W, int Wp, int HpWp)
{
    int bc = 2 * Wp + 2 * H;
    int total = NB * bc * 64;
    int idx = blockIdx.x * 256 + threadIdx.x;
    if (idx >= total) return;
    int ch4 = idx & 63;
    int r   = idx >> 6;
    int n   = r / bc;
    int b   = r - n * bc;
    int py, px;
    if (b < Wp)           { py = 0;     px = b; }
    else if (b < 2 * Wp)  { py = H + 1; px = b - Wp; }
    else {
        int rr = b - 2 * Wp;
        py = 1 + (rr >> 1);
        px = (rr & 1) ? (W + 1) : 0;
    }
    buf[((size_t)n * HpWp + (size_t)py * Wp + px) * 64 + ch4] =
        make_float4(0.f, 0.f, 0.f, 0.f);
}

// ============================================================
// featprep: NCHW fp32 -> padded NHWC fp32 (32x32 smem transpose)
// ============================================================
__global__ __launch_bounds__(1024) void featprep(
    const float* __restrict__ feat, float* __restrict__ XF,
    int H, int W, int Wp, int HpWp)
{
    __shared__ float tile[32][33];
    int xt = blockIdx.x, y = blockIdx.y;
    int n  = blockIdx.z >> 3, ct = blockIdx.z & 7;
    int tx = threadIdx.x, ty = threadIdx.y;

    tile[ty][tx] = feat[(((size_t)n * CC + ct * 32 + ty) * H + y) * W + xt * 32 + tx];
    __syncthreads();

    int c = ct * 32 + tx;
    int x = xt * 32 + ty;
    XF[((size_t)n * HpWp + (size_t)(y + 1) * Wp + (x + 1)) * CC + c] = tile[tx][ty];
}

// ============================================================
// convM: warp-mma 3x3 conv over ALL levels in one launch.
// grid (TOTPT, 1, 32): x = global px-tile (level by segment lookup),
// z = tower*16 + n*2 + cohalf. 512 threads = 16 warps (4m x 4n).
// twoTerm: 1 = act hi+lo (2 MMAs/product), 0 = act hi only (1 MMA).
// GN fused on load when ssv != null (interior pixels only).
// ============================================================
__global__ __launch_bounds__(512) void convM(
    const float4* __restrict__ inC, const float4* __restrict__ inR,
    const uint4* __restrict__ WFb, int layer, int twoTerm,
    const float* __restrict__ clscb, const float* __restrict__ regcb,
    const float* __restrict__ ssv, const float* __restrict__ shv,
    float* __restrict__ outC, float* __restrict__ outR,
    float2* __restrict__ part)
{
    extern __shared__ char smem[];
    const uint32_t sb = smem_u32(smem);

    const int bx = blockIdx.x;
    const int L = (bx >= cSegA[2]) ? 2 : (bx >= cSegA[1]) ? 1 : 0;
    const int tile = bx - cSegA[L];
    const int H = cH[L], W = cW[L], Wp = cWp[L], lgW = cLgW[L];
    const int HW = cHW[L], HpWp = cHpWp[L];
    const size_t lvlpix = (size_t)cXpix[L];

    const int tid = threadIdx.x, wid = tid >> 5, lane = tid & 31;
    const int warp_m = wid >> 2, warp_n = wid & 3;
    const int p0 = tile * 256;
    const int z = blockIdx.z;
    const int tower = z >> 4, zz = z & 15;
    const int n = zz >> 1, co0 = (zz & 1) * 128;
    const size_t nbase = lvlpix + (size_t)n * HpWp;

    const float4* in = tower ? inR : inC;
    float* Y = tower ? outR : outC;
    const uint4* WFl = WFb + (size_t)(tower * 2 + layer) * (WELEM / 8);
    const float* bias = (tower ? regcb : clscb) + layer * CC;

    const int R  = 256 >> lgW;
    const int BR = (R + 2) * Wp;
    const int prow0 = p0 >> lgW;
    const int pstart = prow0 * Wp;

    float* sS = (float*)(smem + OSS);
    float* sHh = (float*)(smem + OSH);
    if (ssv && tid < 256) {
        int so = (L * 2 + tower) * 2048 + n * 256 + tid;
        sS[tid]  = ssv[so];
        sHh[tid] = shv[so];
    }
    __syncthreads();

    float acc[2][8][4];
#pragma unroll
    for (int mt = 0; mt < 2; mt++)
#pragma unroll
        for (int nt = 0; nt < 8; nt++)
#pragma unroll
            for (int i = 0; i < 4; i++) acc[mt][nt][i] = 0.0f;

    const int lrow = lane & 7;
    const int matr = (lane >> 3) & 1;
    const int matc = lane >> 4;

    int rnp[4];
#pragma unroll
    for (int np = 0; np < 4; np++)
        rnp[np] = warp_n * 64 + np * 16 + matc * 8 + lrow;

#pragma unroll 1
    for (int kc = 0; kc < 4; kc++) {
        // ---- B halo fill: fp32 -> (GN+ReLU interior-only) -> fp16 ----
        {
            const int lim = BR * 16;
#pragma unroll 1
            for (int t0 = tid; t0 < lim; t0 += 2048) {
                float4 xa[4];
#pragma unroll
                for (int u = 0; u < 4; u++) {
                    int t = t0 + u * 512;
                    xa[u] = make_float4(0.f, 0.f, 0.f, 0.f);
                    if (t < lim) {
                        int hr = t >> 4, v = t & 15;
                        int gpix = pstart + hr;
                        if (gpix < HpWp)
                            xa[u] = in[(size_t)(nbase + gpix) * 64 + (kc << 4) + v];
                    }
                }
#pragma unroll
                for (int u = 0; u < 4; u++) {
                    int t = t0 + u * 512;
                    if (t >= lim) break;
                    int hr = t >> 4, v = t & 15;
                    float4 x = xa[u];
                    if (ssv) {
                        int hd = hr / Wp;
                        int gx = hr - hd * Wp;
                        int gy = prow0 + hd;
                        if (gy >= 1 && gy <= H && gx >= 1 && gx <= W) {
                            int c = (kc << 6) + (v << 2);
                            x.x = fmaxf(fmaf(x.x, sS[c+0], sHh[c+0]), 0.f);
                            x.y = fmaxf(fmaf(x.y, sS[c+1], sHh[c+1]), 0.f);
                            x.z = fmaxf(fmaf(x.z, sS[c+2], sHh[c+2]), 0.f);
                            x.w = fmaxf(fmaf(x.w, sS[c+3], sHh[c+3]), 0.f);
                        } else {
                            x = make_float4(0.f, 0.f, 0.f, 0.f);
                        }
                    }
                    __half h0 = __float2half_rn(x.x);
                    __half h1 = __float2half_rn(x.y);
                    __half h2 = __float2half_rn(x.z);
                    __half h3 = __float2half_rn(x.w);
                    uint32_t base = (uint32_t)(hr * PITCH + (v << 3));
                    *reinterpret_cast<uint2*>(smem + OB_H + base) =
                        make_uint2(pkh(h0, h1), pkh(h2, h3));
                    if (twoTerm) {
                        __half l0 = __float2half_rn(x.x - __half2float(h0));
                        __half l1 = __float2half_rn(x.y - __half2float(h1));
                        __half l2 = __float2half_rn(x.z - __half2float(h2));
                        __half l3 = __float2half_rn(x.w - __half2float(h3));
                        *reinterpret_cast<uint2*>(smem + OB_L + base) =
                            make_uint2(pkh(l0, l1), pkh(l2, l3));
                    }
                }
            }
        }
        // ---- A tap 0 prefetch (stage 0) ----
#pragma unroll
        for (int t = tid; t < 1024; t += 512) {
            int row = t >> 3, v = t & 7;
            uint32_t d = sb + (uint32_t)(row * PITCH + v * 16);
            size_t g = (size_t)(co0 + row) * 32 + kc * 8 + v;
            cpa16(d, WFl + g);
        }
        CPA_COMMIT();
        CPA_WAIT0();
        __syncthreads();

#pragma unroll 1
        for (int tap = 0; tap < 9; tap++) {
            if (tap < 8) {
                const uint32_t abase = sb + (uint32_t)(((tap + 1) & 1) * ASTG);
#pragma unroll
                for (int t = tid; t < 1024; t += 512) {
                    int row = t >> 3, v = t & 7;
                    uint32_t d = abase + (uint32_t)(row * PITCH + v * 16);
                    size_t g = (size_t)(tap + 1) * 8192 + (size_t)(co0 + row) * 32 + kc * 8 + v;
                    cpa16(d, WFl + g);
                }
                CPA_COMMIT();
            }

            const int ky = tap / 3, kx = tap - ky * 3;
            uint32_t bOff[4];
#pragma unroll
            for (int np = 0; np < 4; np++) {
                int r = rnp[np];
                int sr = ((r >> lgW) + ky) * Wp + (r & (W - 1)) + kx;
                bOff[np] = (uint32_t)(sr * PITCH);
            }
            const uint32_t sAH = sb + (uint32_t)((tap & 1) * ASTG);
            const uint32_t sBH = sb + OB_H;
            const uint32_t sBL = sb + OB_L;
            const int m0 = warp_m * 32;

#pragma unroll
            for (int ks = 0; ks < 4; ks++) {
                uint32_t ah[2][4], bb[4][4];
#pragma unroll
                for (int mt = 0; mt < 2; mt++) {
                    uint32_t off = (uint32_t)((m0 + mt * 16 + matr * 8 + lrow) * PITCH
                                              + (ks * 16 + matc * 8) * 2);
                    ldsm_x4(ah[mt][0], ah[mt][1], ah[mt][2], ah[mt][3], sAH + off);
                }
                const uint32_t kb = (uint32_t)((ks * 16 + matr * 8) * 2);
#pragma unroll
                for (int np = 0; np < 4; np++)
                    ldsm_x4(bb[np][0], bb[np][1], bb[np][2], bb[np][3],
                            sBH + bOff[np] + kb);
#pragma unroll
                for (int mt = 0; mt < 2; mt++)
#pragma unroll
                    for (int np = 0; np < 4; np++) {
                        mma_f16(acc[mt][np * 2 + 0], ah[mt], &bb[np][0]);
                        mma_f16(acc[mt][np * 2 + 1], ah[mt], &bb[np][2]);
                    }
                if (twoTerm) {
#pragma unroll
                    for (int np = 0; np < 4; np++)
                        ldsm_x4(bb[np][0], bb[np][1], bb[np][2], bb[np][3],
                                sBL + bOff[np] + kb);
#pragma unroll
                    for (int mt = 0; mt < 2; mt++)
#pragma unroll
                        for (int np = 0; np < 4; np++) {
                            mma_f16(acc[mt][np * 2 + 0], ah[mt], &bb[np][0]);
                            mma_f16(acc[mt][np * 2 + 1], ah[mt], &bb[np][2]);
                        }
                }
            }
            if (tap < 8) CPA_WAIT0();
            __syncthreads();
        }
    }

    // ---- epilogue: bias, store fp32 padded NHWC, deterministic GN partials ----
    __shared__ float redS[16][2], redQ[16][2];
    const int qrow = lane >> 2, qcol = (lane & 3) * 2;
    float sg[2] = {0.0f, 0.0f}, qg[2] = {0.0f, 0.0f};

#pragma unroll
    for (int mt = 0; mt < 2; mt++) {
#pragma unroll
        for (int h8 = 0; h8 < 2; h8++) {
            const int col_ = co0 + warp_m * 32 + mt * 16 + qrow + h8 * 8;
            const float b = bias[col_];
#pragma unroll
            for (int nt = 0; nt < 8; nt++) {
#pragma unroll
                for (int cc2 = 0; cc2 < 2; cc2++) {
                    int p = p0 + warp_n * 64 + nt * 8 + qcol + cc2;
                    float v = acc[mt][nt][h8 * 2 + cc2] + b;
                    if (p < HW) {
                        int x = p & (W - 1), y = p >> lgW;
                        Y[(nbase + (size_t)(y + 1) * Wp + (x + 1)) * CC + col_] = v;
                        sg[mt] += v;
                        qg[mt] += v * v;
                    }
                }
            }
        }
    }
#pragma unroll
    for (int off = 16; off > 0; off >>= 1) {
#pragma unroll
        for (int mt = 0; mt < 2; mt++) {
            sg[mt] += __shfl_down_sync(0xffffffffu, sg[mt], off);
            qg[mt] += __shfl_down_sync(0xffffffffu, qg[mt], off);
        }
    }
    if (lane == 0) {
        redS[wid][0] = sg[0]; redS[wid][1] = sg[1];
        redQ[wid][0] = qg[0]; redQ[wid][1] = qg[1];
    }
    __syncthreads();
    if (tid < 8) {
        int wm = tid >> 1, mt = tid & 1;
        float S = 0.0f, Q = 0.0f;
#pragma unroll
        for (int wn = 0; wn < 4; wn++) {
            S += redS[wm * 4 + wn][mt];
            Q += redQ[wm * 4 + wn][mt];
        }
        size_t pidx = (size_t)z * TOTPT + bx;
        part[pidx * 8 + tid] = make_float2(S, Q);
    }
}

// ============================================================
// gn_finalize2: 768 blocks = (level, tower, n, group), all levels.
// Emits per-channel scale = rstd*gamma, shift = beta - mean*scale.
// ============================================================
__global__ __launch_bounds__(256) void gn_finalize2(
    const float2* __restrict__ part,
    const float* __restrict__ clsg, const float* __restrict__ clsbt,
    const float* __restrict__ regg, const float* __restrict__ regbt,
    float* __restrict__ oss, float* __restrict__ osh)
{
    const int b = blockIdx.x;
    const int L = b >> 8;
    const int r = b & 255;
    const int tower = r >> 7;
    const int rr = r & 127;
    const int n = rr >> 4, grp = rr & 15;
    const int half = grp >> 3, i = grp & 7;
    const int z = tower * 16 + n * 2 + half;
    const int seg = cSegA[L], PT = cPT[L];

    float S = 0.0f, Q = 0.0f;
    for (int t = threadIdx.x; t < PT; t += 256) {
        float2 p = part[(size_t)(z * TOTPT + seg + t) * 8 + i];
        S += p.x; Q += p.y;
    }
    __shared__ float sS[256], sQ[256];
    sS[threadIdx.x] = S; sQ[threadIdx.x] = Q;
    __syncthreads();
    for (int off = 128; off > 0; off >>= 1) {
        if (threadIdx.x < off) {
            sS[threadIdx.x] += sS[threadIdx.x + off];
            sQ[threadIdx.x] += sQ[threadIdx.x + off];
        }
        __syncthreads();
    }
    if (threadIdx.x < 16) {
        float cnt  = (float)(GSIZE * cHW[L]);
        float mean = sS[0] / cnt;
        float var  = sQ[0] / cnt - mean * mean;
        float rstd = rsqrtf(var + GN_EPS);
        int c = grp * 16 + threadIdx.x;
        float gam = tower ? regg[c] : clsg[c];
        float bet = tower ? regbt[c] : clsbt[c];
        float scale = rstd * gam;
        int so = (L * 2 + tower) * 2048 + n * 256 + c;
        oss[so] = scale;
        osh[so] = bet - mean * scale;
    }
}

// ============================================================
// convO: head convs over ALL levels. grid (TOTPT, 1, 16):
// z = n*2 + mode. 256 threads = 8 warps, 32co x 256px CTA.
// ============================================================
__global__ __launch_bounds__(256) void convO(
    const float4* __restrict__ inC, const float4* __restrict__ inR,
    const uint4* __restrict__ WOFb,
    const float* __restrict__ ssv, const float* __restrict__ shv,
    const float* __restrict__ clsb, const float* __restrict__ regb,
    const float* __restrict__ ctrb, float* __restrict__ out)
{
    extern __shared__ char smem[];
    const uint32_t sb = smem_u32(smem);

    const int bx = blockIdx.x;
    const int L = (bx >= cSegA[2]) ? 2 : (bx >= cSegA[1]) ? 1 : 0;
    const int tile = bx - cSegA[L];
    const int H = cH[L], W = cW[L], Wp = cWp[L], lgW = cLgW[L];
    const int HW = cHW[L], HpWp = cHpWp[L];
    const int poff = cPoff[L];
    const size_t lvlpix = (size_t)cXpix[L];

    const int tid = threadIdx.x, wid = tid >> 5, lane = tid & 31;
    const int p0 = tile * 256;
    const int z = blockIdx.z;
    const int n = z >> 1, mode = z & 1;
    const size_t nbase = lvlpix + (size_t)n * HpWp;

    const float4* in = mode ? inR : inC;
    const uint4* WFl = WOFb + (size_t)mode * (WOELEM / 8);

    const int R  = 256 >> lgW;
    const int BR = (R + 2) * Wp;
    const int prow0 = p0 >> lgW;
    const int pstart = prow0 * Wp;

    float* sS = (float*)(smem + OSS_O);
    float* sHh = (float*)(smem + OSH_O);
    if (tid < 256) {
        int so = (L * 2 + mode) * 2048 + n * 256 + tid;
        sS[tid]  = ssv[so];
        sHh[tid] = shv[so];
    }
    __syncthreads();

    float acc[2][4][4];
#pragma unroll
    for (int mt = 0; mt < 2; mt++)
#pragma unroll
        for (int nt = 0; nt < 4; nt++)
#pragma unroll
            for (int i = 0; i < 4; i++) acc[mt][nt][i] = 0.0f;

    const int lrow = lane & 7;
    const int matr = (lane >> 3) & 1;
    const int matc = lane >> 4;

    int rnp[2];
#pragma unroll
    for (int np = 0; np < 2; np++)
        rnp[np] = wid * 32 + np * 16 + matc * 8 + lrow;

#pragma unroll 1
    for (int kc = 0; kc < 4; kc++) {
        // ---- B halo fill (fp32 + interior-only GN + fp16 split) ----
        {
            const int lim = BR * 16;
#pragma unroll 1
            for (int t0 = tid; t0 < lim; t0 += 1024) {
                float4 xa[4];
#pragma unroll
                for (int u = 0; u < 4; u++) {
                    int t = t0 + u * 256;
                    xa[u] = make_float4(0.f, 0.f, 0.f, 0.f);
                    if (t < lim) {
                        int hr = t >> 4, v = t & 15;
                        int gpix = pstart + hr;
                        if (gpix < HpWp)
                            xa[u] = in[(size_t)(nbase + gpix) * 64 + (kc << 4) + v];
                    }
                }
#pragma unroll
                for (int u = 0; u < 4; u++) {
                    int t = t0 + u * 256;
                    if (t >= lim) break;
                    int hr = t >> 4, v = t & 15;
                    float4 x = xa[u];
                    int hd = hr / Wp;
                    int gx = hr - hd * Wp;
                    int gy = prow0 + hd;
                    if (gy >= 1 && gy <= H && gx >= 1 && gx <= W) {
                        int c = (kc << 6) + (v << 2);
                        x.x = fmaxf(fmaf(x.x, sS[c+0], sHh[c+0]), 0.f);
                        x.y = fmaxf(fmaf(x.y, sS[c+1], sHh[c+1]), 0.f);
                        x.z = fmaxf(fmaf(x.z, sS[c+2], sHh[c+2]), 0.f);
                        x.w = fmaxf(fmaf(x.w, sS[c+3], sHh[c+3]), 0.f);
                    } else {
                        x = make_float4(0.f, 0.f, 0.f, 0.f);
                    }
                    __half h0 = __float2half_rn(x.x);
                    __half h1 = __float2half_rn(x.y);
                    __half h2 = __float2half_rn(x.z);
                    __half h3 = __float2half_rn(x.w);
                    __half l0 = __float2half_rn(x.x - __half2float(h0));
                    __half l1 = __float2half_rn(x.y - __half2float(h1));
                    __half l2 = __float2half_rn(x.z - __half2float(h2));
                    __half l3 = __float2half_rn(x.w - __half2float(h3));
                    uint32_t base = (uint32_t)(hr * PITCH + (v << 3));
                    *reinterpret_cast<uint2*>(smem + OB_H_O + base) =
                        make_uint2(pkh(h0, h1), pkh(h2, h3));
                    *reinterpret_cast<uint2*>(smem + OB_L_O + base) =
                        make_uint2(pkh(l0, l1), pkh(l2, l3));
                }
            }
        }
        // ---- A tap 0 prefetch ----
        {
            int row = tid >> 3, v = tid & 7;
            uint32_t d = sb + (uint32_t)(row * PITCH + v * 16);
            size_t g = (size_t)row * 32 + kc * 8 + v;
            cpa16(d, WFl + g);
        }
        CPA_COMMIT();
        CPA_WAIT0();
        __syncthreads();

#pragma unroll 1
        for (int tap = 0; tap < 9; tap++) {
            if (tap < 8) {
                const uint32_t abase = sb + (uint32_t)(((tap + 1) & 1) * ASTG_O);
                int row = tid >> 3, v = tid & 7;
                uint32_t d = abase + (uint32_t)(row * PITCH + v * 16);
                size_t g = (size_t)(tap + 1) * 1024 + (size_t)row * 32 + kc * 8 + v;
                cpa16(d, WFl + g);
                CPA_COMMIT();
            }

            const int ky = tap / 3, kx = tap - ky * 3;
            uint32_t bOff[2];
#pragma unroll
            for (int np = 0; np < 2; np++) {
                int r = rnp[np];
                int sr = ((r >> lgW) + ky) * Wp + (r & (W - 1)) + kx;
                bOff[np] = (uint32_t)(sr * PITCH);
            }
            const uint32_t sAH = sb + (uint32_t)((tap & 1) * ASTG_O);
            const uint32_t sBH = sb + OB_H_O;
            const uint32_t sBL = sb + OB_L_O;

#pragma unroll
            for (int ks = 0; ks < 4; ks++) {
                uint32_t ah[2][4], bb[2][4];
#pragma unroll
                for (int mt = 0; mt < 2; mt++) {
                    uint32_t off = (uint32_t)((mt * 16 + matr * 8 + lrow) * PITCH
                                              + (ks * 16 + matc * 8) * 2);
                    ldsm_x4(ah[mt][0], ah[mt][1], ah[mt][2], ah[mt][3], sAH + off);
                }
                const uint32_t kb = (uint32_t)((ks * 16 + matr * 8) * 2);
#pragma unroll
                for (int np = 0; np < 2; np++)
                    ldsm_x4(bb[np][0], bb[np][1], bb[np][2], bb[np][3],
                            sBH + bOff[np] + kb);
#pragma unroll
                for (int mt = 0; mt < 2; mt++)
#pragma unroll
                    for (int np = 0; np < 2; np++) {
                        mma_f16(acc[mt][np * 2 + 0], ah[mt], &bb[np][0]);
                        mma_f16(acc[mt][np * 2 + 1], ah[mt], &bb[np][2]);
                    }
#pragma unroll
                for (int np = 0; np < 2; np++)
                    ldsm_x4(bb[np][0], bb[np][1], bb[np][2], bb[np][3],
                            sBL + bOff[np] + kb);
#pragma unroll
                for (int mt = 0; mt < 2; mt++)
#pragma unroll
                    for (int np = 0; np < 2; np++) {
                        mma_f16(acc[mt][np * 2 + 0], ah[mt], &bb[np][0]);
                        mma_f16(acc[mt][np * 2 + 1], ah[mt], &bb[np][2]);
                    }
            }
            if (tap < 8) CPA_WAIT0();
            __syncthreads();
        }
    }

    // ---- epilogue: scatter into concat output layout ----
    const int qrow = lane >> 2, qcol = (lane & 3) * 2;
#pragma unroll
    for (int mt = 0; mt < 2; mt++) {
#pragma unroll
        for (int h8 = 0; h8 < 2; h8++) {
            const int row = mt * 16 + h8 * 8 + qrow;
#pragma unroll
            for (int nt = 0; nt < 4; nt++) {
#pragma unroll
                for (int cc2 = 0; cc2 < 2; cc2++) {
                    int p = p0 + wid * 32 + nt * 8 + qcol + cc2;
                    if (p >= HW) continue;
                    float v = acc[mt][nt][h8 * 2 + cc2];
                    int x = p & (W - 1), y = p >> lgW;
                    size_t gp = (size_t)n * TOTHW + poff + (size_t)y * W + x;
                    if (mode == 0) {
                        if (row < 20) out[CLSBASE + gp * 20 + row] = v + clsb[row];
                    } else {
                        if (row < 4)
                            out[REGBASE + gp * 4 + row] = fmaxf(v + regb[row], 0.0f);
                        else if (row == 4)
                            out[CTRBASE + gp] = v + ctrb[0];
                    }
                }
            }
        }
    }
}

// ============================================================
// host launcher
// ============================================================
extern "C" void kernel_launch(void* const* d_in, const int* in_sizes, int n_in,
                              void* d_out, int out_size)
{
    (void)in_sizes; (void)n_in; (void)out_size;

    const float* feat[3] = { (const float*)d_in[0], (const float*)d_in[1],
                             (const float*)d_in[2] };
    const float* cls_conv_w = (const float*)d_in[3];
    const float* cls_conv_b = (const float*)d_in[4];
    const float* cls_gn_g   = (const float*)d_in[5];
    const float* cls_gn_b   = (const float*)d_in[6];
    const float* cls_out_w  = (const float*)d_in[7];
    const float* cls_out_b  = (const float*)d_in[8];
    const float* reg_conv_w = (const float*)d_in[9];
    const float* reg_conv_b = (const float*)d_in[10];
    const float* reg_gn_g   = (const float*)d_in[11];
    const float* reg_gn_b   = (const float*)d_in[12];
    const float* reg_out_w  = (const float*)d_in[13];
    const float* reg_out_b  = (const float*)d_in[14];
    const float* ctr_w      = (const float*)d_in[15];
    const float* ctr_b      = (const float*)d_in[16];

    float* out = (float*)d_out;

    float *XF, *Y0, *Y1, *Y2, *Y3, *ssv, *shv;
    __half *WF, *WOF;
    float2* part;
    cudaGetSymbolAddress((void**)&XF, g_XF);
    {
        float* ybase;
        cudaGetSymbolAddress((void**)&ybase, g_Y);
        Y0 = ybase;
        Y1 = ybase + (size_t)XCAP2;
        Y2 = ybase + 2 * (size_t)XCAP2;
        Y3 = ybase + 3 * (size_t)XCAP2;
    }
    cudaGetSymbolAddress((void**)&WF, g_WF);
    cudaGetSymbolAddress((void**)&WOF, g_WOF);
    cudaGetSymbolAddress((void**)&ssv, g_ssv);
    cudaGetSymbolAddress((void**)&shv, g_shv);
    cudaGetSymbolAddress((void**)&part, g_part);

    cudaFuncSetAttribute(convM, cudaFuncAttributeMaxDynamicSharedMemorySize, CM_DYN);
    cudaFuncSetAttribute(convO, cudaFuncAttributeMaxDynamicSharedMemorySize, CO_DYN);

    const int TGRID = (WELEM + 255) / 256;
    wprep<<<TGRID, 256>>>(cls_conv_w,          WF + 0 * (size_t)WELEM);
    wprep<<<TGRID, 256>>>(cls_conv_w + WELEM,  WF + 1 * (size_t)WELEM);
    wprep<<<TGRID, 256>>>(reg_conv_w,          WF + 2 * (size_t)WELEM);
    wprep<<<TGRID, 256>>>(reg_conv_w + WELEM,  WF + 3 * (size_t)WELEM);
    woprep<<<(2 * WOELEM + 255) / 256, 256>>>(cls_out_w, reg_out_w, ctr_w, WOF);

    const int hH[3] = {100, 50, 25};
    const int hW[3] = {128, 64, 32};
    const int hWp[3] = {130, 66, 34};
    const int hHpWp[3] = {13260, 3432, 918};
    const size_t hXoff[3] = {0, 106080ull * 256, 133536ull * 256};

    for (int L = 0; L < 3; L++) {
        const int H = hH[L], W = hW[L], Wp = hWp[L], HpWp = hHpWp[L];
        const int zpN = (NB * (2 * Wp + 2 * H) * 64 + 255) / 256;
        zeropad<<<zpN, 256>>>((float4*)(XF + hXoff[L]), H, W, Wp, HpWp);
        dim3 fgrid(W / 32, H, NB * 8);
        featprep<<<fgrid, dim3(32, 32)>>>(feat[L], XF + hXoff[L], H, W, Wp, HpWp);
    }

    dim3 cgrid(TOTPT, 1, 32);
    dim3 ogrid(TOTPT, 1, 16);

    // conv layer 1, all levels, both towers (single-term: act hi only)
    convM<<<cgrid, 512, CM_DYN>>>(
        (const float4*)XF, (const float4*)XF,
        (const uint4*)WF, 0, /*twoTerm=*/0,
        cls_conv_b, reg_conv_b, nullptr, nullptr,
        Y0, Y1, part);
    gn_finalize2<<<768, 256>>>(part,
        cls_gn_g, cls_gn_b, reg_gn_g, reg_gn_b, ssv, shv);

    // conv layer 2, all levels, both towers (two-term), GN fused on load
    convM<<<cgrid, 512, CM_DYN>>>(
        (const float4*)Y0, (const float4*)Y1,
        (const uint4*)WF, 1, /*twoTerm=*/1,
        cls_conv_b, reg_conv_b, ssv, shv,
        Y2, Y3, part);
    gn_finalize2<<<768, 256>>>(part,
        cls_gn_g + CC, cls_gn_b + CC, reg_gn_g + CC, reg_gn_b + CC,
        ssv + 12288, shv + 12288);

    // heads, all levels, both sets, GN of layer 2 fused on load
    convO<<<ogrid, 256, CO_DYN>>>(
        (const float4*)Y2, (const float4*)Y3,
        (const uint4*)WOF,
        ssv + 12288, shv + 12288,
        cls_out_b, reg_out_b, ctr_b, out);
}

// round 13
// speedup vs baseline: 13.2285x; 1.1706x over previous
#include <cuda_runtime.h>
#include <cuda_fp16.h>
#include <math.h>
#include <stdint.h>

// ---------------- problem constants ----------------
#define NB 8
#define CC 256
#define NGROUPS 16
#define GSIZE 16
#define GN_EPS 1e-5f

#define TOTHW   16800
#define CLSBASE 0
#define REGBASE 2688000
#define CTRBASE 3225600

#define WELEM  (CC * CC * 9)      // 589824 fp16 per tower layer
#define WOELEM (9 * 32 * 256)     // 73728 per head set

#define TOTPT 67                  // 50 + 13 + 4 px-tiles across levels
#define XCAP2 36070000            // all-level fp32 padded NHWC (36,065,280 used)

// per-level compile-time tables
__constant__ int cH[3]    = {100, 50, 25};
__constant__ int cW[3]    = {128, 64, 32};
__constant__ int cLgW[3]  = {7, 6, 5};
__constant__ int cWp[3]   = {130, 66, 34};
__constant__ int cHpWp[3] = {13260, 3432, 918};
__constant__ int cHW[3]   = {12800, 3200, 800};
__constant__ int cPT[3]   = {50, 13, 4};
__constant__ int cSegA[3] = {0, 50, 63};
__constant__ int cPoff[3] = {0, 12800, 16000};
__constant__ unsigned long long cXpix[3] = {0ull, 106080ull, 133536ull};

// scratch (device globals; zero-initialized, no runtime allocation)
__device__ __align__(16) float g_XF[XCAP2];
__device__ __align__(16) float g_Y[4][XCAP2];
__device__ __align__(16) __half g_WF[4 * WELEM];
__device__ __align__(16) __half g_WOF[2 * WOELEM];
__device__ float  g_ssv[2 * 3 * 2 * 2048];   // [conv][level][tower][n*256+c]
__device__ float  g_shv[2 * 3 * 2 * 2048];
__device__ float2 g_part[32 * TOTPT * 8];

// ---------------- PTX helpers (arch-agnostic sm_80+) ----------------
__device__ __forceinline__ uint32_t smem_u32(const void* p) {
    uint32_t a;
    asm("{ .reg .u64 t; cvta.to.shared.u64 t, %1; cvt.u32.u64 %0, t; }"
        : "=r"(a) : "l"(p));
    return a;
}
__device__ __forceinline__ void ldsm_x4(uint32_t& r0, uint32_t& r1,
                                        uint32_t& r2, uint32_t& r3, uint32_t a) {
    asm volatile("ldmatrix.sync.aligned.m8n8.x4.shared.b16 {%0,%1,%2,%3}, [%4];"
        : "=r"(r0), "=r"(r1), "=r"(r2), "=r"(r3) : "r"(a));
}
__device__ __forceinline__ void mma_f16(float* d, const uint32_t* a,
                                        const uint32_t* b) {
    asm volatile("mma.sync.aligned.m16n8k16.row.col.f32.f16.f16.f32 "
        "{%0,%1,%2,%3}, {%4,%5,%6,%7}, {%8,%9}, {%0,%1,%2,%3};"
        : "+f"(d[0]), "+f"(d[1]), "+f"(d[2]), "+f"(d[3])
        : "r"(a[0]), "r"(a[1]), "r"(a[2]), "r"(a[3]), "r"(b[0]), "r"(b[1]));
}
__device__ __forceinline__ void cpa16(uint32_t d, const void* s) {
    asm volatile("cp.async.cg.shared.global [%0], [%1], 16;"
                 :: "r"(d), "l"(s) : "memory");
}
#define CPA_COMMIT() asm volatile("cp.async.commit_group;" ::: "memory")
#define CPA_WAIT0()  asm volatile("cp.async.wait_group 0;" ::: "memory")

__device__ __forceinline__ uint32_t pkh(__half a, __half b) {
    __half2 t = __halves2half2(a, b);
    return *reinterpret_cast<uint32_t*>(&t);
}

// ---- convM smem geometry (dynamic): A 2-stage + B halo (hi only) ----
#define PITCH 144
#define ASTG  18432
#define OB_H  36864
#define OSS   111744                 // OB_H + 520*144
#define OSH   112768
#define CM_DYN 113792

// ---- convO smem geometry (dynamic): B halo hi/lo ----
#define ASTG_O 4608
#define OB_H_O 9216
#define OB_L_O 84096
#define OSS_O  158976
#define OSH_O  160000
#define CO_DYN 161024

// ============================================================
// wprep: all 4 tower layers in one launch.
// w[co][ci][tap] fp32 -> WF[l][tap][co][ci] fp16
// ============================================================
__global__ __launch_bounds__(256) void wprep(
    const float* __restrict__ clsw, const float* __restrict__ regw,
    __half* __restrict__ WF)
{
    int idx = blockIdx.x * 256 + threadIdx.x;
    if (idx >= 4 * WELEM) return;
    int layer = idx / WELEM;
    int r0 = idx - layer * WELEM;
    int tap = r0 / 65536;
    int r   = r0 - tap * 65536;
    int co  = r >> 8, ci = r & 255;
    const float* src = (layer < 2 ? clsw : regw) + (size_t)(layer & 1) * WELEM;
    WF[idx] = __float2half_rn(src[co * 2304 + ci * 9 + tap]);
}

// ============================================================
// woprep: head weights -> [set][tap][row32][ci] fp16
// ============================================================
__global__ __launch_bounds__(256) void woprep(
    const float* __restrict__ clsw, const float* __restrict__ regw,
    const float* __restrict__ ctrw, __half* __restrict__ WOF)
{
    int idx = blockIdx.x * 256 + threadIdx.x;
    if (idx >= 2 * WOELEM) return;
    int set = idx / WOELEM;
    int r   = idx - set * WOELEM;
    int tap = r / 8192;
    int r2  = r - tap * 8192;
    int row = r2 >> 8, ci = r2 & 255;
    float v = 0.0f;
    if (set == 0) {
        if (row < 20) v = clsw[(row * 256 + ci) * 9 + tap];
    } else {
        if (row < 4)       v = regw[(row * 256 + ci) * 9 + tap];
        else if (row == 4) v = ctrw[ci * 9 + tap];
    }
    WOF[idx] = __float2half_rn(v);
}

// ============================================================
// zeropad: zero border pixels of one level's padded NHWC fp32 buffer
// ============================================================
__global__ __launch_bounds__(256) void zeropad(
    float4* __restrict__ buf, int H, int W, int Wp, int HpWp)
{
    int bc = 2 * Wp + 2 * H;
    int total = NB * bc * 64;
    int idx = blockIdx.x * 256 + threadIdx.x;
    if (idx >= total) return;
    int ch4 = idx & 63;
    int r   = idx >> 6;
    int n   = r / bc;
    int b   = r - n * bc;
    int py, px;
    if (b < Wp)           { py = 0;     px = b; }
    else if (b < 2 * Wp)  { py = H + 1; px = b - Wp; }
    else {
        int rr = b - 2 * Wp;
        py = 1 + (rr >> 1);
        px = (rr & 1) ? (W + 1) : 0;
    }
    buf[((size_t)n * HpWp + (size_t)py * Wp + px) * 64 + ch4] =
        make_float4(0.f, 0.f, 0.f, 0.f);
}

// ============================================================
// featprep: NCHW fp32 -> padded NHWC fp32 (32x32 smem transpose)
// ============================================================
__global__ __launch_bounds__(1024) void featprep(
    const float* __restrict__ feat, float* __restrict__ XF,
    int H, int W, int Wp, int HpWp)
{
    __shared__ float tile[32][33];
    int xt = blockIdx.x, y = blockIdx.y;
    int n  = blockIdx.z >> 3, ct = blockIdx.z & 7;
    int tx = threadIdx.x, ty = threadIdx.y;

    tile[ty][tx] = feat[(((size_t)n * CC + ct * 32 + ty) * H + y) * W + xt * 32 + tx];
    __syncthreads();

    int c = ct * 32 + tx;
    int x = xt * 32 + ty;
    XF[((size_t)n * HpWp + (size_t)(y + 1) * Wp + (x + 1)) * CC + c] = tile[tx][ty];
}

// ============================================================
// convM: warp-mma 3x3 conv over ALL levels, SINGLE-TERM fp16
// (weights fp16, activations hi-only). GN fused on load when
// ssv != null (interior pixels only; padding stays zero).
// grid (TOTPT, 1, 32): z = tower*16 + n*2 + cohalf.
// 512 threads = 16 warps (4m x 4n).
// ============================================================
__global__ __launch_bounds__(512) void convM(
    const float4* __restrict__ inC, const float4* __restrict__ inR,
    const uint4* __restrict__ WFb, int layer,
    const float* __restrict__ clscb, const float* __restrict__ regcb,
    const float* __restrict__ ssv, const float* __restrict__ shv,
    float* __restrict__ outC, float* __restrict__ outR,
    float2* __restrict__ part)
{
    extern __shared__ char smem[];
    const uint32_t sb = smem_u32(smem);

    const int bx = blockIdx.x;
    const int L = (bx >= cSegA[2]) ? 2 : (bx >= cSegA[1]) ? 1 : 0;
    const int tile = bx - cSegA[L];
    const int H = cH[L], W = cW[L], Wp = cWp[L], lgW = cLgW[L];
    const int HW = cHW[L], HpWp = cHpWp[L];
    const size_t lvlpix = (size_t)cXpix[L];

    const int tid = threadIdx.x, wid = tid >> 5, lane = tid & 31;
    const int warp_m = wid >> 2, warp_n = wid & 3;
    const int p0 = tile * 256;
    const int z = blockIdx.z;
    const int tower = z >> 4, zz = z & 15;
    const int n = zz >> 1, co0 = (zz & 1) * 128;
    const size_t nbase = lvlpix + (size_t)n * HpWp;

    const float4* in = tower ? inR : inC;
    float* Y = tower ? outR : outC;
    const uint4* WFl = WFb + (size_t)(tower * 2 + layer) * (WELEM / 8);
    const float* bias = (tower ? regcb : clscb) + layer * CC;

    const int R  = 256 >> lgW;
    const int BR = (R + 2) * Wp;
    const int prow0 = p0 >> lgW;
    const int pstart = prow0 * Wp;

    float* sS = (float*)(smem + OSS);
    float* sHh = (float*)(smem + OSH);
    if (ssv && tid < 256) {
        int so = (L * 2 + tower) * 2048 + n * 256 + tid;
        sS[tid]  = ssv[so];
        sHh[tid] = shv[so];
    }
    __syncthreads();

    float acc[2][8][4];
#pragma unroll
    for (int mt = 0; mt < 2; mt++)
#pragma unroll
        for (int nt = 0; nt < 8; nt++)
#pragma unroll
            for (int i = 0; i < 4; i++) acc[mt][nt][i] = 0.0f;

    const int lrow = lane & 7;
    const int matr = (lane >> 3) & 1;
    const int matc = lane >> 4;

    int rnp[4];
#pragma unroll
    for (int np = 0; np < 4; np++)
        rnp[np] = warp_n * 64 + np * 16 + matc * 8 + lrow;

#pragma unroll 1
    for (int kc = 0; kc < 4; kc++) {
        // ---- B halo fill: fp32 -> (GN+ReLU interior-only) -> fp16 hi ----
        {
            const int lim = BR * 16;
#pragma unroll 1
            for (int t0 = tid; t0 < lim; t0 += 2048) {
                float4 xa[4];
#pragma unroll
                for (int u = 0; u < 4; u++) {
                    int t = t0 + u * 512;
                    xa[u] = make_float4(0.f, 0.f, 0.f, 0.f);
                    if (t < lim) {
                        int hr = t >> 4, v = t & 15;
                        int gpix = pstart + hr;
                        if (gpix < HpWp)
                            xa[u] = in[(size_t)(nbase + gpix) * 64 + (kc << 4) + v];
                    }
                }
#pragma unroll
                for (int u = 0; u < 4; u++) {
                    int t = t0 + u * 512;
                    if (t >= lim) break;
                    int hr = t >> 4, v = t & 15;
                    float4 x = xa[u];
                    if (ssv) {
                        int hd = hr / Wp;
                        int gx = hr - hd * Wp;
                        int gy = prow0 + hd;
                        if (gy >= 1 && gy <= H && gx >= 1 && gx <= W) {
                            int c = (kc << 6) + (v << 2);
                            x.x = fmaxf(fmaf(x.x, sS[c+0], sHh[c+0]), 0.f);
                            x.y = fmaxf(fmaf(x.y, sS[c+1], sHh[c+1]), 0.f);
                            x.z = fmaxf(fmaf(x.z, sS[c+2], sHh[c+2]), 0.f);
                            x.w = fmaxf(fmaf(x.w, sS[c+3], sHh[c+3]), 0.f);
                        } else {
                            x = make_float4(0.f, 0.f, 0.f, 0.f);
                        }
                    }
                    uint32_t base = (uint32_t)(hr * PITCH + (v << 3));
                    *reinterpret_cast<uint2*>(smem + OB_H + base) =
                        make_uint2(pkh(__float2half_rn(x.x), __float2half_rn(x.y)),
                                   pkh(__float2half_rn(x.z), __float2half_rn(x.w)));
                }
            }
        }
        // ---- A tap 0 prefetch (stage 0) ----
#pragma unroll
        for (int t = tid; t < 1024; t += 512) {
            int row = t >> 3, v = t & 7;
            uint32_t d = sb + (uint32_t)(row * PITCH + v * 16);
            size_t g = (size_t)(co0 + row) * 32 + kc * 8 + v;
            cpa16(d, WFl + g);
        }
        CPA_COMMIT();
        CPA_WAIT0();
        __syncthreads();

#pragma unroll 1
        for (int tap = 0; tap < 9; tap++) {
            if (tap < 8) {
                const uint32_t abase = sb + (uint32_t)(((tap + 1) & 1) * ASTG);
#pragma unroll
                for (int t = tid; t < 1024; t += 512) {
                    int row = t >> 3, v = t & 7;
                    uint32_t d = abase + (uint32_t)(row * PITCH + v * 16);
                    size_t g = (size_t)(tap + 1) * 8192 + (size_t)(co0 + row) * 32 + kc * 8 + v;
                    cpa16(d, WFl + g);
                }
                CPA_COMMIT();
            }

            const int ky = tap / 3, kx = tap - ky * 3;
            uint32_t bOff[4];
#pragma unroll
            for (int np = 0; np < 4; np++) {
                int r = rnp[np];
                int sr = ((r >> lgW) + ky) * Wp + (r & (W - 1)) + kx;
                bOff[np] = (uint32_t)(sr * PITCH);
            }
            const uint32_t sAH = sb + (uint32_t)((tap & 1) * ASTG);
            const uint32_t sBH = sb + OB_H;
            const int m0 = warp_m * 32;

#pragma unroll
            for (int ks = 0; ks < 4; ks++) {
                uint32_t ah[2][4], bb[4][4];
#pragma unroll
                for (int mt = 0; mt < 2; mt++) {
                    uint32_t off = (uint32_t)((m0 + mt * 16 + matr * 8 + lrow) * PITCH
                                              + (ks * 16 + matc * 8) * 2);
                    ldsm_x4(ah[mt][0], ah[mt][1], ah[mt][2], ah[mt][3], sAH + off);
                }
                const uint32_t kb = (uint32_t)((ks * 16 + matr * 8) * 2);
#pragma unroll
                for (int np = 0; np < 4; np++)
                    ldsm_x4(bb[np][0], bb[np][1], bb[np][2], bb[np][3],
                            sBH + bOff[np] + kb);
#pragma unroll
                for (int mt = 0; mt < 2; mt++)
#pragma unroll
                    for (int np = 0; np < 4; np++) {
                        mma_f16(acc[mt][np * 2 + 0], ah[mt], &bb[np][0]);
                        mma_f16(acc[mt][np * 2 + 1], ah[mt], &bb[np][2]);
                    }
            }
            if (tap < 8) CPA_WAIT0();
            __syncthreads();
        }
    }

    // ---- epilogue: bias, store fp32 padded NHWC, deterministic GN partials ----
    __shared__ float redS[16][2], redQ[16][2];
    const int qrow = lane >> 2, qcol = (lane & 3) * 2;
    float sg[2] = {0.0f, 0.0f}, qg[2] = {0.0f, 0.0f};

#pragma unroll
    for (int mt = 0; mt < 2; mt++) {
#pragma unroll
        for (int h8 = 0; h8 < 2; h8++) {
            const int col_ = co0 + warp_m * 32 + mt * 16 + qrow + h8 * 8;
            const float b = bias[col_];
#pragma unroll
            for (int nt = 0; nt < 8; nt++) {
#pragma unroll
                for (int cc2 = 0; cc2 < 2; cc2++) {
                    int p = p0 + warp_n * 64 + nt * 8 + qcol + cc2;
                    float v = acc[mt][nt][h8 * 2 + cc2] + b;
                    if (p < HW) {
                        int x = p & (W - 1), y = p >> lgW;
                        Y[(nbase + (size_t)(y + 1) * Wp + (x + 1)) * CC + col_] = v;
                        sg[mt] += v;
                        qg[mt] += v * v;
                    }
                }
            }
        }
    }
#pragma unroll
    for (int off = 16; off > 0; off >>= 1) {
#pragma unroll
        for (int mt = 0; mt < 2; mt++) {
            sg[mt] += __shfl_down_sync(0xffffffffu, sg[mt], off);
            qg[mt] += __shfl_down_sync(0xffffffffu, qg[mt], off);
        }
    }
    if (lane == 0) {
        redS[wid][0] = sg[0]; redS[wid][1] = sg[1];
        redQ[wid][0] = qg[0]; redQ[wid][1] = qg[1];
    }
    __syncthreads();
    if (tid < 8) {
        int wm = tid >> 1, mt = tid & 1;
        float S = 0.0f, Q = 0.0f;
#pragma unroll
        for (int wn = 0; wn < 4; wn++) {
            S += redS[wm * 4 + wn][mt];
            Q += redQ[wm * 4 + wn][mt];
        }
        size_t pidx = (size_t)z * TOTPT + bx;
        part[pidx * 8 + tid] = make_float2(S, Q);
    }
}

// ============================================================
// gn_finalize2: 768 blocks = (level, tower, n, group), all levels.
// Emits per-channel scale = rstd*gamma, shift = beta - mean*scale.
// ============================================================
__global__ __launch_bounds__(256) void gn_finalize2(
    const float2* __restrict__ part,
    const float* __restrict__ clsg, const float* __restrict__ clsbt,
    const float* __restrict__ regg, const float* __restrict__ regbt,
    float* __restrict__ oss, float* __restrict__ osh)
{
    const int b = blockIdx.x;
    const int L = b >> 8;
    const int r = b & 255;
    const int tower = r >> 7;
    const int rr = r & 127;
    const int n = rr >> 4, grp = rr & 15;
    const int half = grp >> 3, i = grp & 7;
    const int z = tower * 16 + n * 2 + half;
    const int seg = cSegA[L], PT = cPT[L];

    float S = 0.0f, Q = 0.0f;
    for (int t = threadIdx.x; t < PT; t += 256) {
        float2 p = part[(size_t)(z * TOTPT + seg + t) * 8 + i];
        S += p.x; Q += p.y;
    }
    __shared__ float sS[256], sQ[256];
    sS[threadIdx.x] = S; sQ[threadIdx.x] = Q;
    __syncthreads();
    for (int off = 128; off > 0; off >>= 1) {
        if (threadIdx.x < off) {
            sS[threadIdx.x] += sS[threadIdx.x + off];
            sQ[threadIdx.x] += sQ[threadIdx.x + off];
        }
        __syncthreads();
    }
    if (threadIdx.x < 16) {
        float cnt  = (float)(GSIZE * cHW[L]);
        float mean = sS[0] / cnt;
        float var  = sQ[0] / cnt - mean * mean;
        float rstd = rsqrtf(var + GN_EPS);
        int c = grp * 16 + threadIdx.x;
        float gam = tower ? regg[c] : clsg[c];
        float bet = tower ? regbt[c] : clsbt[c];
        float scale = rstd * gam;
        int so = (L * 2 + tower) * 2048 + n * 256 + c;
        oss[so] = scale;
        osh[so] = bet - mean * scale;
    }
}

// ============================================================
// convO: head convs over ALL levels, TWO-TERM (act hi+lo).
// grid (TOTPT, 1, 16): z = n*2 + mode. 256 threads = 8 warps.
// ============================================================
__global__ __launch_bounds__(256) void convO(
    const float4* __restrict__ inC, const float4* __restrict__ inR,
    const uint4* __restrict__ WOFb,
    const float* __restrict__ ssv, const float* __restrict__ shv,
    const float* __restrict__ clsb, const float* __restrict__ regb,
    const float* __restrict__ ctrb, float* __restrict__ out)
{
    extern __shared__ char smem[];
    const uint32_t sb = smem_u32(smem);

    const int bx = blockIdx.x;
    const int L = (bx >= cSegA[2]) ? 2 : (bx >= cSegA[1]) ? 1 : 0;
    const int tile = bx - cSegA[L];
    const int H = cH[L], W = cW[L], Wp = cWp[L], lgW = cLgW[L];
    const int HW = cHW[L], HpWp = cHpWp[L];
    const int poff = cPoff[L];
    const size_t lvlpix = (size_t)cXpix[L];

    const int tid = threadIdx.x, wid = tid >> 5, lane = tid & 31;
    const int p0 = tile * 256;
    const int z = blockIdx.z;
    const int n = z >> 1, mode = z & 1;
    const size_t nbase = lvlpix + (size_t)n * HpWp;

    const float4* in = mode ? inR : inC;
    const uint4* WFl = WOFb + (size_t)mode * (WOELEM / 8);

    const int R  = 256 >> lgW;
    const int BR = (R + 2) * Wp;
    const int prow0 = p0 >> lgW;
    const int pstart = prow0 * Wp;

    float* sS = (float*)(smem + OSS_O);
    float* sHh = (float*)(smem + OSH_O);
    if (tid < 256) {
        int so = (L * 2 + mode) * 2048 + n * 256 + tid;
        sS[tid]  = ssv[so];
        sHh[tid] = shv[so];
    }
    __syncthreads();

    float acc[2][4][4];
#pragma unroll
    for (int mt = 0; mt < 2; mt++)
#pragma unroll
        for (int nt = 0; nt < 4; nt++)
#pragma unroll
            for (int i = 0; i < 4; i++) acc[mt][nt][i] = 0.0f;

    const int lrow = lane & 7;
    const int matr = (lane >> 3) & 1;
    const int matc = lane >> 4;

    int rnp[2];
#pragma unroll
    for (int np = 0; np < 2; np++)
        rnp[np] = wid * 32 + np * 16 + matc * 8 + lrow;

#pragma unroll 1
    for (int kc = 0; kc < 4; kc++) {
        // ---- B halo fill (fp32 + interior-only GN + fp16 split) ----
        {
            const int lim = BR * 16;
#pragma unroll 1
            for (int t0 = tid; t0 < lim; t0 += 1024) {
                float4 xa[4];
#pragma unroll
                for (int u = 0; u < 4; u++) {
                    int t = t0 + u * 256;
                    xa[u] = make_float4(0.f, 0.f, 0.f, 0.f);
                    if (t < lim) {
                        int hr = t >> 4, v = t & 15;
                        int gpix = pstart + hr;
                        if (gpix < HpWp)
                            xa[u] = in[(size_t)(nbase + gpix) * 64 + (kc << 4) + v];
                    }
                }
#pragma unroll
                for (int u = 0; u < 4; u++) {
                    int t = t0 + u * 256;
                    if (t >= lim) break;
                    int hr = t >> 4, v = t & 15;
                    float4 x = xa[u];
                    int hd = hr / Wp;
                    int gx = hr - hd * Wp;
                    int gy = prow0 + hd;
                    if (gy >= 1 && gy <= H && gx >= 1 && gx <= W) {
                        int c = (kc << 6) + (v << 2);
                        x.x = fmaxf(fmaf(x.x, sS[c+0], sHh[c+0]), 0.f);
                        x.y = fmaxf(fmaf(x.y, sS[c+1], sHh[c+1]), 0.f);
                        x.z = fmaxf(fmaf(x.z, sS[c+2], sHh[c+2]), 0.f);
                        x.w = fmaxf(fmaf(x.w, sS[c+3], sHh[c+3]), 0.f);
                    } else {
                        x = make_float4(0.f, 0.f, 0.f, 0.f);
                    }
                    __half h0 = __float2half_rn(x.x);
                    __half h1 = __float2half_rn(x.y);
                    __half h2 = __float2half_rn(x.z);
                    __half h3 = __float2half_rn(x.w);
                    __half l0 = __float2half_rn(x.x - __half2float(h0));
                    __half l1 = __float2half_rn(x.y - __half2float(h1));
                    __half l2 = __float2half_rn(x.z - __half2float(h2));
                    __half l3 = __float2half_rn(x.w - __half2float(h3));
                    uint32_t base = (uint32_t)(hr * PITCH + (v << 3));
                    *reinterpret_cast<uint2*>(smem + OB_H_O + base) =
                        make_uint2(pkh(h0, h1), pkh(h2, h3));
                    *reinterpret_cast<uint2*>(smem + OB_L_O + base) =
                        make_uint2(pkh(l0, l1), pkh(l2, l3));
                }
            }
        }
        // ---- A tap 0 prefetch ----
        {
            int row = tid >> 3, v = tid & 7;
            uint32_t d = sb + (uint32_t)(row * PITCH + v * 16);
            size_t g = (size_t)row * 32 + kc * 8 + v;
            cpa16(d, WFl + g);
        }
        CPA_COMMIT();
        CPA_WAIT0();
        __syncthreads();

#pragma unroll 1
        for (int tap = 0; tap < 9; tap++) {
            if (tap < 8) {
                const uint32_t abase = sb + (uint32_t)(((tap + 1) & 1) * ASTG_O);
                int row = tid >> 3, v = tid & 7;
                uint32_t d = abase + (uint32_t)(row * PITCH + v * 16);
                size_t g = (size_t)(tap + 1) * 1024 + (size_t)row * 32 + kc * 8 + v;
                cpa16(d, WFl + g);
                CPA_COMMIT();
            }

            const int ky = tap / 3, kx = tap - ky * 3;
            uint32_t bOff[2];
#pragma unroll
            for (int np = 0; np < 2; np++) {
                int r = rnp[np];
                int sr = ((r >> lgW) + ky) * Wp + (r & (W - 1)) + kx;
                bOff[np] = (uint32_t)(sr * PITCH);
            }
            const uint32_t sAH = sb + (uint32_t)((tap & 1) * ASTG_O);
            const uint32_t sBH = sb + OB_H_O;
            const uint32_t sBL = sb + OB_L_O;

#pragma unroll
            for (int ks = 0; ks < 4; ks++) {
                uint32_t ah[2][4], bb[2][4];
#pragma unroll
                for (int mt = 0; mt < 2; mt++) {
                    uint32_t off = (uint32_t)((mt * 16 + matr * 8 + lrow) * PITCH
                                              + (ks * 16 + matc * 8) * 2);
                    ldsm_x4(ah[mt][0], ah[mt][1], ah[mt][2], ah[mt][3], sAH + off);
                }
                const uint32_t kb = (uint32_t)((ks * 16 + matr * 8) * 2);
#pragma unroll
                for (int np = 0; np < 2; np++)
                    ldsm_x4(bb[np][0], bb[np][1], bb[np][2], bb[np][3],
                            sBH + bOff[np] + kb);
#pragma unroll
                for (int mt = 0; mt < 2; mt++)
#pragma unroll
                    for (int np = 0; np < 2; np++) {
                        mma_f16(acc[mt][np * 2 + 0], ah[mt], &bb[np][0]);
                        mma_f16(acc[mt][np * 2 + 1], ah[mt], &bb[np][2]);
                    }
#pragma unroll
                for (int np = 0; np < 2; np++)
                    ldsm_x4(bb[np][0], bb[np][1], bb[np][2], bb[np][3],
                            sBL + bOff[np] + kb);
#pragma unroll
                for (int mt = 0; mt < 2; mt++)
#pragma unroll
                    for (int np = 0; np < 2; np++) {
                        mma_f16(acc[mt][np * 2 + 0], ah[mt], &bb[np][0]);
                        mma_f16(acc[mt][np * 2 + 1], ah[mt], &bb[np][2]);
                    }
            }
            if (tap < 8) CPA_WAIT0();
            __syncthreads();
        }
    }

    // ---- epilogue: scatter into concat output layout ----
    const int qrow = lane >> 2, qcol = (lane & 3) * 2;
#pragma unroll
    for (int mt = 0; mt < 2; mt++) {
#pragma unroll
        for (int h8 = 0; h8 < 2; h8++) {
            const int row = mt * 16 + h8 * 8 + qrow;
#pragma unroll
            for (int nt = 0; nt < 4; nt++) {
#pragma unroll
                for (int cc2 = 0; cc2 < 2; cc2++) {
                    int p = p0 + wid * 32 + nt * 8 + qcol + cc2;
                    if (p >= HW) continue;
                    float v = acc[mt][nt][h8 * 2 + cc2];
                    int x = p & (W - 1), y = p >> lgW;
                    size_t gp = (size_t)n * TOTHW + poff + (size_t)y * W + x;
                    if (mode == 0) {
                        if (row < 20) out[CLSBASE + gp * 20 + row] = v + clsb[row];
                    } else {
                        if (row < 4)
                            out[REGBASE + gp * 4 + row] = fmaxf(v + regb[row], 0.0f);
                        else if (row == 4)
                            out[CTRBASE + gp] = v + ctrb[0];
                    }
                }
            }
        }
    }
}

// ============================================================
// host launcher
// ============================================================
extern "C" void kernel_launch(void* const* d_in, const int* in_sizes, int n_in,
                              void* d_out, int out_size)
{
    (void)in_sizes; (void)n_in; (void)out_size;

    const float* feat[3] = { (const float*)d_in[0], (const float*)d_in[1],
                             (const float*)d_in[2] };
    const float* cls_conv_w = (const float*)d_in[3];
    const float* cls_conv_b = (const float*)d_in[4];
    const float* cls_gn_g   = (const float*)d_in[5];
    const float* cls_gn_b   = (const float*)d_in[6];
    const float* cls_out_w  = (const float*)d_in[7];
    const float* cls_out_b  = (const float*)d_in[8];
    const float* reg_conv_w = (const float*)d_in[9];
    const float* reg_conv_b = (const float*)d_in[10];
    const float* reg_gn_g   = (const float*)d_in[11];
    const float* reg_gn_b   = (const float*)d_in[12];
    const float* reg_out_w  = (const float*)d_in[13];
    const float* reg_out_b  = (const float*)d_in[14];
    const float* ctr_w      = (const float*)d_in[15];
    const float* ctr_b      = (const float*)d_in[16];

    float* out = (float*)d_out;

    float *XF, *Y0, *Y1, *Y2, *Y3, *ssv, *shv;
    __half *WF, *WOF;
    float2* part;
    cudaGetSymbolAddress((void**)&XF, g_XF);
    {
        float* ybase;
        cudaGetSymbolAddress((void**)&ybase, g_Y);
        Y0 = ybase;
        Y1 = ybase + (size_t)XCAP2;
        Y2 = ybase + 2 * (size_t)XCAP2;
        Y3 = ybase + 3 * (size_t)XCAP2;
    }
    cudaGetSymbolAddress((void**)&WF, g_WF);
    cudaGetSymbolAddress((void**)&WOF, g_WOF);
    cudaGetSymbolAddress((void**)&ssv, g_ssv);
    cudaGetSymbolAddress((void**)&shv, g_shv);
    cudaGetSymbolAddress((void**)&part, g_part);

    cudaFuncSetAttribute(convM, cudaFuncAttributeMaxDynamicSharedMemorySize, CM_DYN);
    cudaFuncSetAttribute(convO, cudaFuncAttributeMaxDynamicSharedMemorySize, CO_DYN);

    wprep<<<(4 * WELEM + 255) / 256, 256>>>(cls_conv_w, reg_conv_w, WF);
    woprep<<<(2 * WOELEM + 255) / 256, 256>>>(cls_out_w, reg_out_w, ctr_w, WOF);

    const int hH[3] = {100, 50, 25};
    const int hW[3] = {128, 64, 32};
    const int hWp[3] = {130, 66, 34};
    const int hHpWp[3] = {13260, 3432, 918};
    const size_t hXoff[3] = {0, 106080ull * 256, 133536ull * 256};

    for (int L = 0; L < 3; L++) {
        const int H = hH[L], W = hW[L], Wp = hWp[L], HpWp = hHpWp[L];
        const int zpN = (NB * (2 * Wp + 2 * H) * 64 + 255) / 256;
        zeropad<<<zpN, 256>>>((float4*)(XF + hXoff[L]), H, W, Wp, HpWp);
        dim3 fgrid(W / 32, H, NB * 8);
        featprep<<<fgrid, dim3(32, 32)>>>(feat[L], XF + hXoff[L], H, W, Wp, HpWp);
    }

    dim3 cgrid(TOTPT, 1, 32);
    dim3 ogrid(TOTPT, 1, 16);

    // conv layer 1, all levels, both towers (single-term)
    convM<<<cgrid, 512, CM_DYN>>>(
        (const float4*)XF, (const float4*)XF,
        (const uint4*)WF, 0,
        cls_conv_b, reg_conv_b, nullptr, nullptr,
        Y0, Y1, part);
    gn_finalize2<<<768, 256>>>(part,
        cls_gn_g, cls_gn_b, reg_gn_g, reg_gn_b, ssv, shv);

    // conv layer 2, all levels, both towers (single-term), GN fused on load
    convM<<<cgrid, 512, CM_DYN>>>(
        (const float4*)Y0, (const float4*)Y1,
        (const uint4*)WF, 1,
        cls_conv_b, reg_conv_b, ssv, shv,
        Y2, Y3, part);
    gn_finalize2<<<768, 256>>>(part,
        cls_gn_g + CC, cls_gn_b + CC, reg_gn_g + CC, reg_gn_b + CC,
        ssv + 12288, shv + 12288);

    // heads, all levels, both sets (two-term), GN of layer 2 fused on load
    convO<<<ogrid, 256, CO_DYN>>>(
        (const float4*)Y2, (const float4*)Y3,
        (const uint4*)WOF,
        ssv + 12288, shv + 12288,
        cls_out_b, reg_out_b, ctr_b, out);
}

// round 14
// speedup vs baseline: 15.5014x; 1.1718x over previous
#include <cuda_runtime.h>
#include <cuda_fp16.h>
#include <math.h>
#include <stdint.h>

// ---------------- problem constants ----------------
#define NB 8
#define CC 256
#define NGROUPS 16
#define GSIZE 16
#define GN_EPS 1e-5f

#define TOTHW   16800
#define CLSBASE 0
#define REGBASE 2688000
#define CTRBASE 3225600

#define WELEM  (CC * CC * 9)      // 589824 fp16 per tower layer
#define WOELEM (9 * 32 * 256)     // 73728 per head set

#define TOTPT 67                  // 50 + 13 + 4 px-tiles across levels
#define XCAP2 36070000            // all-level padded NHWC capacity (36,065,280 used)

// per-level compile-time tables
__constant__ int cH[3]    = {100, 50, 25};
__constant__ int cW[3]    = {128, 64, 32};
__constant__ int cLgW[3]  = {7, 6, 5};
__constant__ int cWp[3]   = {130, 66, 34};
__constant__ int cHpWp[3] = {13260, 3432, 918};
__constant__ int cHW[3]   = {12800, 3200, 800};
__constant__ int cPT[3]   = {50, 13, 4};
__constant__ int cSegA[3] = {0, 50, 63};
__constant__ int cPoff[3] = {0, 12800, 16000};
__constant__ unsigned long long cXpix[3] = {0ull, 106080ull, 133536ull};

// scratch (device globals; zero-initialized, no runtime allocation)
__device__ __align__(16) __half g_XFH[XCAP2];         // features fp16 padded NHWC
__device__ __align__(16) float g_Y[4][XCAP2];         // tower outputs fp32
__device__ __align__(16) __half g_WF[4 * WELEM];
__device__ __align__(16) __half g_WOF[2 * WOELEM];
__device__ float  g_ssv[2 * 3 * 2 * 2048];   // [conv][level][tower][n*256+c]
__device__ float  g_shv[2 * 3 * 2 * 2048];
__device__ float2 g_part[32 * TOTPT * 8];

// ---------------- PTX helpers (arch-agnostic sm_80+) ----------------
__device__ __forceinline__ uint32_t smem_u32(const void* p) {
    uint32_t a;
    asm("{ .reg .u64 t; cvta.to.shared.u64 t, %1; cvt.u32.u64 %0, t; }"
        : "=r"(a) : "l"(p));
    return a;
}
__device__ __forceinline__ void ldsm_x4(uint32_t& r0, uint32_t& r1,
                                        uint32_t& r2, uint32_t& r3, uint32_t a) {
    asm volatile("ldmatrix.sync.aligned.m8n8.x4.shared.b16 {%0,%1,%2,%3}, [%4];"
        : "=r"(r0), "=r"(r1), "=r"(r2), "=r"(r3) : "r"(a));
}
__device__ __forceinline__ void mma_f16(float* d, const uint32_t* a,
                                        const uint32_t* b) {
    asm volatile("mma.sync.aligned.m16n8k16.row.col.f32.f16.f16.f32 "
        "{%0,%1,%2,%3}, {%4,%5,%6,%7}, {%8,%9}, {%0,%1,%2,%3};"
        : "+f"(d[0]), "+f"(d[1]), "+f"(d[2]), "+f"(d[3])
        : "r"(a[0]), "r"(a[1]), "r"(a[2]), "r"(a[3]), "r"(b[0]), "r"(b[1]));
}
__device__ __forceinline__ void cpa16(uint32_t d, const void* s) {
    asm volatile("cp.async.cg.shared.global [%0], [%1], 16;"
                 :: "r"(d), "l"(s) : "memory");
}
// zero-fill variant: bytes beyond src_sz are written as 0
__device__ __forceinline__ void cpa16z(uint32_t d, const void* s, uint32_t src_sz) {
    asm volatile("cp.async.cg.shared.global [%0], [%1], 16, %2;"
                 :: "r"(d), "l"(s), "r"(src_sz) : "memory");
}
#define CPA_COMMIT() asm volatile("cp.async.commit_group;" ::: "memory")
#define CPA_WAIT0()  asm volatile("cp.async.wait_group 0;" ::: "memory")

__device__ __forceinline__ uint32_t pkh(__half a, __half b) {
    __half2 t = __halves2half2(a, b);
    return *reinterpret_cast<uint32_t*>(&t);
}

// ---- convM smem geometry (dynamic): A 2-stage + B halo (hi only) ----
#define PITCH 144
#define ASTG  18432
#define OB_H  36864
#define OSS   111744                 // OB_H + 520*144
#define OSH   112768
#define CM_DYN 113792

// ---- convO smem geometry (dynamic): B halo hi only ----
#define ASTG_O 4608
#define OB_H_O 9216
#define OSS_O  84096                 // OB_H_O + 520*144
#define OSH_O  85120
#define CO_DYN 86144

// ============================================================
// wprep: all 4 tower layers in one launch.
// ============================================================
__global__ __launch_bounds__(256) void wprep(
    const float* __restrict__ clsw, const float* __restrict__ regw,
    __half* __restrict__ WF)
{
    int idx = blockIdx.x * 256 + threadIdx.x;
    if (idx >= 4 * WELEM) return;
    int layer = idx / WELEM;
    int r0 = idx - layer * WELEM;
    int tap = r0 / 65536;
    int r   = r0 - tap * 65536;
    int co  = r >> 8, ci = r & 255;
    const float* src = (layer < 2 ? clsw : regw) + (size_t)(layer & 1) * WELEM;
    WF[idx] = __float2half_rn(src[co * 2304 + ci * 9 + tap]);
}

// ============================================================
// woprep: head weights -> [set][tap][row32][ci] fp16
// ============================================================
__global__ __launch_bounds__(256) void woprep(
    const float* __restrict__ clsw, const float* __restrict__ regw,
    const float* __restrict__ ctrw, __half* __restrict__ WOF)
{
    int idx = blockIdx.x * 256 + threadIdx.x;
    if (idx >= 2 * WOELEM) return;
    int set = idx / WOELEM;
    int r   = idx - set * WOELEM;
    int tap = r / 8192;
    int r2  = r - tap * 8192;
    int row = r2 >> 8, ci = r2 & 255;
    float v = 0.0f;
    if (set == 0) {
        if (row < 20) v = clsw[(row * 256 + ci) * 9 + tap];
    } else {
        if (row < 4)       v = regw[(row * 256 + ci) * 9 + tap];
        else if (row == 4) v = ctrw[ci * 9 + tap];
    }
    WOF[idx] = __float2half_rn(v);
}

// ============================================================
// zeropad_h: zero border pixels of one level's padded NHWC fp16 buffer
// ============================================================
__global__ __launch_bounds__(256) void zeropad_h(
    uint4* __restrict__ buf, int H, int W, int Wp, int HpWp)
{
    int bc = 2 * Wp + 2 * H;
    int total = NB * bc * 32;            // 256 half = 32 uint4 per pixel
    int idx = blockIdx.x * 256 + threadIdx.x;
    if (idx >= total) return;
    int ch4 = idx & 31;
    int r   = idx >> 5;
    int n   = r / bc;
    int b   = r - n * bc;
    int py, px;
    if (b < Wp)           { py = 0;     px = b; }
    else if (b < 2 * Wp)  { py = H + 1; px = b - Wp; }
    else {
        int rr = b - 2 * Wp;
        py = 1 + (rr >> 1);
        px = (rr & 1) ? (W + 1) : 0;
    }
    buf[((size_t)n * HpWp + (size_t)py * Wp + px) * 32 + ch4] =
        make_uint4(0u, 0u, 0u, 0u);
}

// ============================================================
// featprep: NCHW fp32 -> padded NHWC fp16 (32x32 smem transpose)
// ============================================================
__global__ __launch_bounds__(1024) void featprep(
    const float* __restrict__ feat, __half* __restrict__ XH,
    int H, int W, int Wp, int HpWp)
{
    __shared__ float tile[32][33];
    int xt = blockIdx.x, y = blockIdx.y;
    int n  = blockIdx.z >> 3, ct = blockIdx.z & 7;
    int tx = threadIdx.x, ty = threadIdx.y;

    tile[ty][tx] = feat[(((size_t)n * CC + ct * 32 + ty) * H + y) * W + xt * 32 + tx];
    __syncthreads();

    int c = ct * 32 + tx;
    int x = xt * 32 + ty;
    XH[((size_t)n * HpWp + (size_t)(y + 1) * Wp + (x + 1)) * CC + c] =
        __float2half_rn(tile[tx][ty]);
}

// ============================================================
// convM: warp-mma 3x3 conv over ALL levels, single-term fp16.
// If inH != null (layer 1): B halo filled by pure cp.async from fp16
// features. Else (layer 2): fp32 input + fused GN (interior-only) +
// fp16 convert. grid (TOTPT, 1, 32). 512 threads = 16 warps (4m x 4n).
// ============================================================
__global__ __launch_bounds__(512) void convM(
    const __half* __restrict__ inH,
    const float4* __restrict__ inC, const float4* __restrict__ inR,
    const uint4* __restrict__ WFb, int layer,
    const float* __restrict__ clscb, const float* __restrict__ regcb,
    const float* __restrict__ ssv, const float* __restrict__ shv,
    float* __restrict__ outC, float* __restrict__ outR,
    float2* __restrict__ part)
{
    extern __shared__ char smem[];
    const uint32_t sb = smem_u32(smem);

    const int bx = blockIdx.x;
    const int L = (bx >= cSegA[2]) ? 2 : (bx >= cSegA[1]) ? 1 : 0;
    const int tile = bx - cSegA[L];
    const int H = cH[L], W = cW[L], Wp = cWp[L], lgW = cLgW[L];
    const int HW = cHW[L], HpWp = cHpWp[L];
    const size_t lvlpix = (size_t)cXpix[L];

    const int tid = threadIdx.x, wid = tid >> 5, lane = tid & 31;
    const int warp_m = wid >> 2, warp_n = wid & 3;
    const int p0 = tile * 256;
    const int z = blockIdx.z;
    const int tower = z >> 4, zz = z & 15;
    const int n = zz >> 1, co0 = (zz & 1) * 128;
    const size_t nbase = lvlpix + (size_t)n * HpWp;

    const float4* in = tower ? inR : inC;
    float* Y = tower ? outR : outC;
    const uint4* WFl = WFb + (size_t)(tower * 2 + layer) * (WELEM / 8);
    const float* bias = (tower ? regcb : clscb) + layer * CC;

    const int R  = 256 >> lgW;
    const int BR = (R + 2) * Wp;
    const int prow0 = p0 >> lgW;
    const int pstart = prow0 * Wp;

    float* sS = (float*)(smem + OSS);
    float* sHh = (float*)(smem + OSH);
    if (ssv && tid < 256) {
        int so = (L * 2 + tower) * 2048 + n * 256 + tid;
        sS[tid]  = ssv[so];
        sHh[tid] = shv[so];
    }
    __syncthreads();

    float acc[2][8][4];
#pragma unroll
    for (int mt = 0; mt < 2; mt++)
#pragma unroll
        for (int nt = 0; nt < 8; nt++)
#pragma unroll
            for (int i = 0; i < 4; i++) acc[mt][nt][i] = 0.0f;

    const int lrow = lane & 7;
    const int matr = (lane >> 3) & 1;
    const int matc = lane >> 4;

    int rnp[4];
#pragma unroll
    for (int np = 0; np < 4; np++)
        rnp[np] = warp_n * 64 + np * 16 + matc * 8 + lrow;

#pragma unroll 1
    for (int kc = 0; kc < 4; kc++) {
        if (inH) {
            // ---- L1: B halo via pure cp.async from fp16 features ----
#pragma unroll 1
            for (int t = tid; t < BR * 8; t += 512) {
                int hr = t >> 3, v = t & 7;
                int gpix = pstart + hr;
                uint32_t ok = (gpix < HpWp) ? 16u : 0u;
                uint32_t d = sb + OB_H + (uint32_t)(hr * PITCH + v * 16);
                cpa16z(d, inH + (nbase + gpix) * 256 + (kc << 6) + (v << 3), ok);
            }
        } else {
            // ---- L2: fp32 -> (GN+ReLU interior-only) -> fp16 hi ----
            const int lim = BR * 16;
#pragma unroll 1
            for (int t0 = tid; t0 < lim; t0 += 2048) {
                float4 xa[4];
#pragma unroll
                for (int u = 0; u < 4; u++) {
                    int t = t0 + u * 512;
                    xa[u] = make_float4(0.f, 0.f, 0.f, 0.f);
                    if (t < lim) {
                        int hr = t >> 4, v = t & 15;
                        int gpix = pstart + hr;
                        if (gpix < HpWp)
                            xa[u] = in[(size_t)(nbase + gpix) * 64 + (kc << 4) + v];
                    }
                }
#pragma unroll
                for (int u = 0; u < 4; u++) {
                    int t = t0 + u * 512;
                    if (t >= lim) break;
                    int hr = t >> 4, v = t & 15;
                    float4 x = xa[u];
                    int hd = hr / Wp;
                    int gx = hr - hd * Wp;
                    int gy = prow0 + hd;
                    if (gy >= 1 && gy <= H && gx >= 1 && gx <= W) {
                        int c = (kc << 6) + (v << 2);
                        x.x = fmaxf(fmaf(x.x, sS[c+0], sHh[c+0]), 0.f);
                        x.y = fmaxf(fmaf(x.y, sS[c+1], sHh[c+1]), 0.f);
                        x.z = fmaxf(fmaf(x.z, sS[c+2], sHh[c+2]), 0.f);
                        x.w = fmaxf(fmaf(x.w, sS[c+3], sHh[c+3]), 0.f);
                    } else {
                        x = make_float4(0.f, 0.f, 0.f, 0.f);
                    }
                    uint32_t base = (uint32_t)(hr * PITCH + (v << 3));
                    *reinterpret_cast<uint2*>(smem + OB_H + base) =
                        make_uint2(pkh(__float2half_rn(x.x), __float2half_rn(x.y)),
                                   pkh(__float2half_rn(x.z), __float2half_rn(x.w)));
                }
            }
        }
        // ---- A tap 0 prefetch (stage 0) ----
#pragma unroll
        for (int t = tid; t < 1024; t += 512) {
            int row = t >> 3, v = t & 7;
            uint32_t d = sb + (uint32_t)(row * PITCH + v * 16);
            size_t g = (size_t)(co0 + row) * 32 + kc * 8 + v;
            cpa16(d, WFl + g);
        }
        CPA_COMMIT();
        CPA_WAIT0();
        __syncthreads();

#pragma unroll 1
        for (int tap = 0; tap < 9; tap++) {
            if (tap < 8) {
                const uint32_t abase = sb + (uint32_t)(((tap + 1) & 1) * ASTG);
#pragma unroll
                for (int t = tid; t < 1024; t += 512) {
                    int row = t >> 3, v = t & 7;
                    uint32_t d = abase + (uint32_t)(row * PITCH + v * 16);
                    size_t g = (size_t)(tap + 1) * 8192 + (size_t)(co0 + row) * 32 + kc * 8 + v;
                    cpa16(d, WFl + g);
                }
                CPA_COMMIT();
            }

            const int ky = tap / 3, kx = tap - ky * 3;
            uint32_t bOff[4];
#pragma unroll
            for (int np = 0; np < 4; np++) {
                int r = rnp[np];
                int sr = ((r >> lgW) + ky) * Wp + (r & (W - 1)) + kx;
                bOff[np] = (uint32_t)(sr * PITCH);
            }
            const uint32_t sAH = sb + (uint32_t)((tap & 1) * ASTG);
            const uint32_t sBH = sb + OB_H;
            const int m0 = warp_m * 32;

#pragma unroll
            for (int ks = 0; ks < 4; ks++) {
                uint32_t ah[2][4], bb[4][4];
#pragma unroll
                for (int mt = 0; mt < 2; mt++) {
                    uint32_t off = (uint32_t)((m0 + mt * 16 + matr * 8 + lrow) * PITCH
                                              + (ks * 16 + matc * 8) * 2);
                    ldsm_x4(ah[mt][0], ah[mt][1], ah[mt][2], ah[mt][3], sAH + off);
                }
                const uint32_t kb = (uint32_t)((ks * 16 + matr * 8) * 2);
#pragma unroll
                for (int np = 0; np < 4; np++)
                    ldsm_x4(bb[np][0], bb[np][1], bb[np][2], bb[np][3],
                            sBH + bOff[np] + kb);
#pragma unroll
                for (int mt = 0; mt < 2; mt++)
#pragma unroll
                    for (int np = 0; np < 4; np++) {
                        mma_f16(acc[mt][np * 2 + 0], ah[mt], &bb[np][0]);
                        mma_f16(acc[mt][np * 2 + 1], ah[mt], &bb[np][2]);
                    }
            }
            if (tap < 8) CPA_WAIT0();
            __syncthreads();
        }
    }

    // ---- epilogue: bias, store fp32 padded NHWC, deterministic GN partials ----
    __shared__ float redS[16][2], redQ[16][2];
    const int qrow = lane >> 2, qcol = (lane & 3) * 2;
    float sg[2] = {0.0f, 0.0f}, qg[2] = {0.0f, 0.0f};

#pragma unroll
    for (int mt = 0; mt < 2; mt++) {
#pragma unroll
        for (int h8 = 0; h8 < 2; h8++) {
            const int col_ = co0 + warp_m * 32 + mt * 16 + qrow + h8 * 8;
            const float b = bias[col_];
#pragma unroll
            for (int nt = 0; nt < 8; nt++) {
#pragma unroll
                for (int cc2 = 0; cc2 < 2; cc2++) {
                    int p = p0 + warp_n * 64 + nt * 8 + qcol + cc2;
                    float v = acc[mt][nt][h8 * 2 + cc2] + b;
                    if (p < HW) {
                        int x = p & (W - 1), y = p >> lgW;
                        Y[(nbase + (size_t)(y + 1) * Wp + (x + 1)) * CC + col_] = v;
                        sg[mt] += v;
                        qg[mt] += v * v;
                    }
                }
            }
        }
    }
#pragma unroll
    for (int off = 16; off > 0; off >>= 1) {
#pragma unroll
        for (int mt = 0; mt < 2; mt++) {
            sg[mt] += __shfl_down_sync(0xffffffffu, sg[mt], off);
            qg[mt] += __shfl_down_sync(0xffffffffu, qg[mt], off);
        }
    }
    if (lane == 0) {
        redS[wid][0] = sg[0]; redS[wid][1] = sg[1];
        redQ[wid][0] = qg[0]; redQ[wid][1] = qg[1];
    }
    __syncthreads();
    if (tid < 8) {
        int wm = tid >> 1, mt = tid & 1;
        float S = 0.0f, Q = 0.0f;
#pragma unroll
        for (int wn = 0; wn < 4; wn++) {
            S += redS[wm * 4 + wn][mt];
            Q += redQ[wm * 4 + wn][mt];
        }
        size_t pidx = (size_t)z * TOTPT + bx;
        part[pidx * 8 + tid] = make_float2(S, Q);
    }
}

// ============================================================
// gn_finalize2: 768 blocks = (level, tower, n, group), all levels.
// ============================================================
__global__ __launch_bounds__(256) void gn_finalize2(
    const float2* __restrict__ part,
    const float* __restrict__ clsg, const float* __restrict__ clsbt,
    const float* __restrict__ regg, const float* __restrict__ regbt,
    float* __restrict__ oss, float* __restrict__ osh)
{
    const int b = blockIdx.x;
    const int L = b >> 8;
    const int r = b & 255;
    const int tower = r >> 7;
    const int rr = r & 127;
    const int n = rr >> 4, grp = rr & 15;
    const int half = grp >> 3, i = grp & 7;
    const int z = tower * 16 + n * 2 + half;
    const int seg = cSegA[L], PT = cPT[L];

    float S = 0.0f, Q = 0.0f;
    for (int t = threadIdx.x; t < PT; t += 256) {
        float2 p = part[(size_t)(z * TOTPT + seg + t) * 8 + i];
        S += p.x; Q += p.y;
    }
    __shared__ float sS[256], sQ[256];
    sS[threadIdx.x] = S; sQ[threadIdx.x] = Q;
    __syncthreads();
    for (int off = 128; off > 0; off >>= 1) {
        if (threadIdx.x < off) {
            sS[threadIdx.x] += sS[threadIdx.x + off];
            sQ[threadIdx.x] += sQ[threadIdx.x + off];
        }
        __syncthreads();
    }
    if (threadIdx.x < 16) {
        float cnt  = (float)(GSIZE * cHW[L]);
        float mean = sS[0] / cnt;
        float var  = sQ[0] / cnt - mean * mean;
        float rstd = rsqrtf(var + GN_EPS);
        int c = grp * 16 + threadIdx.x;
        float gam = tower ? regg[c] : clsg[c];
        float bet = tower ? regbt[c] : clsbt[c];
        float scale = rstd * gam;
        int so = (L * 2 + tower) * 2048 + n * 256 + c;
        oss[so] = scale;
        osh[so] = bet - mean * scale;
    }
}

// ============================================================
// convO: head convs over ALL levels, SINGLE-TERM (act hi only).
// grid (TOTPT, 1, 16): z = n*2 + mode. 256 threads = 8 warps.
// ============================================================
__global__ __launch_bounds__(256) void convO(
    const float4* __restrict__ inC, const float4* __restrict__ inR,
    const uint4* __restrict__ WOFb,
    const float* __restrict__ ssv, const float* __restrict__ shv,
    const float* __restrict__ clsb, const float* __restrict__ regb,
    const float* __restrict__ ctrb, float* __restrict__ out)
{
    extern __shared__ char smem[];
    const uint32_t sb = smem_u32(smem);

    const int bx = blockIdx.x;
    const int L = (bx >= cSegA[2]) ? 2 : (bx >= cSegA[1]) ? 1 : 0;
    const int tile = bx - cSegA[L];
    const int H = cH[L], W = cW[L], Wp = cWp[L], lgW = cLgW[L];
    const int HW = cHW[L], HpWp = cHpWp[L];
    const int poff = cPoff[L];
    const size_t lvlpix = (size_t)cXpix[L];

    const int tid = threadIdx.x, wid = tid >> 5, lane = tid & 31;
    const int p0 = tile * 256;
    const int z = blockIdx.z;
    const int n = z >> 1, mode = z & 1;
    const size_t nbase = lvlpix + (size_t)n * HpWp;

    const float4* in = mode ? inR : inC;
    const uint4* WFl = WOFb + (size_t)mode * (WOELEM / 8);

    const int R  = 256 >> lgW;
    const int BR = (R + 2) * Wp;
    const int prow0 = p0 >> lgW;
    const int pstart = prow0 * Wp;

    float* sS = (float*)(smem + OSS_O);
    float* sHh = (float*)(smem + OSH_O);
    if (tid < 256) {
        int so = (L * 2 + mode) * 2048 + n * 256 + tid;
        sS[tid]  = ssv[so];
        sHh[tid] = shv[so];
    }
    __syncthreads();

    float acc[2][4][4];
#pragma unroll
    for (int mt = 0; mt < 2; mt++)
#pragma unroll
        for (int nt = 0; nt < 4; nt++)
#pragma unroll
            for (int i = 0; i < 4; i++) acc[mt][nt][i] = 0.0f;

    const int lrow = lane & 7;
    const int matr = (lane >> 3) & 1;
    const int matc = lane >> 4;

    int rnp[2];
#pragma unroll
    for (int np = 0; np < 2; np++)
        rnp[np] = wid * 32 + np * 16 + matc * 8 + lrow;

#pragma unroll 1
    for (int kc = 0; kc < 4; kc++) {
        // ---- B halo fill (fp32 + interior-only GN + fp16 hi) ----
        {
            const int lim = BR * 16;
#pragma unroll 1
            for (int t0 = tid; t0 < lim; t0 += 1024) {
                float4 xa[4];
#pragma unroll
                for (int u = 0; u < 4; u++) {
                    int t = t0 + u * 256;
                    xa[u] = make_float4(0.f, 0.f, 0.f, 0.f);
                    if (t < lim) {
                        int hr = t >> 4, v = t & 15;
                        int gpix = pstart + hr;
                        if (gpix < HpWp)
                            xa[u] = in[(size_t)(nbase + gpix) * 64 + (kc << 4) + v];
                    }
                }
#pragma unroll
                for (int u = 0; u < 4; u++) {
                    int t = t0 + u * 256;
                    if (t >= lim) break;
                    int hr = t >> 4, v = t & 15;
                    float4 x = xa[u];
                    int hd = hr / Wp;
                    int gx = hr - hd * Wp;
                    int gy = prow0 + hd;
                    if (gy >= 1 && gy <= H && gx >= 1 && gx <= W) {
                        int c = (kc << 6) + (v << 2);
                        x.x = fmaxf(fmaf(x.x, sS[c+0], sHh[c+0]), 0.f);
                        x.y = fmaxf(fmaf(x.y, sS[c+1], sHh[c+1]), 0.f);
                        x.z = fmaxf(fmaf(x.z, sS[c+2], sHh[c+2]), 0.f);
                        x.w = fmaxf(fmaf(x.w, sS[c+3], sHh[c+3]), 0.f);
                    } else {
                        x = make_float4(0.f, 0.f, 0.f, 0.f);
                    }
                    uint32_t base = (uint32_t)(hr * PITCH + (v << 3));
                    *reinterpret_cast<uint2*>(smem + OB_H_O + base) =
                        make_uint2(pkh(__float2half_rn(x.x), __float2half_rn(x.y)),
                                   pkh(__float2half_rn(x.z), __float2half_rn(x.w)));
                }
            }
        }
        // ---- A tap 0 prefetch ----
        {
            int row = tid >> 3, v = tid & 7;
            uint32_t d = sb + (uint32_t)(row * PITCH + v * 16);
            size_t g = (size_t)row * 32 + kc * 8 + v;
            cpa16(d, WFl + g);
        }
        CPA_COMMIT();
        CPA_WAIT0();
        __syncthreads();

#pragma unroll 1
        for (int tap = 0; tap < 9; tap++) {
            if (tap < 8) {
                const uint32_t abase = sb + (uint32_t)(((tap + 1) & 1) * ASTG_O);
                int row = tid >> 3, v = tid & 7;
                uint32_t d = abase + (uint32_t)(row * PITCH + v * 16);
                size_t g = (size_t)(tap + 1) * 1024 + (size_t)row * 32 + kc * 8 + v;
                cpa16(d, WFl + g);
                CPA_COMMIT();
            }

            const int ky = tap / 3, kx = tap - ky * 3;
            uint32_t bOff[2];
#pragma unroll
            for (int np = 0; np < 2; np++) {
                int r = rnp[np];
                int sr = ((r >> lgW) + ky) * Wp + (r & (W - 1)) + kx;
                bOff[np] = (uint32_t)(sr * PITCH);
            }
            const uint32_t sAH = sb + (uint32_t)((tap & 1) * ASTG_O);
            const uint32_t sBH = sb + OB_H_O;

#pragma unroll
            for (int ks = 0; ks < 4; ks++) {
                uint32_t ah[2][4], bb[2][4];
#pragma unroll
                for (int mt = 0; mt < 2; mt++) {
                    uint32_t off = (uint32_t)((mt * 16 + matr * 8 + lrow) * PITCH
                                              + (ks * 16 + matc * 8) * 2);
                    ldsm_x4(ah[mt][0], ah[mt][1], ah[mt][2], ah[mt][3], sAH + off);
                }
                const uint32_t kb = (uint32_t)((ks * 16 + matr * 8) * 2);
#pragma unroll
                for (int np = 0; np < 2; np++)
                    ldsm_x4(bb[np][0], bb[np][1], bb[np][2], bb[np][3],
                            sBH + bOff[np] + kb);
#pragma unroll
                for (int mt = 0; mt < 2; mt++)
#pragma unroll
                    for (int np = 0; np < 2; np++) {
                        mma_f16(acc[mt][np * 2 + 0], ah[mt], &bb[np][0]);
                        mma_f16(acc[mt][np * 2 + 1], ah[mt], &bb[np][2]);
                    }
            }
            if (tap < 8) CPA_WAIT0();
            __syncthreads();
        }
    }

    // ---- epilogue: scatter into concat output layout ----
    const int qrow = lane >> 2, qcol = (lane & 3) * 2;
#pragma unroll
    for (int mt = 0; mt < 2; mt++) {
#pragma unroll
        for (int h8 = 0; h8 < 2; h8++) {
            const int row = mt * 16 + h8 * 8 + qrow;
#pragma unroll
            for (int nt = 0; nt < 4; nt++) {
#pragma unroll
                for (int cc2 = 0; cc2 < 2; cc2++) {
                    int p = p0 + wid * 32 + nt * 8 + qcol + cc2;
                    if (p >= HW) continue;
                    float v = acc[mt][nt][h8 * 2 + cc2];
                    int x = p & (W - 1), y = p >> lgW;
                    size_t gp = (size_t)n * TOTHW + poff + (size_t)y * W + x;
                    if (mode == 0) {
                        if (row < 20) out[CLSBASE + gp * 20 + row] = v + clsb[row];
                    } else {
                        if (row < 4)
                            out[REGBASE + gp * 4 + row] = fmaxf(v + regb[row], 0.0f);
                        else if (row == 4)
                            out[CTRBASE + gp] = v + ctrb[0];
                    }
                }
            }
        }
    }
}

// ============================================================
// host launcher
// ============================================================
extern "C" void kernel_launch(void* const* d_in, const int* in_sizes, int n_in,
                              void* d_out, int out_size)
{
    (void)in_sizes; (void)n_in; (void)out_size;

    const float* feat[3] = { (const float*)d_in[0], (const float*)d_in[1],
                             (const float*)d_in[2] };
    const float* cls_conv_w = (const float*)d_in[3];
    const float* cls_conv_b = (const float*)d_in[4];
    const float* cls_gn_g   = (const float*)d_in[5];
    const float* cls_gn_b   = (const float*)d_in[6];
    const float* cls_out_w  = (const float*)d_in[7];
    const float* cls_out_b  = (const float*)d_in[8];
    const float* reg_conv_w = (const float*)d_in[9];
    const float* reg_conv_b = (const float*)d_in[10];
    const float* reg_gn_g   = (const float*)d_in[11];
    const float* reg_gn_b   = (const float*)d_in[12];
    const float* reg_out_w  = (const float*)d_in[13];
    const float* reg_out_b  = (const float*)d_in[14];
    const float* ctr_w      = (const float*)d_in[15];
    const float* ctr_b      = (const float*)d_in[16];

    float* out = (float*)d_out;

    __half *XFH, *WF, *WOF;
    float *Y0, *Y1, *Y2, *Y3, *ssv, *shv;
    float2* part;
    cudaGetSymbolAddress((void**)&XFH, g_XFH);
    {
        float* ybase;
        cudaGetSymbolAddress((void**)&ybase, g_Y);
        Y0 = ybase;
        Y1 = ybase + (size_t)XCAP2;
        Y2 = ybase + 2 * (size_t)XCAP2;
        Y3 = ybase + 3 * (size_t)XCAP2;
    }
    cudaGetSymbolAddress((void**)&WF, g_WF);
    cudaGetSymbolAddress((void**)&WOF, g_WOF);
    cudaGetSymbolAddress((void**)&ssv, g_ssv);
    cudaGetSymbolAddress((void**)&shv, g_shv);
    cudaGetSymbolAddress((void**)&part, g_part);

    cudaFuncSetAttribute(convM, cudaFuncAttributeMaxDynamicSharedMemorySize, CM_DYN);
    cudaFuncSetAttribute(convO, cudaFuncAttributeMaxDynamicSharedMemorySize, CO_DYN);

    wprep<<<(4 * WELEM + 255) / 256, 256>>>(cls_conv_w, reg_conv_w, WF);
    woprep<<<(2 * WOELEM + 255) / 256, 256>>>(cls_out_w, reg_out_w, ctr_w, WOF);

    const int hH[3] = {100, 50, 25};
    const int hW[3] = {128, 64, 32};
    const int hWp[3] = {130, 66, 34};
    const int hHpWp[3] = {13260, 3432, 918};
    const size_t hXoff[3] = {0, 106080ull * 256, 133536ull * 256};

    for (int L = 0; L < 3; L++) {
        const int H = hH[L], W = hW[L], Wp = hWp[L], HpWp = hHpWp[L];
        const int zpN = (NB * (2 * Wp + 2 * H) * 32 + 255) / 256;
        zeropad_h<<<zpN, 256>>>((uint4*)(XFH + hXoff[L]), H, W, Wp, HpWp);
        dim3 fgrid(W / 32, H, NB * 8);
        featprep<<<fgrid, dim3(32, 32)>>>(feat[L], XFH + hXoff[L], H, W, Wp, HpWp);
    }

    dim3 cgrid(TOTPT, 1, 32);
    dim3 ogrid(TOTPT, 1, 16);

    // conv layer 1: fp16 feature input, pure cp.async B fill
    convM<<<cgrid, 512, CM_DYN>>>(
        XFH, nullptr, nullptr,
        (const uint4*)WF, 0,
        cls_conv_b, reg_conv_b, nullptr, nullptr,
        Y0, Y1, part);
    gn_finalize2<<<768, 256>>>(part,
        cls_gn_g, cls_gn_b, reg_gn_g, reg_gn_b, ssv, shv);

    // conv layer 2: fp32 Y input, GN fused on load
    convM<<<cgrid, 512, CM_DYN>>>(
        nullptr, (const float4*)Y0, (const float4*)Y1,
        (const uint4*)WF, 1,
        cls_conv_b, reg_conv_b, ssv, shv,
        Y2, Y3, part);
    gn_finalize2<<<768, 256>>>(part,
        cls_gn_g + CC, cls_gn_b + CC, reg_gn_g + CC, reg_gn_b + CC,
        ssv + 12288, shv + 12288);

    // heads (single-term), GN of layer 2 fused on load
    convO<<<ogrid, 256, CO_DYN>>>(
        (const float4*)Y2, (const float4*)Y3,
        (const uint4*)WOF,
        ssv + 12288, shv + 12288,
        cls_out_b, reg_out_b, ctr_b, out);
}